// round 6
// baseline (speedup 1.0000x reference)
#include <cuda_runtime.h>
#include <math.h>
#include <string.h>

// Problem constants
#define N_B    4
#define S_LEN  1024
#define E_DIM  768
#define H_HEADS 12
constexpr int NS  = N_B * S_LEN;       // 4096 rows
constexpr int HE  = H_HEADS * E_DIM;   // 9216
constexpr int FF  = 4 * E_DIM;         // 3072

typedef unsigned long long u64;

// ---------------- scratch (allocation-free: __device__ globals) ----------------
__device__ float g_x    [NS * E_DIM];
__device__ float g_q    [H_HEADS * NS * E_DIM];
__device__ float g_k    [H_HEADS * NS * E_DIM];
__device__ float g_v    [H_HEADS * NS * E_DIM];
__device__ float g_sc   [(long)H_HEADS * N_B * S_LEN * S_LEN];
__device__ float g_heads[H_HEADS * NS * E_DIM];
__device__ float g_cat  [NS * HE];
__device__ float g_mha  [NS * E_DIM];
__device__ float g_y2   [NS * E_DIM];
__device__ float g_hbuf [NS * FF];

// ---------------- f32x2 packed math ----------------
__device__ __forceinline__ u64 dup2(float a) {
    u64 r;
    asm("mov.b64 %0, {%1, %1};" : "=l"(r) : "f"(a));
    return r;
}
__device__ __forceinline__ void fma2(u64& c, u64 a, u64 b) {
    asm("fma.rn.f32x2 %0, %1, %2, %0;" : "+l"(c) : "l"(a), "l"(b));
}

// ---------------- reductions ----------------
__device__ __forceinline__ float warpReduceSum(float v) {
    #pragma unroll
    for (int o = 16; o > 0; o >>= 1) v += __shfl_xor_sync(0xffffffffu, v, o);
    return v;
}
__device__ __forceinline__ float warpReduceMax(float v) {
    #pragma unroll
    for (int o = 16; o > 0; o >>= 1) v = fmaxf(v, __shfl_xor_sync(0xffffffffu, v, o));
    return v;
}

// ---------------- LayerNorm (optionally fused residual add) ----------------
__global__ void ln_kernel(const float* __restrict__ in, const float* __restrict__ resid,
                          const float* __restrict__ gamma, const float* __restrict__ beta,
                          float* __restrict__ out) {
    long base = (long)blockIdx.x * E_DIM;
    int tid = threadIdx.x;
    float vals[3];
    float s = 0.f, s2 = 0.f;
    #pragma unroll
    for (int i = 0; i < 3; i++) {
        int c = tid + i * 256;
        float v = in[base + c];
        if (resid) v += resid[base + c];
        vals[i] = v; s += v; s2 += v * v;
    }
    __shared__ float shs[8], shs2[8];
    s = warpReduceSum(s); s2 = warpReduceSum(s2);
    int lane = tid & 31, w = tid >> 5;
    if (lane == 0) { shs[w] = s; shs2[w] = s2; }
    __syncthreads();
    if (tid < 32) {
        float a = (lane < 8) ? shs[lane]  : 0.f;
        float b = (lane < 8) ? shs2[lane] : 0.f;
        a = warpReduceSum(a); b = warpReduceSum(b);
        if (lane == 0) { shs[0] = a; shs2[0] = b; }
    }
    __syncthreads();
    float mean = shs[0] * (1.f / E_DIM);
    float var  = shs2[0] * (1.f / E_DIM) - mean * mean;
    float rstd = rsqrtf(var + 1e-5f);
    #pragma unroll
    for (int i = 0; i < 3; i++) {
        int c = tid + i * 256;
        out[base + c] = (vals[i] - mean) * rstd * gamma[c] + beta[c];
    }
}

// ---------------- causal softmax (writes zeros in masked region) ----------------
__global__ void softmax_causal(float* __restrict__ scores) {
    int srow = blockIdx.x;
    float* row = scores + ((long)blockIdx.y * S_LEN + srow) * S_LEN;
    int tid = threadIdx.x;
    const float scale = 0.03608439182435161f;  // 1/sqrt(768)
    float v[4];
    float mx = -1e30f;
    #pragma unroll
    for (int i = 0; i < 4; i++) {
        int t = tid + i * 256;
        float val = (t <= srow) ? row[t] * scale : -1e30f;
        v[i] = val; mx = fmaxf(mx, val);
    }
    __shared__ float sh[8];
    int lane = tid & 31, w = tid >> 5;
    mx = warpReduceMax(mx);
    if (lane == 0) sh[w] = mx;
    __syncthreads();
    if (tid < 32) {
        float m2 = (lane < 8) ? sh[lane] : -1e30f;
        m2 = warpReduceMax(m2);
        if (lane == 0) sh[0] = m2;
    }
    __syncthreads();
    mx = sh[0];
    __syncthreads();
    float sum = 0.f;
    #pragma unroll
    for (int i = 0; i < 4; i++) {
        int t = tid + i * 256;
        float e = (t <= srow) ? __expf(v[i] - mx) : 0.f;
        v[i] = e; sum += e;
    }
    sum = warpReduceSum(sum);
    if (lane == 0) sh[w] = sum;
    __syncthreads();
    if (tid < 32) {
        float s2 = (lane < 8) ? sh[lane] : 0.f;
        s2 = warpReduceSum(s2);
        if (lane == 0) sh[0] = s2;
    }
    __syncthreads();
    float inv = 1.f / sh[0];
    #pragma unroll
    for (int i = 0; i < 4; i++) {
        int t = tid + i * 256;
        row[t] = v[i] * inv;   // exact zeros where masked
    }
}

// ---------------- heads [h][n*s][e] -> cat [n*s][h*768+e] ----------------
__global__ void heads_to_cat_kernel(const float4* __restrict__ heads4,
                                    float4* __restrict__ cat4) {
    int idx = blockIdx.x * 256 + threadIdx.x;
    const int HE4 = HE / 4;
    const int E4  = E_DIM / 4;
    int row = idx / HE4;
    int c4  = idx % HE4;
    int h   = c4 / E4;
    int e4  = c4 % E4;
    int n    = row >> 10;
    int sidx = row & 1023;
    long src = (((long)(h * N_B + n) * S_LEN + sidx) * E4 + e4);
    cat4[idx] = heads4[src];
}

// ---------------- SGEMM with packed f32x2 FMA ----------------
// TRANSB=false: B is [K,N] ldb=N;  TRANSB=true: B is [N,K] ldb=K (C=A@B^T)
// epi: 0 = bias only, 1 = bias+exact GELU, 2 = bias + residual(res, ldc)
// causal: 0 none; 1 skip blocks col0 > row0+BM-1 (scores QK^T);
//         2 limit K loop to row0+BM (attn@V; A upper-tri is exact zeros)
// Requires M%128==0, N%128==0, K%16==0. lda == K.
template<bool TRANSB>
__global__ void __launch_bounds__(256, 1)
sgemm_kernel(const float* __restrict__ A, const float* __restrict__ B,
             const float* __restrict__ bias, const float* __restrict__ res,
             float* __restrict__ C,
             int M, int N, int K, int ldb, int ldc,
             long strideA, long strideB, long strideBias, long strideC,
             int epi, int causal) {
    constexpr int BM = 128, BN = 128, BK = 16;
    __shared__ float As[BK][BM];
    __shared__ float Bs[BK][BN];

    int row0 = blockIdx.y * BM;
    int col0 = blockIdx.x * BN;
    if (causal == 1 && col0 > row0 + BM - 1) return;   // fully-masked block

    int Keff = K;
    if (causal == 2) { int kl = row0 + BM; Keff = kl < K ? kl : K; }

    int z = blockIdx.z;
    A += strideA * z;
    B += strideB * z;
    C += strideC * z;
    if (bias) bias += strideBias * z;

    int tid = threadIdx.x;
    int tx = tid & 15, ty = tid >> 4;

    u64 acc2[8][4];
    #pragma unroll
    for (int i = 0; i < 8; i++)
        #pragma unroll
        for (int j = 0; j < 4; j++) acc2[i][j] = 0ULL;

    // register prefetch buffers
    float4 pa[2], pb[2];

    // indices for loads (constant across iterations)
    const int a_mm0  = (tid)       >> 2;
    const int a_kk0  = ((tid) & 3) * 4;
    const int a_mm1  = (tid + 256) >> 2;
    const int a_kk1  = ((tid + 256) & 3) * 4;

    auto loadA = [&](int k0) {
        pa[0] = *reinterpret_cast<const float4*>(&A[(long)(row0 + a_mm0) * K + k0 + a_kk0]);
        pa[1] = *reinterpret_cast<const float4*>(&A[(long)(row0 + a_mm1) * K + k0 + a_kk1]);
    };
    auto loadB = [&](int k0) {
        if (!TRANSB) {
            #pragma unroll
            for (int l = 0; l < 2; l++) {
                int j = tid + l * 256;
                int kk = j >> 5;
                int nn = (j & 31) * 4;
                pb[l] = *reinterpret_cast<const float4*>(&B[(long)(k0 + kk) * ldb + col0 + nn]);
            }
        } else {
            #pragma unroll
            for (int l = 0; l < 2; l++) {
                int j = tid + l * 256;
                int nn  = j >> 2;
                int kk4 = (j & 3) * 4;
                pb[l] = *reinterpret_cast<const float4*>(&B[(long)(col0 + nn) * ldb + k0 + kk4]);
            }
        }
    };
    auto stash = [&]() {
        As[a_kk0 + 0][a_mm0] = pa[0].x; As[a_kk0 + 1][a_mm0] = pa[0].y;
        As[a_kk0 + 2][a_mm0] = pa[0].z; As[a_kk0 + 3][a_mm0] = pa[0].w;
        As[a_kk1 + 0][a_mm1] = pa[1].x; As[a_kk1 + 1][a_mm1] = pa[1].y;
        As[a_kk1 + 2][a_mm1] = pa[1].z; As[a_kk1 + 3][a_mm1] = pa[1].w;
        if (!TRANSB) {
            #pragma unroll
            for (int l = 0; l < 2; l++) {
                int j = tid + l * 256;
                int kk = j >> 5;
                int nn = (j & 31) * 4;
                *reinterpret_cast<float4*>(&Bs[kk][nn]) = pb[l];
            }
        } else {
            #pragma unroll
            for (int l = 0; l < 2; l++) {
                int j = tid + l * 256;
                int nn  = j >> 2;
                int kk4 = (j & 3) * 4;
                Bs[kk4 + 0][nn] = pb[l].x; Bs[kk4 + 1][nn] = pb[l].y;
                Bs[kk4 + 2][nn] = pb[l].z; Bs[kk4 + 3][nn] = pb[l].w;
            }
        }
    };

    loadA(0); loadB(0);
    for (int k0 = 0; k0 < Keff; k0 += BK) {
        stash();
        __syncthreads();
        bool more = (k0 + BK) < Keff;
        if (more) { loadA(k0 + BK); loadB(k0 + BK); }

        #pragma unroll
        for (int kk = 0; kk < BK; kk++) {
            float a[8];
            *reinterpret_cast<float4*>(&a[0]) = *reinterpret_cast<const float4*>(&As[kk][ty * 8]);
            *reinterpret_cast<float4*>(&a[4]) = *reinterpret_cast<const float4*>(&As[kk][ty * 8 + 4]);
            ulonglong2 bb0 = *reinterpret_cast<const ulonglong2*>(&Bs[kk][tx * 8]);
            ulonglong2 bb1 = *reinterpret_cast<const ulonglong2*>(&Bs[kk][tx * 8 + 4]);
            u64 b2[4] = {bb0.x, bb0.y, bb1.x, bb1.y};
            #pragma unroll
            for (int i = 0; i < 8; i++) {
                u64 ad = dup2(a[i]);
                #pragma unroll
                for (int j = 0; j < 4; j++) fma2(acc2[i][j], ad, b2[j]);
            }
        }
        __syncthreads();
    }

    int r = row0 + ty * 8;
    int c = col0 + tx * 8;
    float bv[8];
    #pragma unroll
    for (int j = 0; j < 8; j++) bv[j] = bias ? bias[c + j] : 0.f;
    #pragma unroll
    for (int i = 0; i < 8; i++) {
        float accf[8];
        memcpy(accf, acc2[i], 32);
        #pragma unroll
        for (int j = 0; j < 8; j++) {
            float v = accf[j] + bv[j];
            if (epi == 1)      v = v * normcdff(v);                   // exact GELU
            else if (epi == 2) v += res[(long)(r + i) * ldc + c + j]; // residual add
            C[(long)(r + i) * ldc + c + j] = v;
        }
    }
}

// ---------------- launch ----------------
extern "C" void kernel_launch(void* const* d_in, const int* in_sizes, int n_in,
                              void* d_out, int out_size) {
    const float* inputs = (const float*)d_in[0];
    const float* g1  = (const float*)d_in[1];
    const float* b1  = (const float*)d_in[2];
    const float* Wq  = (const float*)d_in[3];
    const float* bq  = (const float*)d_in[4];
    const float* Wk  = (const float*)d_in[5];
    const float* bk  = (const float*)d_in[6];
    const float* Wv  = (const float*)d_in[7];
    const float* bv  = (const float*)d_in[8];
    const float* Wc  = (const float*)d_in[9];
    const float* bc  = (const float*)d_in[10];
    const float* g2  = (const float*)d_in[11];
    const float* b2  = (const float*)d_in[12];
    const float* Wfc = (const float*)d_in[13];
    const float* bfc = (const float*)d_in[14];
    const float* Wp  = (const float*)d_in[15];
    const float* bp  = (const float*)d_in[16];
    float* out = (float*)d_out;

    float *x, *q, *k, *v, *sc, *hd, *cat, *mha, *y2, *hb;
    cudaGetSymbolAddress((void**)&x,   g_x);
    cudaGetSymbolAddress((void**)&q,   g_q);
    cudaGetSymbolAddress((void**)&k,   g_k);
    cudaGetSymbolAddress((void**)&v,   g_v);
    cudaGetSymbolAddress((void**)&sc,  g_sc);
    cudaGetSymbolAddress((void**)&hd,  g_heads);
    cudaGetSymbolAddress((void**)&cat, g_cat);
    cudaGetSymbolAddress((void**)&mha, g_mha);
    cudaGetSymbolAddress((void**)&y2,  g_y2);
    cudaGetSymbolAddress((void**)&hb,  g_hbuf);

    const long QKV_STRIDE = (long)NS * E_DIM;
    const long ATT_A      = (long)S_LEN * E_DIM;
    const long SC_STRIDE  = (long)S_LEN * S_LEN;

    // 1) LN1
    ln_kernel<<<NS, 256>>>(inputs, nullptr, g1, b1, x);

    // 2) Q,K,V projections
    dim3 gQKV(E_DIM / 128, NS / 128, H_HEADS);
    sgemm_kernel<false><<<gQKV, 256>>>(x, Wq, bq, nullptr, q, NS, E_DIM, E_DIM,
                                       E_DIM, E_DIM, 0, (long)E_DIM * E_DIM, E_DIM, QKV_STRIDE, 0, 0);
    sgemm_kernel<false><<<gQKV, 256>>>(x, Wk, bk, nullptr, k, NS, E_DIM, E_DIM,
                                       E_DIM, E_DIM, 0, (long)E_DIM * E_DIM, E_DIM, QKV_STRIDE, 0, 0);
    sgemm_kernel<false><<<gQKV, 256>>>(x, Wv, bv, nullptr, v, NS, E_DIM, E_DIM,
                                       E_DIM, E_DIM, 0, (long)E_DIM * E_DIM, E_DIM, QKV_STRIDE, 0, 0);

    // 3) scores = Q @ K^T per (h,n), skipping fully-masked blocks
    dim3 gSC(S_LEN / 128, S_LEN / 128, H_HEADS * N_B);
    sgemm_kernel<true><<<gSC, 256>>>(q, k, nullptr, nullptr, sc, S_LEN, S_LEN, E_DIM,
                                     E_DIM, S_LEN, ATT_A, ATT_A, 0, SC_STRIDE, 0, 1);

    // 4) causal softmax (writes exact zeros in masked region)
    softmax_causal<<<dim3(S_LEN, H_HEADS * N_B), 256>>>(sc);

    // 5) heads = attn @ V, K-loop limited by causal structure
    dim3 gAV(E_DIM / 128, S_LEN / 128, H_HEADS * N_B);
    sgemm_kernel<false><<<gAV, 256>>>(sc, v, nullptr, nullptr, hd, S_LEN, E_DIM, S_LEN,
                                      E_DIM, E_DIM, SC_STRIDE, ATT_A, 0, ATT_A, 0, 2);

    // 6) transpose heads -> cat
    heads_to_cat_kernel<<<(NS * HE / 4) / 256, 256>>>((const float4*)hd, (float4*)cat);

    // 7) c_proj
    dim3 gCP(E_DIM / 128, NS / 128, 1);
    sgemm_kernel<false><<<gCP, 256>>>(cat, Wc, bc, nullptr, mha, NS, E_DIM, HE,
                                      E_DIM, E_DIM, 0, 0, 0, 0, 0, 0);

    // 8) y2 = LN2(mha + x)
    ln_kernel<<<NS, 256>>>(mha, x, g2, b2, y2);

    // 9) fc + GELU
    dim3 gFC(FF / 128, NS / 128, 1);
    sgemm_kernel<false><<<gFC, 256>>>(y2, Wfc, bfc, nullptr, hb, NS, FF, E_DIM,
                                      FF, FF, 0, 0, 0, 0, 1, 0);

    // 10) proj + residual -> out
    dim3 gPJ(E_DIM / 128, NS / 128, 1);
    sgemm_kernel<false><<<gPJ, 256>>>(hb, Wp, bp, y2, out, NS, E_DIM, FF,
                                      E_DIM, E_DIM, 0, 0, 0, 0, 2, 0);
}

// round 8
// speedup vs baseline: 2.5303x; 2.5303x over previous
#include <cuda_runtime.h>
#include <cuda_bf16.h>
#include <math.h>
#include <stdint.h>
#include <string.h>

// Problem constants
#define N_B    4
#define S_LEN  1024
#define E_DIM  768
#define H_HEADS 12
constexpr int NS  = N_B * S_LEN;       // 4096
constexpr int HE  = H_HEADS * E_DIM;   // 9216
constexpr int FF  = 4 * E_DIM;         // 3072

// ---------------- scratch (__device__ globals; allocation-free) ----------------
__device__ float         g_x   [(size_t)NS * E_DIM];
__device__ __nv_bfloat16 g_xh  [(size_t)NS * E_DIM];
__device__ __nv_bfloat16 g_xl  [(size_t)NS * E_DIM];

__device__ __nv_bfloat16 g_wqth[(size_t)H_HEADS * E_DIM * E_DIM];
__device__ __nv_bfloat16 g_wqtl[(size_t)H_HEADS * E_DIM * E_DIM];
__device__ __nv_bfloat16 g_wkth[(size_t)H_HEADS * E_DIM * E_DIM];
__device__ __nv_bfloat16 g_wktl[(size_t)H_HEADS * E_DIM * E_DIM];
__device__ __nv_bfloat16 g_wvth[(size_t)H_HEADS * E_DIM * E_DIM];
__device__ __nv_bfloat16 g_wvtl[(size_t)H_HEADS * E_DIM * E_DIM];

__device__ __nv_bfloat16 g_qh  [(size_t)H_HEADS * NS * E_DIM];
__device__ __nv_bfloat16 g_ql  [(size_t)H_HEADS * NS * E_DIM];
__device__ __nv_bfloat16 g_kh  [(size_t)H_HEADS * NS * E_DIM];
__device__ __nv_bfloat16 g_kl  [(size_t)H_HEADS * NS * E_DIM];
__device__ float         g_v   [(size_t)H_HEADS * NS * E_DIM];
__device__ __nv_bfloat16 g_vth [(size_t)H_HEADS * NS * E_DIM];
__device__ __nv_bfloat16 g_vtl [(size_t)H_HEADS * NS * E_DIM];

__device__ float         g_sc  [(size_t)H_HEADS * N_B * S_LEN * S_LEN];
__device__ __nv_bfloat16 g_ah  [(size_t)H_HEADS * N_B * S_LEN * S_LEN];
__device__ __nv_bfloat16 g_al  [(size_t)H_HEADS * N_B * S_LEN * S_LEN];

__device__ __nv_bfloat16 g_cath[(size_t)NS * HE];
__device__ __nv_bfloat16 g_catl[(size_t)NS * HE];
__device__ __nv_bfloat16 g_wcth[(size_t)HE * E_DIM];
__device__ __nv_bfloat16 g_wctl[(size_t)HE * E_DIM];
__device__ float         g_mha [(size_t)NS * E_DIM];

__device__ float         g_y2  [(size_t)NS * E_DIM];
__device__ __nv_bfloat16 g_y2h [(size_t)NS * E_DIM];
__device__ __nv_bfloat16 g_y2l [(size_t)NS * E_DIM];
__device__ __nv_bfloat16 g_wfcth[(size_t)E_DIM * FF];
__device__ __nv_bfloat16 g_wfctl[(size_t)E_DIM * FF];
__device__ __nv_bfloat16 g_hbh [(size_t)NS * FF];
__device__ __nv_bfloat16 g_hbl [(size_t)NS * FF];
__device__ __nv_bfloat16 g_wpth[(size_t)FF * E_DIM];
__device__ __nv_bfloat16 g_wptl[(size_t)FF * E_DIM];

// ---------------- helpers ----------------
__device__ __forceinline__ uint32_t smem_u32(const void* p) {
    uint32_t a;
    asm("{ .reg .u64 t; cvta.to.shared.u64 t, %1; cvt.u32.u64 %0, t; }" : "=r"(a) : "l"(p));
    return a;
}

__device__ __forceinline__ void cp_async16(uint32_t dst, const void* src) {
    asm volatile("cp.async.cg.shared.global [%0], [%1], 16;" :: "r"(dst), "l"(src) : "memory");
}
__device__ __forceinline__ void cp_commit() {
    asm volatile("cp.async.commit_group;" ::: "memory");
}
__device__ __forceinline__ void cp_wait1() {
    asm volatile("cp.async.wait_group 1;" ::: "memory");
}
__device__ __forceinline__ void cp_wait0() {
    asm volatile("cp.async.wait_group 0;" ::: "memory");
}

__device__ __forceinline__ void ldmatrix_x4(uint32_t& r0, uint32_t& r1, uint32_t& r2, uint32_t& r3,
                                            uint32_t addr) {
    asm volatile("ldmatrix.sync.aligned.m8n8.x4.shared.b16 {%0,%1,%2,%3}, [%4];"
                 : "=r"(r0), "=r"(r1), "=r"(r2), "=r"(r3) : "r"(addr));
}

__device__ __forceinline__ void split_store(float v, __nv_bfloat16* ph, __nv_bfloat16* pl, long o) {
    __nv_bfloat16 h = __float2bfloat16(v);
    ph[o] = h;
    pl[o] = __float2bfloat16(v - __bfloat162float(h));
}

// ---------------- reductions ----------------
__device__ __forceinline__ float warpReduceSum(float v) {
    #pragma unroll
    for (int o = 16; o > 0; o >>= 1) v += __shfl_xor_sync(0xffffffffu, v, o);
    return v;
}
__device__ __forceinline__ float warpReduceMax(float v) {
    #pragma unroll
    for (int o = 16; o > 0; o >>= 1) v = fmaxf(v, __shfl_xor_sync(0xffffffffu, v, o));
    return v;
}

// ---------------- LayerNorm: fp32 out + bf16 hi/lo out ----------------
__global__ void ln_kernel(const float* __restrict__ in, const float* __restrict__ resid,
                          const float* __restrict__ gamma, const float* __restrict__ beta,
                          float* __restrict__ out,
                          __nv_bfloat16* __restrict__ oh, __nv_bfloat16* __restrict__ ol) {
    long base = (long)blockIdx.x * E_DIM;
    int tid = threadIdx.x;
    float vals[3];
    float s = 0.f, s2 = 0.f;
    #pragma unroll
    for (int i = 0; i < 3; i++) {
        int c = tid + i * 256;
        float v = in[base + c];
        if (resid) v += resid[base + c];
        vals[i] = v; s += v; s2 += v * v;
    }
    __shared__ float shs[8], shs2[8];
    s = warpReduceSum(s); s2 = warpReduceSum(s2);
    int lane = tid & 31, w = tid >> 5;
    if (lane == 0) { shs[w] = s; shs2[w] = s2; }
    __syncthreads();
    if (tid < 32) {
        float a = (lane < 8) ? shs[lane]  : 0.f;
        float b = (lane < 8) ? shs2[lane] : 0.f;
        a = warpReduceSum(a); b = warpReduceSum(b);
        if (lane == 0) { shs[0] = a; shs2[0] = b; }
    }
    __syncthreads();
    float mean = shs[0] * (1.f / E_DIM);
    float var  = shs2[0] * (1.f / E_DIM) - mean * mean;
    float rstd = rsqrtf(var + 1e-5f);
    #pragma unroll
    for (int i = 0; i < 3; i++) {
        int c = tid + i * 256;
        float v = (vals[i] - mean) * rstd * gamma[c] + beta[c];
        out[base + c] = v;
        split_store(v, oh, ol, base + c);
    }
}

// ---------------- causal softmax: fp32 scores in, bf16 hi/lo probs out ----------------
__global__ void softmax_causal(const float* __restrict__ scores,
                               __nv_bfloat16* __restrict__ ah, __nv_bfloat16* __restrict__ al) {
    int srow = blockIdx.x;
    long off = ((long)blockIdx.y * S_LEN + srow) * S_LEN;
    const float* row = scores + off;
    int tid = threadIdx.x;
    const float scale = 0.03608439182435161f;  // 1/sqrt(768)
    float v[4];
    float mx = -1e30f;
    #pragma unroll
    for (int i = 0; i < 4; i++) {
        int t = tid + i * 256;
        float val = (t <= srow) ? row[t] * scale : -1e30f;
        v[i] = val; mx = fmaxf(mx, val);
    }
    __shared__ float sh[8];
    int lane = tid & 31, w = tid >> 5;
    mx = warpReduceMax(mx);
    if (lane == 0) sh[w] = mx;
    __syncthreads();
    if (tid < 32) {
        float m2 = (lane < 8) ? sh[lane] : -1e30f;
        m2 = warpReduceMax(m2);
        if (lane == 0) sh[0] = m2;
    }
    __syncthreads();
    mx = sh[0];
    __syncthreads();
    float sum = 0.f;
    #pragma unroll
    for (int i = 0; i < 4; i++) {
        int t = tid + i * 256;
        float e = (t <= srow) ? __expf(v[i] - mx) : 0.f;
        v[i] = e; sum += e;
    }
    sum = warpReduceSum(sum);
    if (lane == 0) sh[w] = sum;
    __syncthreads();
    if (tid < 32) {
        float s2 = (lane < 8) ? sh[lane] : 0.f;
        s2 = warpReduceSum(s2);
        if (lane == 0) sh[0] = s2;
    }
    __syncthreads();
    float inv = 1.f / sh[0];
    #pragma unroll
    for (int i = 0; i < 4; i++) {
        int t = tid + i * 256;
        split_store(v[i] * inv, ah, al, off + t);
    }
}

// ---------------- tiled transpose + bf16 split: src[R,C] f32 -> dst[C,R] hi/lo ----------------
__global__ void transpose_conv(const float* __restrict__ src,
                               __nv_bfloat16* __restrict__ dh, __nv_bfloat16* __restrict__ dl,
                               int R, int C, long sS, long sD) {
    __shared__ float t[32][33];
    src += (long)blockIdx.z * sS;
    dh  += (long)blockIdx.z * sD;
    dl  += (long)blockIdx.z * sD;
    int c0 = blockIdx.x * 32, r0 = blockIdx.y * 32;
    #pragma unroll
    for (int i = 0; i < 32; i += 8)
        t[threadIdx.y + i][threadIdx.x] = src[(long)(r0 + threadIdx.y + i) * C + c0 + threadIdx.x];
    __syncthreads();
    #pragma unroll
    for (int i = 0; i < 32; i += 8) {
        float v = t[threadIdx.x][threadIdx.y + i];
        long o = (long)(c0 + threadIdx.y + i) * R + r0 + threadIdx.x;
        __nv_bfloat16 h = __float2bfloat16(v);
        dh[o] = h;
        dl[o] = __float2bfloat16(v - __bfloat162float(h));
    }
}

// ---------------- mma.sync bf16x3 GEMM ----------------
// C[M,N] = (Ah+Al)[M,K] @ (Bh+Bl)[N,K]^T  (both K-major), fp32 accum in regs.
// Tile 128x128, BK=64 bf16 (128B SW128 rows). 8 warps (4m x 2n), warp tile 32x64.
// epi: 0 bias, 1 bias+GELU(exact), 2 bias+residual.
// causal: 0 none, 1 skip upper blocks, 2 K limited to row0+128.
// catmode: write Ch/Cl at [(z&3)*S + row][(z>>2)*E + col], ld=HE.
constexpr int GEMM_SMEM = 2 * 65536 + 128;

__global__ void __launch_bounds__(256)
gemm_mma(const __nv_bfloat16* __restrict__ Ah, const __nv_bfloat16* __restrict__ Al,
         const __nv_bfloat16* __restrict__ Bh, const __nv_bfloat16* __restrict__ Bl,
         const float* __restrict__ bias, const float* __restrict__ res,
         float* __restrict__ Cf, __nv_bfloat16* __restrict__ Ch, __nv_bfloat16* __restrict__ Cl,
         int Ntot, int K,
         long sA, long sB, long sBias, long sC,
         int epi, int causal, int catmode) {
    extern __shared__ char smem_raw[];
    const int row0 = blockIdx.y * 128;
    const int col0 = blockIdx.x * 128;
    if (causal == 1 && col0 > row0 + 127) return;

    const int z = blockIdx.z;
    Ah += (long)z * sA; Al += (long)z * sA;
    Bh += (long)z * sB; Bl += (long)z * sB;
    if (bias) bias += (long)z * sBias;
    if (!catmode) {
        if (Cf) Cf += (long)z * sC;
        if (Ch) { Ch += (long)z * sC; Cl += (long)z * sC; }
    }

    const int tid = threadIdx.x;
    const int wid = tid >> 5, lane = tid & 31;
    const int warp_m = wid & 3, warp_n = wid >> 2;

    uint32_t sbase = (smem_u32(smem_raw) + 127) & ~127u;

    int Keff = K;
    if (causal == 2) { int kl = row0 + 128; Keff = kl < K ? kl : K; }
    const int nch = Keff >> 6;

    float acc[2][8][4];
    #pragma unroll
    for (int a = 0; a < 2; a++)
        #pragma unroll
        for (int b = 0; b < 8; b++)
            #pragma unroll
            for (int d = 0; d < 4; d++) acc[a][b][d] = 0.f;

    const __nv_bfloat16* srcs[4] = {Ah, Al, Bh, Bl};
    const int rbs[4] = {row0, row0, col0, col0};

    auto issue = [&](int c) {
        int buf = c & 1;
        uint32_t dstb = sbase + buf * 65536;
        int k0 = c << 6;
        #pragma unroll
        for (int t = 0; t < 4; t++) {
            #pragma unroll
            for (int i = 0; i < 4; i++) {
                int idx = i * 256 + tid;
                int r = idx >> 3, kb = idx & 7;
                uint32_t so = (uint32_t)(r * 128 + ((kb * 16) ^ ((r & 7) << 4)));
                const void* src = (const char*)(srcs[t] + (long)(rbs[t] + r) * K + k0) + kb * 16;
                cp_async16(dstb + t * 16384 + so, src);
            }
        }
        cp_commit();
    };

    // ldmatrix lane addressing pieces
    const int li  = lane & 7;
    const int s8  = (lane >> 3) & 1;
    const int s16 = lane >> 4;

    issue(0);
    for (int c = 0; c < nch; c++) {
        bool more = (c + 1) < nch;
        if (more) { issue(c + 1); cp_wait1(); }
        else      { cp_wait0(); }
        __syncthreads();
        uint32_t bufb = sbase + (c & 1) * 65536;

        #pragma unroll
        for (int pass = 0; pass < 3; pass++) {
            uint32_t abase = bufb + (pass == 2 ? 16384 : 0);
            uint32_t bbase = bufb + (pass == 1 ? 49152 : 32768);
            #pragma unroll
            for (int ks = 0; ks < 4; ks++) {
                int kb = ks * 32 + s16 * 16;
                uint32_t afr[2][4];
                #pragma unroll
                for (int mt = 0; mt < 2; mt++) {
                    int r = warp_m * 32 + mt * 16 + s8 * 8 + li;
                    uint32_t ad = abase + (uint32_t)(r * 128 + (kb ^ ((r & 7) << 4)));
                    ldmatrix_x4(afr[mt][0], afr[mt][1], afr[mt][2], afr[mt][3], ad);
                }
                uint32_t bfr[8][2];
                #pragma unroll
                for (int nt2 = 0; nt2 < 4; nt2++) {
                    int r = warp_n * 64 + nt2 * 16 + s8 * 8 + li;
                    uint32_t bd = bbase + (uint32_t)(r * 128 + (kb ^ ((r & 7) << 4)));
                    uint32_t r0, r1, r2, r3;
                    ldmatrix_x4(r0, r1, r2, r3, bd);
                    bfr[nt2 * 2][0]     = r0; bfr[nt2 * 2][1]     = r2;
                    bfr[nt2 * 2 + 1][0] = r1; bfr[nt2 * 2 + 1][1] = r3;
                }
                #pragma unroll
                for (int mt = 0; mt < 2; mt++)
                    #pragma unroll
                    for (int nt = 0; nt < 8; nt++)
                        asm volatile(
                            "mma.sync.aligned.m16n8k16.row.col.f32.bf16.bf16.f32 "
                            "{%0,%1,%2,%3}, {%4,%5,%6,%7}, {%8,%9}, {%0,%1,%2,%3};"
                            : "+f"(acc[mt][nt][0]), "+f"(acc[mt][nt][1]),
                              "+f"(acc[mt][nt][2]), "+f"(acc[mt][nt][3])
                            : "r"(afr[mt][0]), "r"(afr[mt][1]), "r"(afr[mt][2]), "r"(afr[mt][3]),
                              "r"(bfr[nt][0]), "r"(bfr[nt][1]));
            }
        }
        __syncthreads();
    }

    // ---------------- epilogue straight from register fragments ----------------
    const int g = lane >> 2, t = lane & 3;
    const int hh = z >> 2, nb = z & 3;
    #pragma unroll
    for (int mt = 0; mt < 2; mt++)
        #pragma unroll
        for (int nt = 0; nt < 8; nt++)
            #pragma unroll
            for (int hr = 0; hr < 2; hr++) {
                int gr = row0 + warp_m * 32 + mt * 16 + g + hr * 8;
                int gc = col0 + warp_n * 64 + nt * 8 + t * 2;
                float v0 = acc[mt][nt][hr * 2];
                float v1 = acc[mt][nt][hr * 2 + 1];
                if (bias) { v0 += bias[gc]; v1 += bias[gc + 1]; }
                if (epi == 1) { v0 = v0 * normcdff(v0); v1 = v1 * normcdff(v1); }
                else if (epi == 2) {
                    long o = (long)gr * Ntot + gc;
                    v0 += res[o]; v1 += res[o + 1];
                }
                if (Cf) {
                    long o = (long)gr * Ntot + gc;
                    Cf[o] = v0; Cf[o + 1] = v1;
                }
                if (Ch) {
                    long o = catmode ? ((long)(nb * S_LEN + gr) * HE + (long)hh * E_DIM + gc)
                                     : ((long)gr * Ntot + gc);
                    __nv_bfloat16 h0 = __float2bfloat16(v0);
                    __nv_bfloat16 h1 = __float2bfloat16(v1);
                    __nv_bfloat162 hp; hp.x = h0; hp.y = h1;
                    *(__nv_bfloat162*)(Ch + o) = hp;
                    __nv_bfloat162 lp;
                    lp.x = __float2bfloat16(v0 - __bfloat162float(h0));
                    lp.y = __float2bfloat16(v1 - __bfloat162float(h1));
                    *(__nv_bfloat162*)(Cl + o) = lp;
                }
            }
}

// ---------------- launch ----------------
extern "C" void kernel_launch(void* const* d_in, const int* in_sizes, int n_in,
                              void* d_out, int out_size) {
    const float* inputs = (const float*)d_in[0];
    const float* g1  = (const float*)d_in[1];
    const float* b1  = (const float*)d_in[2];
    const float* Wq  = (const float*)d_in[3];
    const float* bq  = (const float*)d_in[4];
    const float* Wk  = (const float*)d_in[5];
    const float* bk  = (const float*)d_in[6];
    const float* Wv  = (const float*)d_in[7];
    const float* bv  = (const float*)d_in[8];
    const float* Wc  = (const float*)d_in[9];
    const float* bc  = (const float*)d_in[10];
    const float* g2  = (const float*)d_in[11];
    const float* b2  = (const float*)d_in[12];
    const float* Wfc = (const float*)d_in[13];
    const float* bfc = (const float*)d_in[14];
    const float* Wp  = (const float*)d_in[15];
    const float* bp  = (const float*)d_in[16];
    float* out = (float*)d_out;

    cudaFuncSetAttribute(gemm_mma, cudaFuncAttributeMaxDynamicSharedMemorySize, GEMM_SMEM);

    float *x, *v, *sc, *mha, *y2;
    __nv_bfloat16 *xh, *xl, *wqth, *wqtl, *wkth, *wktl, *wvth, *wvtl;
    __nv_bfloat16 *qh, *ql, *kh, *kl, *vth, *vtl, *ah, *al;
    __nv_bfloat16 *cath, *catl, *wcth, *wctl, *y2h, *y2l, *wfcth, *wfctl, *hbh, *hbl, *wpth, *wptl;
    cudaGetSymbolAddress((void**)&x, g_x);     cudaGetSymbolAddress((void**)&xh, g_xh);
    cudaGetSymbolAddress((void**)&xl, g_xl);
    cudaGetSymbolAddress((void**)&wqth, g_wqth); cudaGetSymbolAddress((void**)&wqtl, g_wqtl);
    cudaGetSymbolAddress((void**)&wkth, g_wkth); cudaGetSymbolAddress((void**)&wktl, g_wktl);
    cudaGetSymbolAddress((void**)&wvth, g_wvth); cudaGetSymbolAddress((void**)&wvtl, g_wvtl);
    cudaGetSymbolAddress((void**)&qh, g_qh);   cudaGetSymbolAddress((void**)&ql, g_ql);
    cudaGetSymbolAddress((void**)&kh, g_kh);   cudaGetSymbolAddress((void**)&kl, g_kl);
    cudaGetSymbolAddress((void**)&v, g_v);
    cudaGetSymbolAddress((void**)&vth, g_vth); cudaGetSymbolAddress((void**)&vtl, g_vtl);
    cudaGetSymbolAddress((void**)&sc, g_sc);
    cudaGetSymbolAddress((void**)&ah, g_ah);   cudaGetSymbolAddress((void**)&al, g_al);
    cudaGetSymbolAddress((void**)&cath, g_cath); cudaGetSymbolAddress((void**)&catl, g_catl);
    cudaGetSymbolAddress((void**)&wcth, g_wcth); cudaGetSymbolAddress((void**)&wctl, g_wctl);
    cudaGetSymbolAddress((void**)&mha, g_mha);
    cudaGetSymbolAddress((void**)&y2, g_y2);
    cudaGetSymbolAddress((void**)&y2h, g_y2h); cudaGetSymbolAddress((void**)&y2l, g_y2l);
    cudaGetSymbolAddress((void**)&wfcth, g_wfcth); cudaGetSymbolAddress((void**)&wfctl, g_wfctl);
    cudaGetSymbolAddress((void**)&hbh, g_hbh); cudaGetSymbolAddress((void**)&hbl, g_hbl);
    cudaGetSymbolAddress((void**)&wpth, g_wpth); cudaGetSymbolAddress((void**)&wptl, g_wptl);

    const long WEE = (long)E_DIM * E_DIM;
    const long QKV = (long)NS * E_DIM;
    const long ATT = (long)S_LEN * E_DIM;
    const long SCS = (long)S_LEN * S_LEN;
    dim3 tb(32, 8);

    // weight transposes + splits (W[in,out] -> W^T[out,in] hi/lo, K-major for mma B)
    transpose_conv<<<dim3(E_DIM / 32, E_DIM / 32, H_HEADS), tb>>>(Wq, wqth, wqtl, E_DIM, E_DIM, WEE, WEE);
    transpose_conv<<<dim3(E_DIM / 32, E_DIM / 32, H_HEADS), tb>>>(Wk, wkth, wktl, E_DIM, E_DIM, WEE, WEE);
    transpose_conv<<<dim3(E_DIM / 32, E_DIM / 32, H_HEADS), tb>>>(Wv, wvth, wvtl, E_DIM, E_DIM, WEE, WEE);
    transpose_conv<<<dim3(E_DIM / 32, HE / 32, 1), tb>>>(Wc, wcth, wctl, HE, E_DIM, 0, 0);
    transpose_conv<<<dim3(FF / 32, E_DIM / 32, 1), tb>>>(Wfc, wfcth, wfctl, E_DIM, FF, 0, 0);
    transpose_conv<<<dim3(E_DIM / 32, FF / 32, 1), tb>>>(Wp, wpth, wptl, FF, E_DIM, 0, 0);

    // 1) LN1 -> x (fp32 + hi/lo)
    ln_kernel<<<NS, 256>>>(inputs, nullptr, g1, b1, x, xh, xl);

    // 2) QKV projections (z = head)
    dim3 gQKV(E_DIM / 128, NS / 128, H_HEADS);
    gemm_mma<<<gQKV, 256, GEMM_SMEM>>>(xh, xl, wqth, wqtl, bq, nullptr,
                                       nullptr, qh, ql, E_DIM, E_DIM,
                                       0, WEE, E_DIM, QKV, 0, 0, 0);
    gemm_mma<<<gQKV, 256, GEMM_SMEM>>>(xh, xl, wkth, wktl, bk, nullptr,
                                       nullptr, kh, kl, E_DIM, E_DIM,
                                       0, WEE, E_DIM, QKV, 0, 0, 0);
    gemm_mma<<<gQKV, 256, GEMM_SMEM>>>(xh, xl, wvth, wvtl, bv, nullptr,
                                       v, nullptr, nullptr, E_DIM, E_DIM,
                                       0, WEE, E_DIM, QKV, 0, 0, 0);

    // 3) v -> v^T hi/lo per (h,n)  (K-major for mma B operand of attn@V)
    transpose_conv<<<dim3(E_DIM / 32, S_LEN / 32, H_HEADS * N_B), tb>>>(v, vth, vtl, S_LEN, E_DIM, ATT, ATT);

    // 4) scores = Q @ K^T (causal block skip), fp32 out
    dim3 gSC(S_LEN / 128, S_LEN / 128, H_HEADS * N_B);
    gemm_mma<<<gSC, 256, GEMM_SMEM>>>(qh, ql, kh, kl, nullptr, nullptr,
                                      sc, nullptr, nullptr, S_LEN, E_DIM,
                                      ATT, ATT, 0, SCS, 0, 1, 0);

    // 5) softmax -> attn hi/lo
    softmax_causal<<<dim3(S_LEN, H_HEADS * N_B), 256>>>(sc, ah, al);

    // 6) heads = attn @ V^T, epilogue writes straight into cat layout (hi/lo)
    dim3 gAV(E_DIM / 128, S_LEN / 128, H_HEADS * N_B);
    gemm_mma<<<gAV, 256, GEMM_SMEM>>>(ah, al, vth, vtl, nullptr, nullptr,
                                      nullptr, cath, catl, E_DIM, S_LEN,
                                      SCS, ATT, 0, 0, 0, 2, 1);

    // 7) c_proj
    dim3 gCP(E_DIM / 128, NS / 128, 1);
    gemm_mma<<<gCP, 256, GEMM_SMEM>>>(cath, catl, wcth, wctl, bc, nullptr,
                                      mha, nullptr, nullptr, E_DIM, HE,
                                      0, 0, 0, 0, 0, 0, 0);

    // 8) y2 = LN2(mha + x)
    ln_kernel<<<NS, 256>>>(mha, x, g2, b2, y2, y2h, y2l);

    // 9) fc + GELU -> hb hi/lo
    dim3 gFC(FF / 128, NS / 128, 1);
    gemm_mma<<<gFC, 256, GEMM_SMEM>>>(y2h, y2l, wfcth, wfctl, bfc, nullptr,
                                      nullptr, hbh, hbl, FF, E_DIM,
                                      0, 0, 0, 0, 1, 0, 0);

    // 10) proj + bias + residual(y2) -> out
    dim3 gPJ(E_DIM / 128, NS / 128, 1);
    gemm_mma<<<gPJ, 256, GEMM_SMEM>>>(hbh, hbl, wpth, wptl, bp, y2,
                                      out, nullptr, nullptr, E_DIM, FF,
                                      0, 0, 0, 0, 2, 0, 0);
}

// round 9
// speedup vs baseline: 2.6194x; 1.0352x over previous
#include <cuda_runtime.h>
#include <cuda_bf16.h>
#include <math.h>
#include <stdint.h>
#include <string.h>

// Problem constants
#define N_B    4
#define S_LEN  1024
#define E_DIM  768
#define H_HEADS 12
constexpr int NS  = N_B * S_LEN;       // 4096
constexpr int HE  = H_HEADS * E_DIM;   // 9216
constexpr int FF  = 4 * E_DIM;         // 3072

// ---------------- scratch (__device__ globals; allocation-free) ----------------
__device__ float         g_x   [(size_t)NS * E_DIM];
__device__ __nv_bfloat16 g_xh  [(size_t)NS * E_DIM];
__device__ __nv_bfloat16 g_xl  [(size_t)NS * E_DIM];

__device__ __nv_bfloat16 g_wqth[(size_t)H_HEADS * E_DIM * E_DIM];
__device__ __nv_bfloat16 g_wqtl[(size_t)H_HEADS * E_DIM * E_DIM];
__device__ __nv_bfloat16 g_wkth[(size_t)H_HEADS * E_DIM * E_DIM];
__device__ __nv_bfloat16 g_wktl[(size_t)H_HEADS * E_DIM * E_DIM];
__device__ __nv_bfloat16 g_wvth[(size_t)H_HEADS * E_DIM * E_DIM];
__device__ __nv_bfloat16 g_wvtl[(size_t)H_HEADS * E_DIM * E_DIM];

__device__ __nv_bfloat16 g_qh  [(size_t)H_HEADS * NS * E_DIM];
__device__ __nv_bfloat16 g_ql  [(size_t)H_HEADS * NS * E_DIM];
__device__ __nv_bfloat16 g_kh  [(size_t)H_HEADS * NS * E_DIM];
__device__ __nv_bfloat16 g_kl  [(size_t)H_HEADS * NS * E_DIM];
__device__ float         g_v   [(size_t)H_HEADS * NS * E_DIM];
__device__ __nv_bfloat16 g_vth [(size_t)H_HEADS * NS * E_DIM];
__device__ __nv_bfloat16 g_vtl [(size_t)H_HEADS * NS * E_DIM];

__device__ float         g_sc  [(size_t)H_HEADS * N_B * S_LEN * S_LEN];
__device__ __nv_bfloat16 g_ah  [(size_t)H_HEADS * N_B * S_LEN * S_LEN];
__device__ __nv_bfloat16 g_al  [(size_t)H_HEADS * N_B * S_LEN * S_LEN];

__device__ __nv_bfloat16 g_cath[(size_t)NS * HE];
__device__ __nv_bfloat16 g_catl[(size_t)NS * HE];
__device__ __nv_bfloat16 g_wcth[(size_t)HE * E_DIM];
__device__ __nv_bfloat16 g_wctl[(size_t)HE * E_DIM];
__device__ float         g_mha [(size_t)NS * E_DIM];

__device__ float         g_y2  [(size_t)NS * E_DIM];
__device__ __nv_bfloat16 g_y2h [(size_t)NS * E_DIM];
__device__ __nv_bfloat16 g_y2l [(size_t)NS * E_DIM];
__device__ __nv_bfloat16 g_wfcth[(size_t)E_DIM * FF];
__device__ __nv_bfloat16 g_wfctl[(size_t)E_DIM * FF];
__device__ __nv_bfloat16 g_hbh [(size_t)NS * FF];
__device__ __nv_bfloat16 g_hbl [(size_t)NS * FF];
__device__ __nv_bfloat16 g_wpth[(size_t)FF * E_DIM];
__device__ __nv_bfloat16 g_wptl[(size_t)FF * E_DIM];

// ---------------- helpers ----------------
__device__ __forceinline__ uint32_t smem_u32(const void* p) {
    uint32_t a;
    asm("{ .reg .u64 t; cvta.to.shared.u64 t, %1; cvt.u32.u64 %0, t; }" : "=r"(a) : "l"(p));
    return a;
}

__device__ __forceinline__ void cp_async16(uint32_t dst, const void* src) {
    asm volatile("cp.async.cg.shared.global [%0], [%1], 16;" :: "r"(dst), "l"(src) : "memory");
}
__device__ __forceinline__ void cp_commit() {
    asm volatile("cp.async.commit_group;" ::: "memory");
}
__device__ __forceinline__ void cp_wait2() { asm volatile("cp.async.wait_group 2;" ::: "memory"); }
__device__ __forceinline__ void cp_wait1() { asm volatile("cp.async.wait_group 1;" ::: "memory"); }
__device__ __forceinline__ void cp_wait0() { asm volatile("cp.async.wait_group 0;" ::: "memory"); }

__device__ __forceinline__ void ldmatrix_x4(uint32_t& r0, uint32_t& r1, uint32_t& r2, uint32_t& r3,
                                            uint32_t addr) {
    asm volatile("ldmatrix.sync.aligned.m8n8.x4.shared.b16 {%0,%1,%2,%3}, [%4];"
                 : "=r"(r0), "=r"(r1), "=r"(r2), "=r"(r3) : "r"(addr));
}

#define MMA16816(acc, af, b0, b1) \
    asm volatile( \
        "mma.sync.aligned.m16n8k16.row.col.f32.bf16.bf16.f32 " \
        "{%0,%1,%2,%3}, {%4,%5,%6,%7}, {%8,%9}, {%0,%1,%2,%3};" \
        : "+f"((acc)[0]), "+f"((acc)[1]), "+f"((acc)[2]), "+f"((acc)[3]) \
        : "r"((af)[0]), "r"((af)[1]), "r"((af)[2]), "r"((af)[3]), \
          "r"(b0), "r"(b1))

__device__ __forceinline__ void split_store(float v, __nv_bfloat16* ph, __nv_bfloat16* pl, long o) {
    __nv_bfloat16 h = __float2bfloat16(v);
    ph[o] = h;
    pl[o] = __float2bfloat16(v - __bfloat162float(h));
}

// ---------------- reductions ----------------
__device__ __forceinline__ float warpReduceSum(float v) {
    #pragma unroll
    for (int o = 16; o > 0; o >>= 1) v += __shfl_xor_sync(0xffffffffu, v, o);
    return v;
}
__device__ __forceinline__ float warpReduceMax(float v) {
    #pragma unroll
    for (int o = 16; o > 0; o >>= 1) v = fmaxf(v, __shfl_xor_sync(0xffffffffu, v, o));
    return v;
}

// ---------------- LayerNorm: fp32 out + bf16 hi/lo out ----------------
__global__ void ln_kernel(const float* __restrict__ in, const float* __restrict__ resid,
                          const float* __restrict__ gamma, const float* __restrict__ beta,
                          float* __restrict__ out,
                          __nv_bfloat16* __restrict__ oh, __nv_bfloat16* __restrict__ ol) {
    long base = (long)blockIdx.x * E_DIM;
    int tid = threadIdx.x;
    float vals[3];
    float s = 0.f, s2 = 0.f;
    #pragma unroll
    for (int i = 0; i < 3; i++) {
        int c = tid + i * 256;
        float v = in[base + c];
        if (resid) v += resid[base + c];
        vals[i] = v; s += v; s2 += v * v;
    }
    __shared__ float shs[8], shs2[8];
    s = warpReduceSum(s); s2 = warpReduceSum(s2);
    int lane = tid & 31, w = tid >> 5;
    if (lane == 0) { shs[w] = s; shs2[w] = s2; }
    __syncthreads();
    if (tid < 32) {
        float a = (lane < 8) ? shs[lane]  : 0.f;
        float b = (lane < 8) ? shs2[lane] : 0.f;
        a = warpReduceSum(a); b = warpReduceSum(b);
        if (lane == 0) { shs[0] = a; shs2[0] = b; }
    }
    __syncthreads();
    float mean = shs[0] * (1.f / E_DIM);
    float var  = shs2[0] * (1.f / E_DIM) - mean * mean;
    float rstd = rsqrtf(var + 1e-5f);
    #pragma unroll
    for (int i = 0; i < 3; i++) {
        int c = tid + i * 256;
        float v = (vals[i] - mean) * rstd * gamma[c] + beta[c];
        out[base + c] = v;
        split_store(v, oh, ol, base + c);
    }
}

// ---------------- causal softmax: fp32 scores in, bf16 hi/lo probs out ----------------
__global__ void softmax_causal(const float* __restrict__ scores,
                               __nv_bfloat16* __restrict__ ah, __nv_bfloat16* __restrict__ al) {
    int srow = blockIdx.x;
    long off = ((long)blockIdx.y * S_LEN + srow) * S_LEN;
    const float* row = scores + off;
    int tid = threadIdx.x;
    const float scale = 0.03608439182435161f;  // 1/sqrt(768)
    float v[4];
    float mx = -1e30f;
    #pragma unroll
    for (int i = 0; i < 4; i++) {
        int t = tid + i * 256;
        float val = (t <= srow) ? row[t] * scale : -1e30f;
        v[i] = val; mx = fmaxf(mx, val);
    }
    __shared__ float sh[8];
    int lane = tid & 31, w = tid >> 5;
    mx = warpReduceMax(mx);
    if (lane == 0) sh[w] = mx;
    __syncthreads();
    if (tid < 32) {
        float m2 = (lane < 8) ? sh[lane] : -1e30f;
        m2 = warpReduceMax(m2);
        if (lane == 0) sh[0] = m2;
    }
    __syncthreads();
    mx = sh[0];
    __syncthreads();
    float sum = 0.f;
    #pragma unroll
    for (int i = 0; i < 4; i++) {
        int t = tid + i * 256;
        float e = (t <= srow) ? __expf(v[i] - mx) : 0.f;
        v[i] = e; sum += e;
    }
    sum = warpReduceSum(sum);
    if (lane == 0) sh[w] = sum;
    __syncthreads();
    if (tid < 32) {
        float s2 = (lane < 8) ? sh[lane] : 0.f;
        s2 = warpReduceSum(s2);
        if (lane == 0) sh[0] = s2;
    }
    __syncthreads();
    float inv = 1.f / sh[0];
    #pragma unroll
    for (int i = 0; i < 4; i++) {
        int t = tid + i * 256;
        split_store(v[i] * inv, ah, al, off + t);
    }
}

// ---------------- tiled transpose + bf16 split: src[R,C] f32 -> dst[C,R] hi/lo ----------------
__global__ void transpose_conv(const float* __restrict__ src,
                               __nv_bfloat16* __restrict__ dh, __nv_bfloat16* __restrict__ dl,
                               int R, int C, long sS, long sD) {
    __shared__ float t[32][33];
    src += (long)blockIdx.z * sS;
    dh  += (long)blockIdx.z * sD;
    dl  += (long)blockIdx.z * sD;
    int c0 = blockIdx.x * 32, r0 = blockIdx.y * 32;
    #pragma unroll
    for (int i = 0; i < 32; i += 8)
        t[threadIdx.y + i][threadIdx.x] = src[(long)(r0 + threadIdx.y + i) * C + c0 + threadIdx.x];
    __syncthreads();
    #pragma unroll
    for (int i = 0; i < 32; i += 8) {
        float v = t[threadIdx.x][threadIdx.y + i];
        long o = (long)(c0 + threadIdx.y + i) * R + r0 + threadIdx.x;
        __nv_bfloat16 h = __float2bfloat16(v);
        dh[o] = h;
        dl[o] = __float2bfloat16(v - __bfloat162float(h));
    }
}

// ---------------- mma.sync bf16x3 GEMM ----------------
// C[M,N] = (Ah+Al)[M,K] @ (Bh+Bl)[N,K]^T  (both K-major), fp32 accum in regs.
// Tile 128x128, BK=64 bf16 (128B SW128 rows). 8 warps (4m x 2n), warp tile 32x64.
// 3-stage cp.async pipeline; fragments (Ah,Al,Bh,Bl) loaded once per k16-step.
// epi: 0 bias, 1 bias+GELU(exact), 2 bias+residual.
// causal: 0 none, 1 skip upper blocks, 2 K limited to row0+128.
// catmode: write Ch/Cl at [(z&3)*S + row][(z>>2)*E + col], ld=HE.
constexpr int STAGE_BYTES = 65536;
constexpr int GEMM_SMEM = 3 * STAGE_BYTES + 128;

__global__ void __launch_bounds__(256, 1)
gemm_mma(const __nv_bfloat16* __restrict__ Ah, const __nv_bfloat16* __restrict__ Al,
         const __nv_bfloat16* __restrict__ Bh, const __nv_bfloat16* __restrict__ Bl,
         const float* __restrict__ bias, const float* __restrict__ res,
         float* __restrict__ Cf, __nv_bfloat16* __restrict__ Ch, __nv_bfloat16* __restrict__ Cl,
         int Ntot, int K,
         long sA, long sB, long sBias, long sC,
         int epi, int causal, int catmode) {
    extern __shared__ char smem_raw[];
    const int row0 = blockIdx.y * 128;
    const int col0 = blockIdx.x * 128;
    if (causal == 1 && col0 > row0 + 127) return;

    const int z = blockIdx.z;
    Ah += (long)z * sA; Al += (long)z * sA;
    Bh += (long)z * sB; Bl += (long)z * sB;
    if (bias) bias += (long)z * sBias;
    if (!catmode) {
        if (Cf) Cf += (long)z * sC;
        if (Ch) { Ch += (long)z * sC; Cl += (long)z * sC; }
    }

    const int tid = threadIdx.x;
    const int wid = tid >> 5, lane = tid & 31;
    const int warp_m = wid & 3, warp_n = wid >> 2;

    uint32_t sbase = (smem_u32(smem_raw) + 127) & ~127u;

    int Keff = K;
    if (causal == 2) { int kl = row0 + 128; Keff = kl < K ? kl : K; }
    const int nch = Keff >> 6;

    float acc[2][8][4];
    #pragma unroll
    for (int a = 0; a < 2; a++)
        #pragma unroll
        for (int b = 0; b < 8; b++)
            #pragma unroll
            for (int d = 0; d < 4; d++) acc[a][b][d] = 0.f;

    const __nv_bfloat16* srcs[4] = {Ah, Al, Bh, Bl};
    const int rbs[4] = {row0, row0, col0, col0};

    auto issue = [&](int c) {
        uint32_t dstb = sbase + (uint32_t)(c % 3) * STAGE_BYTES;
        int k0 = c << 6;
        #pragma unroll
        for (int t = 0; t < 4; t++) {
            #pragma unroll
            for (int i = 0; i < 4; i++) {
                int idx = i * 256 + tid;
                int r = idx >> 3, kb = idx & 7;
                uint32_t so = (uint32_t)(r * 128 + ((kb * 16) ^ ((r & 7) << 4)));
                const void* src = (const char*)(srcs[t] + (long)(rbs[t] + r) * K + k0) + kb * 16;
                cp_async16(dstb + t * 16384 + so, src);
            }
        }
        cp_commit();
    };

    // ldmatrix lane addressing pieces
    const int li  = lane & 7;
    const int s8  = (lane >> 3) & 1;
    const int s16 = lane >> 4;

    // precomputed per-thread row offsets (row*128) and swizzle keys
    int ar[2], arsw[2];
    #pragma unroll
    for (int mt = 0; mt < 2; mt++) {
        int r = warp_m * 32 + mt * 16 + s8 * 8 + li;
        ar[mt] = r * 128; arsw[mt] = (r & 7) << 4;
    }
    int br[4], brsw[4];
    #pragma unroll
    for (int nt2 = 0; nt2 < 4; nt2++) {
        int r = warp_n * 64 + nt2 * 16 + s8 * 8 + li;
        br[nt2] = r * 128; brsw[nt2] = (r & 7) << 4;
    }

    issue(0);
    if (nch > 1) issue(1);
    for (int c = 0; c < nch; c++) {
        if (c + 2 < nch) { issue(c + 2); cp_wait2(); }
        else if (c + 1 < nch) cp_wait1();
        else cp_wait0();
        __syncthreads();
        uint32_t bufb = sbase + (uint32_t)(c % 3) * STAGE_BYTES;

        #pragma unroll
        for (int ks = 0; ks < 4; ks++) {
            const int kb = ks * 32 + s16 * 16;
            uint32_t afh[2][4], afl[2][4];
            #pragma unroll
            for (int mt = 0; mt < 2; mt++) {
                uint32_t off = (uint32_t)(ar[mt] + (kb ^ arsw[mt]));
                ldmatrix_x4(afh[mt][0], afh[mt][1], afh[mt][2], afh[mt][3], bufb + off);
                ldmatrix_x4(afl[mt][0], afl[mt][1], afl[mt][2], afl[mt][3], bufb + 16384 + off);
            }
            uint32_t bfh[8][2], bfl[8][2];
            #pragma unroll
            for (int nt2 = 0; nt2 < 4; nt2++) {
                uint32_t off = (uint32_t)(br[nt2] + (kb ^ brsw[nt2]));
                uint32_t r0, r1, r2, r3;
                ldmatrix_x4(r0, r1, r2, r3, bufb + 32768 + off);
                bfh[nt2 * 2][0] = r0; bfh[nt2 * 2][1] = r2;
                bfh[nt2 * 2 + 1][0] = r1; bfh[nt2 * 2 + 1][1] = r3;
                ldmatrix_x4(r0, r1, r2, r3, bufb + 49152 + off);
                bfl[nt2 * 2][0] = r0; bfl[nt2 * 2][1] = r2;
                bfl[nt2 * 2 + 1][0] = r1; bfl[nt2 * 2 + 1][1] = r3;
            }
            #pragma unroll
            for (int mt = 0; mt < 2; mt++) {
                #pragma unroll
                for (int nt = 0; nt < 8; nt++) {
                    MMA16816(acc[mt][nt], afh[mt], bfh[nt][0], bfh[nt][1]);
                    MMA16816(acc[mt][nt], afh[mt], bfl[nt][0], bfl[nt][1]);
                    MMA16816(acc[mt][nt], afl[mt], bfh[nt][0], bfh[nt][1]);
                }
            }
        }
        __syncthreads();
    }

    // ---------------- epilogue straight from register fragments ----------------
    const int g = lane >> 2, t = lane & 3;
    const int hh = z >> 2, nb = z & 3;
    #pragma unroll
    for (int mt = 0; mt < 2; mt++)
        #pragma unroll
        for (int nt = 0; nt < 8; nt++)
            #pragma unroll
            for (int hr = 0; hr < 2; hr++) {
                int gr = row0 + warp_m * 32 + mt * 16 + g + hr * 8;
                int gc = col0 + warp_n * 64 + nt * 8 + t * 2;
                float v0 = acc[mt][nt][hr * 2];
                float v1 = acc[mt][nt][hr * 2 + 1];
                if (bias) { v0 += bias[gc]; v1 += bias[gc + 1]; }
                if (epi == 1) { v0 = v0 * normcdff(v0); v1 = v1 * normcdff(v1); }
                else if (epi == 2) {
                    long o = (long)gr * Ntot + gc;
                    v0 += res[o]; v1 += res[o + 1];
                }
                if (Cf) {
                    long o = (long)gr * Ntot + gc;
                    Cf[o] = v0; Cf[o + 1] = v1;
                }
                if (Ch) {
                    long o = catmode ? ((long)(nb * S_LEN + gr) * HE + (long)hh * E_DIM + gc)
                                     : ((long)gr * Ntot + gc);
                    __nv_bfloat16 h0 = __float2bfloat16(v0);
                    __nv_bfloat16 h1 = __float2bfloat16(v1);
                    __nv_bfloat162 hp; hp.x = h0; hp.y = h1;
                    *(__nv_bfloat162*)(Ch + o) = hp;
                    __nv_bfloat162 lp;
                    lp.x = __float2bfloat16(v0 - __bfloat162float(h0));
                    lp.y = __float2bfloat16(v1 - __bfloat162float(h1));
                    *(__nv_bfloat162*)(Cl + o) = lp;
                }
            }
}

// ---------------- launch ----------------
extern "C" void kernel_launch(void* const* d_in, const int* in_sizes, int n_in,
                              void* d_out, int out_size) {
    const float* inputs = (const float*)d_in[0];
    const float* g1  = (const float*)d_in[1];
    const float* b1  = (const float*)d_in[2];
    const float* Wq  = (const float*)d_in[3];
    const float* bq  = (const float*)d_in[4];
    const float* Wk  = (const float*)d_in[5];
    const float* bk  = (const float*)d_in[6];
    const float* Wv  = (const float*)d_in[7];
    const float* bv  = (const float*)d_in[8];
    const float* Wc  = (const float*)d_in[9];
    const float* bc  = (const float*)d_in[10];
    const float* g2  = (const float*)d_in[11];
    const float* b2  = (const float*)d_in[12];
    const float* Wfc = (const float*)d_in[13];
    const float* bfc = (const float*)d_in[14];
    const float* Wp  = (const float*)d_in[15];
    const float* bp  = (const float*)d_in[16];
    float* out = (float*)d_out;

    cudaFuncSetAttribute(gemm_mma, cudaFuncAttributeMaxDynamicSharedMemorySize, GEMM_SMEM);

    float *x, *v, *sc, *mha, *y2;
    __nv_bfloat16 *xh, *xl, *wqth, *wqtl, *wkth, *wktl, *wvth, *wvtl;
    __nv_bfloat16 *qh, *ql, *kh, *kl, *vth, *vtl, *ah, *al;
    __nv_bfloat16 *cath, *catl, *wcth, *wctl, *y2h, *y2l, *wfcth, *wfctl, *hbh, *hbl, *wpth, *wptl;
    cudaGetSymbolAddress((void**)&x, g_x);     cudaGetSymbolAddress((void**)&xh, g_xh);
    cudaGetSymbolAddress((void**)&xl, g_xl);
    cudaGetSymbolAddress((void**)&wqth, g_wqth); cudaGetSymbolAddress((void**)&wqtl, g_wqtl);
    cudaGetSymbolAddress((void**)&wkth, g_wkth); cudaGetSymbolAddress((void**)&wktl, g_wktl);
    cudaGetSymbolAddress((void**)&wvth, g_wvth); cudaGetSymbolAddress((void**)&wvtl, g_wvtl);
    cudaGetSymbolAddress((void**)&qh, g_qh);   cudaGetSymbolAddress((void**)&ql, g_ql);
    cudaGetSymbolAddress((void**)&kh, g_kh);   cudaGetSymbolAddress((void**)&kl, g_kl);
    cudaGetSymbolAddress((void**)&v, g_v);
    cudaGetSymbolAddress((void**)&vth, g_vth); cudaGetSymbolAddress((void**)&vtl, g_vtl);
    cudaGetSymbolAddress((void**)&sc, g_sc);
    cudaGetSymbolAddress((void**)&ah, g_ah);   cudaGetSymbolAddress((void**)&al, g_al);
    cudaGetSymbolAddress((void**)&cath, g_cath); cudaGetSymbolAddress((void**)&catl, g_catl);
    cudaGetSymbolAddress((void**)&wcth, g_wcth); cudaGetSymbolAddress((void**)&wctl, g_wctl);
    cudaGetSymbolAddress((void**)&mha, g_mha);
    cudaGetSymbolAddress((void**)&y2, g_y2);
    cudaGetSymbolAddress((void**)&y2h, g_y2h); cudaGetSymbolAddress((void**)&y2l, g_y2l);
    cudaGetSymbolAddress((void**)&wfcth, g_wfcth); cudaGetSymbolAddress((void**)&wfctl, g_wfctl);
    cudaGetSymbolAddress((void**)&hbh, g_hbh); cudaGetSymbolAddress((void**)&hbl, g_hbl);
    cudaGetSymbolAddress((void**)&wpth, g_wpth); cudaGetSymbolAddress((void**)&wptl, g_wptl);

    const long WEE = (long)E_DIM * E_DIM;
    const long QKV = (long)NS * E_DIM;
    const long ATT = (long)S_LEN * E_DIM;
    const long SCS = (long)S_LEN * S_LEN;
    dim3 tb(32, 8);

    // weight transposes + splits (W[in,out] -> W^T[out,in] hi/lo, K-major for mma B)
    transpose_conv<<<dim3(E_DIM / 32, E_DIM / 32, H_HEADS), tb>>>(Wq, wqth, wqtl, E_DIM, E_DIM, WEE, WEE);
    transpose_conv<<<dim3(E_DIM / 32, E_DIM / 32, H_HEADS), tb>>>(Wk, wkth, wktl, E_DIM, E_DIM, WEE, WEE);
    transpose_conv<<<dim3(E_DIM / 32, E_DIM / 32, H_HEADS), tb>>>(Wv, wvth, wvtl, E_DIM, E_DIM, WEE, WEE);
    transpose_conv<<<dim3(E_DIM / 32, HE / 32, 1), tb>>>(Wc, wcth, wctl, HE, E_DIM, 0, 0);
    transpose_conv<<<dim3(FF / 32, E_DIM / 32, 1), tb>>>(Wfc, wfcth, wfctl, E_DIM, FF, 0, 0);
    transpose_conv<<<dim3(E_DIM / 32, FF / 32, 1), tb>>>(Wp, wpth, wptl, FF, E_DIM, 0, 0);

    // 1) LN1 -> x (fp32 + hi/lo)
    ln_kernel<<<NS, 256>>>(inputs, nullptr, g1, b1, x, xh, xl);

    // 2) QKV projections (z = head)
    dim3 gQKV(E_DIM / 128, NS / 128, H_HEADS);
    gemm_mma<<<gQKV, 256, GEMM_SMEM>>>(xh, xl, wqth, wqtl, bq, nullptr,
                                       nullptr, qh, ql, E_DIM, E_DIM,
                                       0, WEE, E_DIM, QKV, 0, 0, 0);
    gemm_mma<<<gQKV, 256, GEMM_SMEM>>>(xh, xl, wkth, wktl, bk, nullptr,
                                       nullptr, kh, kl, E_DIM, E_DIM,
                                       0, WEE, E_DIM, QKV, 0, 0, 0);
    gemm_mma<<<gQKV, 256, GEMM_SMEM>>>(xh, xl, wvth, wvtl, bv, nullptr,
                                       v, nullptr, nullptr, E_DIM, E_DIM,
                                       0, WEE, E_DIM, QKV, 0, 0, 0);

    // 3) v -> v^T hi/lo per (h,n)  (K-major for mma B operand of attn@V)
    transpose_conv<<<dim3(E_DIM / 32, S_LEN / 32, H_HEADS * N_B), tb>>>(v, vth, vtl, S_LEN, E_DIM, ATT, ATT);

    // 4) scores = Q @ K^T (causal block skip), fp32 out
    dim3 gSC(S_LEN / 128, S_LEN / 128, H_HEADS * N_B);
    gemm_mma<<<gSC, 256, GEMM_SMEM>>>(qh, ql, kh, kl, nullptr, nullptr,
                                      sc, nullptr, nullptr, S_LEN, E_DIM,
                                      ATT, ATT, 0, SCS, 0, 1, 0);

    // 5) softmax -> attn hi/lo
    softmax_causal<<<dim3(S_LEN, H_HEADS * N_B), 256>>>(sc, ah, al);

    // 6) heads = attn @ V^T, epilogue writes straight into cat layout (hi/lo)
    dim3 gAV(E_DIM / 128, S_LEN / 128, H_HEADS * N_B);
    gemm_mma<<<gAV, 256, GEMM_SMEM>>>(ah, al, vth, vtl, nullptr, nullptr,
                                      nullptr, cath, catl, E_DIM, S_LEN,
                                      SCS, ATT, 0, 0, 0, 2, 1);

    // 7) c_proj
    dim3 gCP(E_DIM / 128, NS / 128, 1);
    gemm_mma<<<gCP, 256, GEMM_SMEM>>>(cath, catl, wcth, wctl, bc, nullptr,
                                      mha, nullptr, nullptr, E_DIM, HE,
                                      0, 0, 0, 0, 0, 0, 0);

    // 8) y2 = LN2(mha + x)
    ln_kernel<<<NS, 256>>>(mha, x, g2, b2, y2, y2h, y2l);

    // 9) fc + GELU -> hb hi/lo
    dim3 gFC(FF / 128, NS / 128, 1);
    gemm_mma<<<gFC, 256, GEMM_SMEM>>>(y2h, y2l, wfcth, wfctl, bfc, nullptr,
                                      nullptr, hbh, hbl, FF, E_DIM,
                                      0, 0, 0, 0, 1, 0, 0);

    // 10) proj + bias + residual(y2) -> out
    dim3 gPJ(E_DIM / 128, NS / 128, 1);
    gemm_mma<<<gPJ, 256, GEMM_SMEM>>>(hbh, hbl, wpth, wptl, bp, y2,
                                      out, nullptr, nullptr, E_DIM, FF,
                                      0, 0, 0, 0, 2, 0, 0);
}

// round 10
// speedup vs baseline: 2.6587x; 1.0150x over previous
#include <cuda_runtime.h>
#include <cuda_bf16.h>
#include <math.h>
#include <stdint.h>
#include <string.h>

// Problem constants
#define N_B    4
#define S_LEN  1024
#define E_DIM  768
#define H_HEADS 12
constexpr int NS  = N_B * S_LEN;       // 4096
constexpr int HE  = H_HEADS * E_DIM;   // 9216
constexpr int FF  = 4 * E_DIM;         // 3072

// ---------------- scratch (__device__ globals; allocation-free) ----------------
__device__ float         g_x   [(size_t)NS * E_DIM];
__device__ __nv_bfloat16 g_xh  [(size_t)NS * E_DIM];
__device__ __nv_bfloat16 g_xl  [(size_t)NS * E_DIM];

__device__ __nv_bfloat16 g_wqth[(size_t)H_HEADS * E_DIM * E_DIM];
__device__ __nv_bfloat16 g_wqtl[(size_t)H_HEADS * E_DIM * E_DIM];
__device__ __nv_bfloat16 g_wkth[(size_t)H_HEADS * E_DIM * E_DIM];
__device__ __nv_bfloat16 g_wktl[(size_t)H_HEADS * E_DIM * E_DIM];
__device__ __nv_bfloat16 g_wvth[(size_t)H_HEADS * E_DIM * E_DIM];
__device__ __nv_bfloat16 g_wvtl[(size_t)H_HEADS * E_DIM * E_DIM];

__device__ __nv_bfloat16 g_qh  [(size_t)H_HEADS * NS * E_DIM];
__device__ __nv_bfloat16 g_ql  [(size_t)H_HEADS * NS * E_DIM];
__device__ __nv_bfloat16 g_kh  [(size_t)H_HEADS * NS * E_DIM];
__device__ __nv_bfloat16 g_kl  [(size_t)H_HEADS * NS * E_DIM];
__device__ float         g_v   [(size_t)H_HEADS * NS * E_DIM];
__device__ __nv_bfloat16 g_vth [(size_t)H_HEADS * NS * E_DIM];
__device__ __nv_bfloat16 g_vtl [(size_t)H_HEADS * NS * E_DIM];

__device__ float         g_sc  [(size_t)H_HEADS * N_B * S_LEN * S_LEN];
__device__ __nv_bfloat16 g_ah  [(size_t)H_HEADS * N_B * S_LEN * S_LEN];
__device__ __nv_bfloat16 g_al  [(size_t)H_HEADS * N_B * S_LEN * S_LEN];

__device__ __nv_bfloat16 g_cath[(size_t)NS * HE];
__device__ __nv_bfloat16 g_catl[(size_t)NS * HE];
__device__ __nv_bfloat16 g_wcth[(size_t)HE * E_DIM];
__device__ __nv_bfloat16 g_wctl[(size_t)HE * E_DIM];
__device__ float         g_mha [(size_t)NS * E_DIM];

__device__ float         g_y2  [(size_t)NS * E_DIM];
__device__ __nv_bfloat16 g_y2h [(size_t)NS * E_DIM];
__device__ __nv_bfloat16 g_y2l [(size_t)NS * E_DIM];
__device__ __nv_bfloat16 g_wfcth[(size_t)E_DIM * FF];
__device__ __nv_bfloat16 g_wfctl[(size_t)E_DIM * FF];
__device__ __nv_bfloat16 g_hbh [(size_t)NS * FF];
__device__ __nv_bfloat16 g_hbl [(size_t)NS * FF];
__device__ __nv_bfloat16 g_wpth[(size_t)FF * E_DIM];
__device__ __nv_bfloat16 g_wptl[(size_t)FF * E_DIM];

// ---------------- helpers ----------------
__device__ __forceinline__ uint32_t smem_u32(const void* p) {
    uint32_t a;
    asm("{ .reg .u64 t; cvta.to.shared.u64 t, %1; cvt.u32.u64 %0, t; }" : "=r"(a) : "l"(p));
    return a;
}

__device__ __forceinline__ void cp_async16(uint32_t dst, const void* src) {
    asm volatile("cp.async.cg.shared.global [%0], [%1], 16;" :: "r"(dst), "l"(src) : "memory");
}
__device__ __forceinline__ void cp_commit() {
    asm volatile("cp.async.commit_group;" ::: "memory");
}
__device__ __forceinline__ void cp_wait2() { asm volatile("cp.async.wait_group 2;" ::: "memory"); }
__device__ __forceinline__ void cp_wait1() { asm volatile("cp.async.wait_group 1;" ::: "memory"); }
__device__ __forceinline__ void cp_wait0() { asm volatile("cp.async.wait_group 0;" ::: "memory"); }

__device__ __forceinline__ void ldmatrix_x4(uint32_t& r0, uint32_t& r1, uint32_t& r2, uint32_t& r3,
                                            uint32_t addr) {
    asm volatile("ldmatrix.sync.aligned.m8n8.x4.shared.b16 {%0,%1,%2,%3}, [%4];"
                 : "=r"(r0), "=r"(r1), "=r"(r2), "=r"(r3) : "r"(addr));
}

#define MMA16816(acc, af, b0, b1) \
    asm volatile( \
        "mma.sync.aligned.m16n8k16.row.col.f32.bf16.bf16.f32 " \
        "{%0,%1,%2,%3}, {%4,%5,%6,%7}, {%8,%9}, {%0,%1,%2,%3};" \
        : "+f"((acc)[0]), "+f"((acc)[1]), "+f"((acc)[2]), "+f"((acc)[3]) \
        : "r"((af)[0]), "r"((af)[1]), "r"((af)[2]), "r"((af)[3]), \
          "r"(b0), "r"(b1))

__device__ __forceinline__ void split_store(float v, __nv_bfloat16* ph, __nv_bfloat16* pl, long o) {
    __nv_bfloat16 h = __float2bfloat16(v);
    ph[o] = h;
    pl[o] = __float2bfloat16(v - __bfloat162float(h));
}

// ---------------- reductions ----------------
__device__ __forceinline__ float warpReduceSum(float v) {
    #pragma unroll
    for (int o = 16; o > 0; o >>= 1) v += __shfl_xor_sync(0xffffffffu, v, o);
    return v;
}
__device__ __forceinline__ float warpReduceMax(float v) {
    #pragma unroll
    for (int o = 16; o > 0; o >>= 1) v = fmaxf(v, __shfl_xor_sync(0xffffffffu, v, o));
    return v;
}

// ---------------- LayerNorm: fp32 out + bf16 hi/lo out ----------------
__global__ void ln_kernel(const float* __restrict__ in, const float* __restrict__ resid,
                          const float* __restrict__ gamma, const float* __restrict__ beta,
                          float* __restrict__ out,
                          __nv_bfloat16* __restrict__ oh, __nv_bfloat16* __restrict__ ol) {
    long base = (long)blockIdx.x * E_DIM;
    int tid = threadIdx.x;
    float vals[3];
    float s = 0.f, s2 = 0.f;
    #pragma unroll
    for (int i = 0; i < 3; i++) {
        int c = tid + i * 256;
        float v = in[base + c];
        if (resid) v += resid[base + c];
        vals[i] = v; s += v; s2 += v * v;
    }
    __shared__ float shs[8], shs2[8];
    s = warpReduceSum(s); s2 = warpReduceSum(s2);
    int lane = tid & 31, w = tid >> 5;
    if (lane == 0) { shs[w] = s; shs2[w] = s2; }
    __syncthreads();
    if (tid < 32) {
        float a = (lane < 8) ? shs[lane]  : 0.f;
        float b = (lane < 8) ? shs2[lane] : 0.f;
        a = warpReduceSum(a); b = warpReduceSum(b);
        if (lane == 0) { shs[0] = a; shs2[0] = b; }
    }
    __syncthreads();
    float mean = shs[0] * (1.f / E_DIM);
    float var  = shs2[0] * (1.f / E_DIM) - mean * mean;
    float rstd = rsqrtf(var + 1e-5f);
    #pragma unroll
    for (int i = 0; i < 3; i++) {
        int c = tid + i * 256;
        float v = (vals[i] - mean) * rstd * gamma[c] + beta[c];
        out[base + c] = v;
        split_store(v, oh, ol, base + c);
    }
}

// ---------------- causal softmax: fp32 scores in, bf16 hi/lo probs out ----------------
__global__ void softmax_causal(const float* __restrict__ scores,
                               __nv_bfloat16* __restrict__ ah, __nv_bfloat16* __restrict__ al) {
    int srow = blockIdx.x;
    long off = ((long)blockIdx.y * S_LEN + srow) * S_LEN;
    const float* row = scores + off;
    int tid = threadIdx.x;
    const float scale = 0.03608439182435161f;  // 1/sqrt(768)
    float v[4];
    float mx = -1e30f;
    #pragma unroll
    for (int i = 0; i < 4; i++) {
        int t = tid + i * 256;
        float val = (t <= srow) ? row[t] * scale : -1e30f;
        v[i] = val; mx = fmaxf(mx, val);
    }
    __shared__ float sh[8];
    int lane = tid & 31, w = tid >> 5;
    mx = warpReduceMax(mx);
    if (lane == 0) sh[w] = mx;
    __syncthreads();
    if (tid < 32) {
        float m2 = (lane < 8) ? sh[lane] : -1e30f;
        m2 = warpReduceMax(m2);
        if (lane == 0) sh[0] = m2;
    }
    __syncthreads();
    mx = sh[0];
    __syncthreads();
    float sum = 0.f;
    #pragma unroll
    for (int i = 0; i < 4; i++) {
        int t = tid + i * 256;
        float e = (t <= srow) ? __expf(v[i] - mx) : 0.f;
        v[i] = e; sum += e;
    }
    sum = warpReduceSum(sum);
    if (lane == 0) sh[w] = sum;
    __syncthreads();
    if (tid < 32) {
        float s2 = (lane < 8) ? sh[lane] : 0.f;
        s2 = warpReduceSum(s2);
        if (lane == 0) sh[0] = s2;
    }
    __syncthreads();
    float inv = 1.f / sh[0];
    #pragma unroll
    for (int i = 0; i < 4; i++) {
        int t = tid + i * 256;
        split_store(v[i] * inv, ah, al, off + t);
    }
}

// ---------------- tiled transpose + bf16 split: src[R,C] f32 -> dst[C,R] hi/lo ----------------
__global__ void transpose_conv(const float* __restrict__ src,
                               __nv_bfloat16* __restrict__ dh, __nv_bfloat16* __restrict__ dl,
                               int R, int C, long sS, long sD) {
    __shared__ float t[32][33];
    src += (long)blockIdx.z * sS;
    dh  += (long)blockIdx.z * sD;
    dl  += (long)blockIdx.z * sD;
    int c0 = blockIdx.x * 32, r0 = blockIdx.y * 32;
    #pragma unroll
    for (int i = 0; i < 32; i += 8)
        t[threadIdx.y + i][threadIdx.x] = src[(long)(r0 + threadIdx.y + i) * C + c0 + threadIdx.x];
    __syncthreads();
    #pragma unroll
    for (int i = 0; i < 32; i += 8) {
        float v = t[threadIdx.x][threadIdx.y + i];
        long o = (long)(c0 + threadIdx.y + i) * R + r0 + threadIdx.x;
        __nv_bfloat16 h = __float2bfloat16(v);
        dh[o] = h;
        dl[o] = __float2bfloat16(v - __bfloat162float(h));
    }
}

// ---------------- mma.sync bf16x3 GEMM ----------------
// C[M,N] = (Ah+Al)[M,K] @ (Bh+Bl)[N,K]^T  (both K-major), fp32 accum in regs.
// Tile 128x128, BK=64 bf16 (128B SW128 rows). 8 warps (4m x 2n), warp tile 32x64.
// 3-stage cp.async pipeline; fragments loaded once per k16-step; MMAs issued
// PASS-MAJOR (16 independent accumulators between reuses -> no RAW stalls).
// epi: 0 bias, 1 bias+GELU(exact), 2 bias+residual.
// causal: 0 none, 1 skip upper blocks, 2 K limited to row0+128.
// catmode: write Ch/Cl at [(z&3)*S + row][(z>>2)*E + col], ld=HE.
constexpr int STAGE_BYTES = 65536;
constexpr int GEMM_SMEM = 3 * STAGE_BYTES + 128;

__global__ void __launch_bounds__(256, 1)
gemm_mma(const __nv_bfloat16* __restrict__ Ah, const __nv_bfloat16* __restrict__ Al,
         const __nv_bfloat16* __restrict__ Bh, const __nv_bfloat16* __restrict__ Bl,
         const float* __restrict__ bias, const float* __restrict__ res,
         float* __restrict__ Cf, __nv_bfloat16* __restrict__ Ch, __nv_bfloat16* __restrict__ Cl,
         int Ntot, int K,
         long sA, long sB, long sBias, long sC,
         int epi, int causal, int catmode) {
    extern __shared__ char smem_raw[];
    const int row0 = blockIdx.y * 128;
    const int col0 = blockIdx.x * 128;
    if (causal == 1 && col0 > row0 + 127) return;

    const int z = blockIdx.z;
    Ah += (long)z * sA; Al += (long)z * sA;
    Bh += (long)z * sB; Bl += (long)z * sB;
    if (bias) bias += (long)z * sBias;
    if (!catmode) {
        if (Cf) Cf += (long)z * sC;
        if (Ch) { Ch += (long)z * sC; Cl += (long)z * sC; }
    }

    const int tid = threadIdx.x;
    const int wid = tid >> 5, lane = tid & 31;
    const int warp_m = wid & 3, warp_n = wid >> 2;

    uint32_t sbase = (smem_u32(smem_raw) + 127) & ~127u;

    int Keff = K;
    if (causal == 2) { int kl = row0 + 128; Keff = kl < K ? kl : K; }
    const int nch = Keff >> 6;

    float acc[2][8][4];
    #pragma unroll
    for (int a = 0; a < 2; a++)
        #pragma unroll
        for (int b = 0; b < 8; b++)
            #pragma unroll
            for (int d = 0; d < 4; d++) acc[a][b][d] = 0.f;

    const __nv_bfloat16* srcs[4] = {Ah, Al, Bh, Bl};
    const int rbs[4] = {row0, row0, col0, col0};

    auto issue = [&](int c) {
        uint32_t dstb = sbase + (uint32_t)(c % 3) * STAGE_BYTES;
        int k0 = c << 6;
        #pragma unroll
        for (int t = 0; t < 4; t++) {
            #pragma unroll
            for (int i = 0; i < 4; i++) {
                int idx = i * 256 + tid;
                int r = idx >> 3, kb = idx & 7;
                uint32_t so = (uint32_t)(r * 128 + ((kb * 16) ^ ((r & 7) << 4)));
                const void* src = (const char*)(srcs[t] + (long)(rbs[t] + r) * K + k0) + kb * 16;
                cp_async16(dstb + t * 16384 + so, src);
            }
        }
        cp_commit();
    };

    // ldmatrix lane addressing pieces
    const int li  = lane & 7;
    const int s8  = (lane >> 3) & 1;
    const int s16 = lane >> 4;

    // precomputed per-thread row offsets (row*128) and swizzle keys
    int ar[2], arsw[2];
    #pragma unroll
    for (int mt = 0; mt < 2; mt++) {
        int r = warp_m * 32 + mt * 16 + s8 * 8 + li;
        ar[mt] = r * 128; arsw[mt] = (r & 7) << 4;
    }
    int br[4], brsw[4];
    #pragma unroll
    for (int nt2 = 0; nt2 < 4; nt2++) {
        int r = warp_n * 64 + nt2 * 16 + s8 * 8 + li;
        br[nt2] = r * 128; brsw[nt2] = (r & 7) << 4;
    }

    issue(0);
    if (nch > 1) issue(1);
    for (int c = 0; c < nch; c++) {
        if (c + 2 < nch) { issue(c + 2); cp_wait2(); }
        else if (c + 1 < nch) cp_wait1();
        else cp_wait0();
        __syncthreads();
        uint32_t bufb = sbase + (uint32_t)(c % 3) * STAGE_BYTES;

        #pragma unroll
        for (int ks = 0; ks < 4; ks++) {
            const int kb = ks * 32 + s16 * 16;
            uint32_t afh[2][4], afl[2][4];
            #pragma unroll
            for (int mt = 0; mt < 2; mt++) {
                uint32_t off = (uint32_t)(ar[mt] + (kb ^ arsw[mt]));
                ldmatrix_x4(afh[mt][0], afh[mt][1], afh[mt][2], afh[mt][3], bufb + off);
                ldmatrix_x4(afl[mt][0], afl[mt][1], afl[mt][2], afl[mt][3], bufb + 16384 + off);
            }
            uint32_t bfh[8][2], bfl[8][2];
            #pragma unroll
            for (int nt2 = 0; nt2 < 4; nt2++) {
                uint32_t off = (uint32_t)(br[nt2] + (kb ^ brsw[nt2]));
                uint32_t r0, r1, r2, r3;
                ldmatrix_x4(r0, r1, r2, r3, bufb + 32768 + off);
                bfh[nt2 * 2][0] = r0; bfh[nt2 * 2][1] = r2;
                bfh[nt2 * 2 + 1][0] = r1; bfh[nt2 * 2 + 1][1] = r3;
                ldmatrix_x4(r0, r1, r2, r3, bufb + 49152 + off);
                bfl[nt2 * 2][0] = r0; bfl[nt2 * 2][1] = r2;
                bfl[nt2 * 2 + 1][0] = r1; bfl[nt2 * 2 + 1][1] = r3;
            }
            // PASS-MAJOR issue: each accumulator touched once per 16 MMAs,
            // so the RAW distance always exceeds HMMA latency.
            #pragma unroll
            for (int mt = 0; mt < 2; mt++)
                #pragma unroll
                for (int nt = 0; nt < 8; nt++)
                    MMA16816(acc[mt][nt], afh[mt], bfh[nt][0], bfh[nt][1]);
            #pragma unroll
            for (int mt = 0; mt < 2; mt++)
                #pragma unroll
                for (int nt = 0; nt < 8; nt++)
                    MMA16816(acc[mt][nt], afh[mt], bfl[nt][0], bfl[nt][1]);
            #pragma unroll
            for (int mt = 0; mt < 2; mt++)
                #pragma unroll
                for (int nt = 0; nt < 8; nt++)
                    MMA16816(acc[mt][nt], afl[mt], bfh[nt][0], bfh[nt][1]);
        }
        __syncthreads();
    }

    // ---------------- epilogue straight from register fragments ----------------
    const int g = lane >> 2, t = lane & 3;
    const int hh = z >> 2, nb = z & 3;
    #pragma unroll
    for (int mt = 0; mt < 2; mt++)
        #pragma unroll
        for (int nt = 0; nt < 8; nt++)
            #pragma unroll
            for (int hr = 0; hr < 2; hr++) {
                int gr = row0 + warp_m * 32 + mt * 16 + g + hr * 8;
                int gc = col0 + warp_n * 64 + nt * 8 + t * 2;
                float v0 = acc[mt][nt][hr * 2];
                float v1 = acc[mt][nt][hr * 2 + 1];
                if (bias) { v0 += bias[gc]; v1 += bias[gc + 1]; }
                if (epi == 1) { v0 = v0 * normcdff(v0); v1 = v1 * normcdff(v1); }
                else if (epi == 2) {
                    long o = (long)gr * Ntot + gc;
                    v0 += res[o]; v1 += res[o + 1];
                }
                if (Cf) {
                    long o = (long)gr * Ntot + gc;
                    Cf[o] = v0; Cf[o + 1] = v1;
                }
                if (Ch) {
                    long o = catmode ? ((long)(nb * S_LEN + gr) * HE + (long)hh * E_DIM + gc)
                                     : ((long)gr * Ntot + gc);
                    __nv_bfloat16 h0 = __float2bfloat16(v0);
                    __nv_bfloat16 h1 = __float2bfloat16(v1);
                    __nv_bfloat162 hp; hp.x = h0; hp.y = h1;
                    *(__nv_bfloat162*)(Ch + o) = hp;
                    __nv_bfloat162 lp;
                    lp.x = __float2bfloat16(v0 - __bfloat162float(h0));
                    lp.y = __float2bfloat16(v1 - __bfloat162float(h1));
                    *(__nv_bfloat162*)(Cl + o) = lp;
                }
            }
}

// ---------------- launch ----------------
extern "C" void kernel_launch(void* const* d_in, const int* in_sizes, int n_in,
                              void* d_out, int out_size) {
    const float* inputs = (const float*)d_in[0];
    const float* g1  = (const float*)d_in[1];
    const float* b1  = (const float*)d_in[2];
    const float* Wq  = (const float*)d_in[3];
    const float* bq  = (const float*)d_in[4];
    const float* Wk  = (const float*)d_in[5];
    const float* bk  = (const float*)d_in[6];
    const float* Wv  = (const float*)d_in[7];
    const float* bv  = (const float*)d_in[8];
    const float* Wc  = (const float*)d_in[9];
    const float* bc  = (const float*)d_in[10];
    const float* g2  = (const float*)d_in[11];
    const float* b2  = (const float*)d_in[12];
    const float* Wfc = (const float*)d_in[13];
    const float* bfc = (const float*)d_in[14];
    const float* Wp  = (const float*)d_in[15];
    const float* bp  = (const float*)d_in[16];
    float* out = (float*)d_out;

    cudaFuncSetAttribute(gemm_mma, cudaFuncAttributeMaxDynamicSharedMemorySize, GEMM_SMEM);

    float *x, *v, *sc, *mha, *y2;
    __nv_bfloat16 *xh, *xl, *wqth, *wqtl, *wkth, *wktl, *wvth, *wvtl;
    __nv_bfloat16 *qh, *ql, *kh, *kl, *vth, *vtl, *ah, *al;
    __nv_bfloat16 *cath, *catl, *wcth, *wctl, *y2h, *y2l, *wfcth, *wfctl, *hbh, *hbl, *wpth, *wptl;
    cudaGetSymbolAddress((void**)&x, g_x);     cudaGetSymbolAddress((void**)&xh, g_xh);
    cudaGetSymbolAddress((void**)&xl, g_xl);
    cudaGetSymbolAddress((void**)&wqth, g_wqth); cudaGetSymbolAddress((void**)&wqtl, g_wqtl);
    cudaGetSymbolAddress((void**)&wkth, g_wkth); cudaGetSymbolAddress((void**)&wktl, g_wktl);
    cudaGetSymbolAddress((void**)&wvth, g_wvth); cudaGetSymbolAddress((void**)&wvtl, g_wvtl);
    cudaGetSymbolAddress((void**)&qh, g_qh);   cudaGetSymbolAddress((void**)&ql, g_ql);
    cudaGetSymbolAddress((void**)&kh, g_kh);   cudaGetSymbolAddress((void**)&kl, g_kl);
    cudaGetSymbolAddress((void**)&v, g_v);
    cudaGetSymbolAddress((void**)&vth, g_vth); cudaGetSymbolAddress((void**)&vtl, g_vtl);
    cudaGetSymbolAddress((void**)&sc, g_sc);
    cudaGetSymbolAddress((void**)&ah, g_ah);   cudaGetSymbolAddress((void**)&al, g_al);
    cudaGetSymbolAddress((void**)&cath, g_cath); cudaGetSymbolAddress((void**)&catl, g_catl);
    cudaGetSymbolAddress((void**)&wcth, g_wcth); cudaGetSymbolAddress((void**)&wctl, g_wctl);
    cudaGetSymbolAddress((void**)&mha, g_mha);
    cudaGetSymbolAddress((void**)&y2, g_y2);
    cudaGetSymbolAddress((void**)&y2h, g_y2h); cudaGetSymbolAddress((void**)&y2l, g_y2l);
    cudaGetSymbolAddress((void**)&wfcth, g_wfcth); cudaGetSymbolAddress((void**)&wfctl, g_wfctl);
    cudaGetSymbolAddress((void**)&hbh, g_hbh); cudaGetSymbolAddress((void**)&hbl, g_hbl);
    cudaGetSymbolAddress((void**)&wpth, g_wpth); cudaGetSymbolAddress((void**)&wptl, g_wptl);

    const long WEE = (long)E_DIM * E_DIM;
    const long QKV = (long)NS * E_DIM;
    const long ATT = (long)S_LEN * E_DIM;
    const long SCS = (long)S_LEN * S_LEN;
    dim3 tb(32, 8);

    // weight transposes + splits (W[in,out] -> W^T[out,in] hi/lo, K-major for mma B)
    transpose_conv<<<dim3(E_DIM / 32, E_DIM / 32, H_HEADS), tb>>>(Wq, wqth, wqtl, E_DIM, E_DIM, WEE, WEE);
    transpose_conv<<<dim3(E_DIM / 32, E_DIM / 32, H_HEADS), tb>>>(Wk, wkth, wktl, E_DIM, E_DIM, WEE, WEE);
    transpose_conv<<<dim3(E_DIM / 32, E_DIM / 32, H_HEADS), tb>>>(Wv, wvth, wvtl, E_DIM, E_DIM, WEE, WEE);
    transpose_conv<<<dim3(E_DIM / 32, HE / 32, 1), tb>>>(Wc, wcth, wctl, HE, E_DIM, 0, 0);
    transpose_conv<<<dim3(FF / 32, E_DIM / 32, 1), tb>>>(Wfc, wfcth, wfctl, E_DIM, FF, 0, 0);
    transpose_conv<<<dim3(E_DIM / 32, FF / 32, 1), tb>>>(Wp, wpth, wptl, FF, E_DIM, 0, 0);

    // 1) LN1 -> x (fp32 + hi/lo)
    ln_kernel<<<NS, 256>>>(inputs, nullptr, g1, b1, x, xh, xl);

    // 2) QKV projections (z = head)
    dim3 gQKV(E_DIM / 128, NS / 128, H_HEADS);
    gemm_mma<<<gQKV, 256, GEMM_SMEM>>>(xh, xl, wqth, wqtl, bq, nullptr,
                                       nullptr, qh, ql, E_DIM, E_DIM,
                                       0, WEE, E_DIM, QKV, 0, 0, 0);
    gemm_mma<<<gQKV, 256, GEMM_SMEM>>>(xh, xl, wkth, wktl, bk, nullptr,
                                       nullptr, kh, kl, E_DIM, E_DIM,
                                       0, WEE, E_DIM, QKV, 0, 0, 0);
    gemm_mma<<<gQKV, 256, GEMM_SMEM>>>(xh, xl, wvth, wvtl, bv, nullptr,
                                       v, nullptr, nullptr, E_DIM, E_DIM,
                                       0, WEE, E_DIM, QKV, 0, 0, 0);

    // 3) v -> v^T hi/lo per (h,n)  (K-major for mma B operand of attn@V)
    transpose_conv<<<dim3(E_DIM / 32, S_LEN / 32, H_HEADS * N_B), tb>>>(v, vth, vtl, S_LEN, E_DIM, ATT, ATT);

    // 4) scores = Q @ K^T (causal block skip), fp32 out
    dim3 gSC(S_LEN / 128, S_LEN / 128, H_HEADS * N_B);
    gemm_mma<<<gSC, 256, GEMM_SMEM>>>(qh, ql, kh, kl, nullptr, nullptr,
                                      sc, nullptr, nullptr, S_LEN, E_DIM,
                                      ATT, ATT, 0, SCS, 0, 1, 0);

    // 5) softmax -> attn hi/lo
    softmax_causal<<<dim3(S_LEN, H_HEADS * N_B), 256>>>(sc, ah, al);

    // 6) heads = attn @ V^T, epilogue writes straight into cat layout (hi/lo)
    dim3 gAV(E_DIM / 128, S_LEN / 128, H_HEADS * N_B);
    gemm_mma<<<gAV, 256, GEMM_SMEM>>>(ah, al, vth, vtl, nullptr, nullptr,
                                      nullptr, cath, catl, E_DIM, S_LEN,
                                      SCS, ATT, 0, 0, 0, 2, 1);

    // 7) c_proj
    dim3 gCP(E_DIM / 128, NS / 128, 1);
    gemm_mma<<<gCP, 256, GEMM_SMEM>>>(cath, catl, wcth, wctl, bc, nullptr,
                                      mha, nullptr, nullptr, E_DIM, HE,
                                      0, 0, 0, 0, 0, 0, 0);

    // 8) y2 = LN2(mha + x)
    ln_kernel<<<NS, 256>>>(mha, x, g2, b2, y2, y2h, y2l);

    // 9) fc + GELU -> hb hi/lo
    dim3 gFC(FF / 128, NS / 128, 1);
    gemm_mma<<<gFC, 256, GEMM_SMEM>>>(y2h, y2l, wfcth, wfctl, bfc, nullptr,
                                      nullptr, hbh, hbl, FF, E_DIM,
                                      0, 0, 0, 0, 1, 0, 0);

    // 10) proj + bias + residual(y2) -> out
    dim3 gPJ(E_DIM / 128, NS / 128, 1);
    gemm_mma<<<gPJ, 256, GEMM_SMEM>>>(hbh, hbl, wpth, wptl, bp, y2,
                                      out, nullptr, nullptr, E_DIM, FF,
                                      0, 0, 0, 0, 2, 0, 0);
}

// round 11
// speedup vs baseline: 3.7289x; 1.4025x over previous
#include <cuda_runtime.h>
#include <cuda_fp16.h>
#include <math.h>
#include <stdint.h>
#include <string.h>

// Problem constants
#define N_B    4
#define S_LEN  1024
#define E_DIM  768
#define H_HEADS 12
constexpr int NS  = N_B * S_LEN;       // 4096
constexpr int HE  = H_HEADS * E_DIM;   // 9216
constexpr int FF  = 4 * E_DIM;         // 3072

// ---------------- scratch (__device__ globals; allocation-free) ----------------
__device__ float  g_x   [(size_t)NS * E_DIM];
__device__ __half g_xh  [(size_t)NS * E_DIM];

__device__ __half g_wqth[(size_t)H_HEADS * E_DIM * E_DIM];
__device__ __half g_wqtl[(size_t)H_HEADS * E_DIM * E_DIM];
__device__ __half g_wkth[(size_t)H_HEADS * E_DIM * E_DIM];
__device__ __half g_wktl[(size_t)H_HEADS * E_DIM * E_DIM];
__device__ __half g_wvth[(size_t)H_HEADS * E_DIM * E_DIM];
__device__ __half g_wvtl[(size_t)H_HEADS * E_DIM * E_DIM];

__device__ __half g_qh  [(size_t)H_HEADS * NS * E_DIM];
__device__ __half g_kh  [(size_t)H_HEADS * NS * E_DIM];
__device__ __half g_kl  [(size_t)H_HEADS * NS * E_DIM];
__device__ float  g_v   [(size_t)H_HEADS * NS * E_DIM];
__device__ __half g_vth [(size_t)H_HEADS * NS * E_DIM];
__device__ __half g_vtl [(size_t)H_HEADS * NS * E_DIM];

__device__ float  g_sc  [(size_t)H_HEADS * N_B * S_LEN * S_LEN];
__device__ __half g_ah  [(size_t)H_HEADS * N_B * S_LEN * S_LEN];

__device__ __half g_cath[(size_t)NS * HE];
__device__ __half g_wcth[(size_t)HE * E_DIM];
__device__ __half g_wctl[(size_t)HE * E_DIM];
__device__ float  g_mha [(size_t)NS * E_DIM];

__device__ float  g_y2  [(size_t)NS * E_DIM];
__device__ __half g_y2h [(size_t)NS * E_DIM];
__device__ __half g_wfcth[(size_t)E_DIM * FF];
__device__ __half g_wfctl[(size_t)E_DIM * FF];
__device__ __half g_hbh [(size_t)NS * FF];
__device__ __half g_wpth[(size_t)FF * E_DIM];
__device__ __half g_wptl[(size_t)FF * E_DIM];

// ---------------- helpers ----------------
__device__ __forceinline__ uint32_t smem_u32(const void* p) {
    uint32_t a;
    asm("{ .reg .u64 t; cvta.to.shared.u64 t, %1; cvt.u32.u64 %0, t; }" : "=r"(a) : "l"(p));
    return a;
}

__device__ __forceinline__ void cp_async16(uint32_t dst, const void* src) {
    asm volatile("cp.async.cg.shared.global [%0], [%1], 16;" :: "r"(dst), "l"(src) : "memory");
}
__device__ __forceinline__ void cp_commit() {
    asm volatile("cp.async.commit_group;" ::: "memory");
}
__device__ __forceinline__ void cp_wait2() { asm volatile("cp.async.wait_group 2;" ::: "memory"); }
__device__ __forceinline__ void cp_wait1() { asm volatile("cp.async.wait_group 1;" ::: "memory"); }
__device__ __forceinline__ void cp_wait0() { asm volatile("cp.async.wait_group 0;" ::: "memory"); }

__device__ __forceinline__ void ldmatrix_x4(uint32_t& r0, uint32_t& r1, uint32_t& r2, uint32_t& r3,
                                            uint32_t addr) {
    asm volatile("ldmatrix.sync.aligned.m8n8.x4.shared.b16 {%0,%1,%2,%3}, [%4];"
                 : "=r"(r0), "=r"(r1), "=r"(r2), "=r"(r3) : "r"(addr));
}

#define MMA16816F16(acc, af, b0, b1) \
    asm volatile( \
        "mma.sync.aligned.m16n8k16.row.col.f32.f16.f16.f32 " \
        "{%0,%1,%2,%3}, {%4,%5,%6,%7}, {%8,%9}, {%0,%1,%2,%3};" \
        : "+f"((acc)[0]), "+f"((acc)[1]), "+f"((acc)[2]), "+f"((acc)[3]) \
        : "r"((af)[0]), "r"((af)[1]), "r"((af)[2]), "r"((af)[3]), \
          "r"(b0), "r"(b1))

__device__ __forceinline__ void split_store_h(float v, __half* ph, __half* pl, long o) {
    __half h = __float2half_rn(v);
    ph[o] = h;
    pl[o] = __float2half_rn(v - __half2float(h));
}

// ---------------- reductions ----------------
__device__ __forceinline__ float warpReduceSum(float v) {
    #pragma unroll
    for (int o = 16; o > 0; o >>= 1) v += __shfl_xor_sync(0xffffffffu, v, o);
    return v;
}
__device__ __forceinline__ float warpReduceMax(float v) {
    #pragma unroll
    for (int o = 16; o > 0; o >>= 1) v = fmaxf(v, __shfl_xor_sync(0xffffffffu, v, o));
    return v;
}

// ---------------- LayerNorm: fp32 out + fp16 out ----------------
__global__ void ln_kernel(const float* __restrict__ in, const float* __restrict__ resid,
                          const float* __restrict__ gamma, const float* __restrict__ beta,
                          float* __restrict__ out, __half* __restrict__ oh) {
    long base = (long)blockIdx.x * E_DIM;
    int tid = threadIdx.x;
    float vals[3];
    float s = 0.f, s2 = 0.f;
    #pragma unroll
    for (int i = 0; i < 3; i++) {
        int c = tid + i * 256;
        float v = in[base + c];
        if (resid) v += resid[base + c];
        vals[i] = v; s += v; s2 += v * v;
    }
    __shared__ float shs[8], shs2[8];
    s = warpReduceSum(s); s2 = warpReduceSum(s2);
    int lane = tid & 31, w = tid >> 5;
    if (lane == 0) { shs[w] = s; shs2[w] = s2; }
    __syncthreads();
    if (tid < 32) {
        float a = (lane < 8) ? shs[lane]  : 0.f;
        float b = (lane < 8) ? shs2[lane] : 0.f;
        a = warpReduceSum(a); b = warpReduceSum(b);
        if (lane == 0) { shs[0] = a; shs2[0] = b; }
    }
    __syncthreads();
    float mean = shs[0] * (1.f / E_DIM);
    float var  = shs2[0] * (1.f / E_DIM) - mean * mean;
    float rstd = rsqrtf(var + 1e-5f);
    #pragma unroll
    for (int i = 0; i < 3; i++) {
        int c = tid + i * 256;
        float v = (vals[i] - mean) * rstd * gamma[c] + beta[c];
        out[base + c] = v;
        oh[base + c] = __float2half_rn(v);
    }
}

// ---------------- causal softmax: fp32 scores in, fp16 probs out ----------------
__global__ void softmax_causal(const float* __restrict__ scores, __half* __restrict__ ah) {
    int srow = blockIdx.x;
    long off = ((long)blockIdx.y * S_LEN + srow) * S_LEN;
    const float* row = scores + off;
    int tid = threadIdx.x;
    const float scale = 0.03608439182435161f;  // 1/sqrt(768)
    float v[4];
    float mx = -1e30f;
    #pragma unroll
    for (int i = 0; i < 4; i++) {
        int t = tid + i * 256;
        float val = (t <= srow) ? row[t] * scale : -1e30f;
        v[i] = val; mx = fmaxf(mx, val);
    }
    __shared__ float sh[8];
    int lane = tid & 31, w = tid >> 5;
    mx = warpReduceMax(mx);
    if (lane == 0) sh[w] = mx;
    __syncthreads();
    if (tid < 32) {
        float m2 = (lane < 8) ? sh[lane] : -1e30f;
        m2 = warpReduceMax(m2);
        if (lane == 0) sh[0] = m2;
    }
    __syncthreads();
    mx = sh[0];
    __syncthreads();
    float sum = 0.f;
    #pragma unroll
    for (int i = 0; i < 4; i++) {
        int t = tid + i * 256;
        float e = (t <= srow) ? __expf(v[i] - mx) : 0.f;
        v[i] = e; sum += e;
    }
    sum = warpReduceSum(sum);
    if (lane == 0) sh[w] = sum;
    __syncthreads();
    if (tid < 32) {
        float s2 = (lane < 8) ? sh[lane] : 0.f;
        s2 = warpReduceSum(s2);
        if (lane == 0) sh[0] = s2;
    }
    __syncthreads();
    float inv = 1.f / sh[0];
    #pragma unroll
    for (int i = 0; i < 4; i++) {
        int t = tid + i * 256;
        ah[off + t] = __float2half_rn(v[i] * inv);
    }
}

// ---------------- tiled transpose + fp16 split: src[R,C] f32 -> dst[C,R] hi/lo ----------------
__global__ void transpose_conv(const float* __restrict__ src,
                               __half* __restrict__ dh, __half* __restrict__ dl,
                               int R, int C, long sS, long sD) {
    __shared__ float t[32][33];
    src += (long)blockIdx.z * sS;
    dh  += (long)blockIdx.z * sD;
    dl  += (long)blockIdx.z * sD;
    int c0 = blockIdx.x * 32, r0 = blockIdx.y * 32;
    #pragma unroll
    for (int i = 0; i < 32; i += 8)
        t[threadIdx.y + i][threadIdx.x] = src[(long)(r0 + threadIdx.y + i) * C + c0 + threadIdx.x];
    __syncthreads();
    #pragma unroll
    for (int i = 0; i < 32; i += 8) {
        float v = t[threadIdx.x][threadIdx.y + i];
        long o = (long)(c0 + threadIdx.y + i) * R + r0 + threadIdx.x;
        split_store_h(v, dh, dl, o);
    }
}

// ---------------- mma.sync fp16 2-pass GEMM ----------------
// C[M,N] = A[M,K](fp16) @ (Bh+Bl)[N,K]^T(fp16 hi/lo), fp32 accum in regs.
// Tile 128x128, BK=64 (128B SW128 rows). 8 warps (4m x 2n), warp tile 32x64.
// 3-stage cp.async pipeline; fragments loaded once per k16-step; pass-major issue.
// epi: 0 bias, 1 bias+GELU(exact), 2 bias+residual.
// causal: 0 none, 1 skip upper blocks, 2 K limited to row0+128.
// catmode: write Ch at [(z&3)*S + row][(z>>2)*E + col], ld=HE.
// Outputs: Cf (fp32) and/or Ch (fp16; Cl!=null -> split hi/lo).
constexpr int STAGE_BYTES = 49152;   // 3 tiles x 16KB (A, Bh, Bl)
constexpr int GEMM_SMEM = 3 * STAGE_BYTES + 128;

__global__ void __launch_bounds__(256, 1)
gemm_mma(const __half* __restrict__ A,
         const __half* __restrict__ Bh, const __half* __restrict__ Bl,
         const float* __restrict__ bias, const float* __restrict__ res,
         float* __restrict__ Cf, __half* __restrict__ Ch, __half* __restrict__ Cl,
         int Ntot, int K,
         long sA, long sB, long sBias, long sC,
         int epi, int causal, int catmode) {
    extern __shared__ char smem_raw[];
    const int row0 = blockIdx.y * 128;
    const int col0 = blockIdx.x * 128;
    if (causal == 1 && col0 > row0 + 127) return;

    const int z = blockIdx.z;
    A += (long)z * sA;
    Bh += (long)z * sB; Bl += (long)z * sB;
    if (bias) bias += (long)z * sBias;
    if (!catmode) {
        if (Cf) Cf += (long)z * sC;
        if (Ch) Ch += (long)z * sC;
        if (Cl) Cl += (long)z * sC;
    }

    const int tid = threadIdx.x;
    const int wid = tid >> 5, lane = tid & 31;
    const int warp_m = wid & 3, warp_n = wid >> 2;

    uint32_t sbase = (smem_u32(smem_raw) + 127) & ~127u;

    int Keff = K;
    if (causal == 2) { int kl = row0 + 128; Keff = kl < K ? kl : K; }
    const int nch = Keff >> 6;

    float acc[2][8][4];
    #pragma unroll
    for (int a = 0; a < 2; a++)
        #pragma unroll
        for (int b = 0; b < 8; b++)
            #pragma unroll
            for (int d = 0; d < 4; d++) acc[a][b][d] = 0.f;

    const __half* srcs[3] = {A, Bh, Bl};
    const int rbs[3] = {row0, col0, col0};

    auto issue = [&](int c) {
        uint32_t dstb = sbase + (uint32_t)(c % 3) * STAGE_BYTES;
        int k0 = c << 6;
        #pragma unroll
        for (int t = 0; t < 3; t++) {
            #pragma unroll
            for (int i = 0; i < 4; i++) {
                int idx = i * 256 + tid;
                int r = idx >> 3, kb = idx & 7;
                uint32_t so = (uint32_t)(r * 128 + ((kb * 16) ^ ((r & 7) << 4)));
                const void* src = (const char*)(srcs[t] + (long)(rbs[t] + r) * K + k0) + kb * 16;
                cp_async16(dstb + t * 16384 + so, src);
            }
        }
        cp_commit();
    };

    // ldmatrix lane addressing pieces
    const int li  = lane & 7;
    const int s8  = (lane >> 3) & 1;
    const int s16 = lane >> 4;

    int ar[2], arsw[2];
    #pragma unroll
    for (int mt = 0; mt < 2; mt++) {
        int r = warp_m * 32 + mt * 16 + s8 * 8 + li;
        ar[mt] = r * 128; arsw[mt] = (r & 7) << 4;
    }
    int br[4], brsw[4];
    #pragma unroll
    for (int nt2 = 0; nt2 < 4; nt2++) {
        int r = warp_n * 64 + nt2 * 16 + s8 * 8 + li;
        br[nt2] = r * 128; brsw[nt2] = (r & 7) << 4;
    }

    issue(0);
    if (nch > 1) issue(1);
    for (int c = 0; c < nch; c++) {
        if (c + 2 < nch) { issue(c + 2); cp_wait2(); }
        else if (c + 1 < nch) cp_wait1();
        else cp_wait0();
        __syncthreads();
        uint32_t bufb = sbase + (uint32_t)(c % 3) * STAGE_BYTES;

        #pragma unroll
        for (int ks = 0; ks < 4; ks++) {
            const int kb = ks * 32 + s16 * 16;
            uint32_t af[2][4];
            #pragma unroll
            for (int mt = 0; mt < 2; mt++) {
                uint32_t off = (uint32_t)(ar[mt] + (kb ^ arsw[mt]));
                ldmatrix_x4(af[mt][0], af[mt][1], af[mt][2], af[mt][3], bufb + off);
            }
            uint32_t bfh[8][2], bfl[8][2];
            #pragma unroll
            for (int nt2 = 0; nt2 < 4; nt2++) {
                uint32_t off = (uint32_t)(br[nt2] + (kb ^ brsw[nt2]));
                uint32_t r0, r1, r2, r3;
                ldmatrix_x4(r0, r1, r2, r3, bufb + 16384 + off);
                bfh[nt2 * 2][0] = r0; bfh[nt2 * 2][1] = r2;
                bfh[nt2 * 2 + 1][0] = r1; bfh[nt2 * 2 + 1][1] = r3;
                ldmatrix_x4(r0, r1, r2, r3, bufb + 32768 + off);
                bfl[nt2 * 2][0] = r0; bfl[nt2 * 2][1] = r2;
                bfl[nt2 * 2 + 1][0] = r1; bfl[nt2 * 2 + 1][1] = r3;
            }
            // pass-major: accumulator RAW distance = 16 MMAs
            #pragma unroll
            for (int mt = 0; mt < 2; mt++)
                #pragma unroll
                for (int nt = 0; nt < 8; nt++)
                    MMA16816F16(acc[mt][nt], af[mt], bfh[nt][0], bfh[nt][1]);
            #pragma unroll
            for (int mt = 0; mt < 2; mt++)
                #pragma unroll
                for (int nt = 0; nt < 8; nt++)
                    MMA16816F16(acc[mt][nt], af[mt], bfl[nt][0], bfl[nt][1]);
        }
        __syncthreads();
    }

    // ---------------- epilogue straight from register fragments ----------------
    const int g = lane >> 2, t = lane & 3;
    const int hh = z >> 2, nb = z & 3;
    #pragma unroll
    for (int mt = 0; mt < 2; mt++)
        #pragma unroll
        for (int nt = 0; nt < 8; nt++)
            #pragma unroll
            for (int hr = 0; hr < 2; hr++) {
                int gr = row0 + warp_m * 32 + mt * 16 + g + hr * 8;
                int gc = col0 + warp_n * 64 + nt * 8 + t * 2;
                float v0 = acc[mt][nt][hr * 2];
                float v1 = acc[mt][nt][hr * 2 + 1];
                if (bias) { v0 += bias[gc]; v1 += bias[gc + 1]; }
                if (epi == 1) { v0 = v0 * normcdff(v0); v1 = v1 * normcdff(v1); }
                else if (epi == 2) {
                    long o = (long)gr * Ntot + gc;
                    v0 += res[o]; v1 += res[o + 1];
                }
                if (Cf) {
                    long o = (long)gr * Ntot + gc;
                    Cf[o] = v0; Cf[o + 1] = v1;
                }
                if (Ch) {
                    long o = catmode ? ((long)(nb * S_LEN + gr) * HE + (long)hh * E_DIM + gc)
                                     : ((long)gr * Ntot + gc);
                    __half h0 = __float2half_rn(v0);
                    __half h1 = __float2half_rn(v1);
                    __half2 hp; hp.x = h0; hp.y = h1;
                    *(__half2*)(Ch + o) = hp;
                    if (Cl) {
                        __half2 lp;
                        lp.x = __float2half_rn(v0 - __half2float(h0));
                        lp.y = __float2half_rn(v1 - __half2float(h1));
                        *(__half2*)(Cl + o) = lp;
                    }
                }
            }
}

// ---------------- launch ----------------
extern "C" void kernel_launch(void* const* d_in, const int* in_sizes, int n_in,
                              void* d_out, int out_size) {
    const float* inputs = (const float*)d_in[0];
    const float* g1  = (const float*)d_in[1];
    const float* b1  = (const float*)d_in[2];
    const float* Wq  = (const float*)d_in[3];
    const float* bq  = (const float*)d_in[4];
    const float* Wk  = (const float*)d_in[5];
    const float* bk  = (const float*)d_in[6];
    const float* Wv  = (const float*)d_in[7];
    const float* bv  = (const float*)d_in[8];
    const float* Wc  = (const float*)d_in[9];
    const float* bc  = (const float*)d_in[10];
    const float* g2  = (const float*)d_in[11];
    const float* b2  = (const float*)d_in[12];
    const float* Wfc = (const float*)d_in[13];
    const float* bfc = (const float*)d_in[14];
    const float* Wp  = (const float*)d_in[15];
    const float* bp  = (const float*)d_in[16];
    float* out = (float*)d_out;

    cudaFuncSetAttribute(gemm_mma, cudaFuncAttributeMaxDynamicSharedMemorySize, GEMM_SMEM);

    float *x, *v, *sc, *mha, *y2;
    __half *xh, *wqth, *wqtl, *wkth, *wktl, *wvth, *wvtl;
    __half *qh, *kh, *kl, *vth, *vtl, *ah;
    __half *cath, *wcth, *wctl, *y2h, *wfcth, *wfctl, *hbh, *wpth, *wptl;
    cudaGetSymbolAddress((void**)&x, g_x);     cudaGetSymbolAddress((void**)&xh, g_xh);
    cudaGetSymbolAddress((void**)&wqth, g_wqth); cudaGetSymbolAddress((void**)&wqtl, g_wqtl);
    cudaGetSymbolAddress((void**)&wkth, g_wkth); cudaGetSymbolAddress((void**)&wktl, g_wktl);
    cudaGetSymbolAddress((void**)&wvth, g_wvth); cudaGetSymbolAddress((void**)&wvtl, g_wvtl);
    cudaGetSymbolAddress((void**)&qh, g_qh);
    cudaGetSymbolAddress((void**)&kh, g_kh);   cudaGetSymbolAddress((void**)&kl, g_kl);
    cudaGetSymbolAddress((void**)&v, g_v);
    cudaGetSymbolAddress((void**)&vth, g_vth); cudaGetSymbolAddress((void**)&vtl, g_vtl);
    cudaGetSymbolAddress((void**)&sc, g_sc);
    cudaGetSymbolAddress((void**)&ah, g_ah);
    cudaGetSymbolAddress((void**)&cath, g_cath);
    cudaGetSymbolAddress((void**)&wcth, g_wcth); cudaGetSymbolAddress((void**)&wctl, g_wctl);
    cudaGetSymbolAddress((void**)&mha, g_mha);
    cudaGetSymbolAddress((void**)&y2, g_y2);
    cudaGetSymbolAddress((void**)&y2h, g_y2h);
    cudaGetSymbolAddress((void**)&wfcth, g_wfcth); cudaGetSymbolAddress((void**)&wfctl, g_wfctl);
    cudaGetSymbolAddress((void**)&hbh, g_hbh);
    cudaGetSymbolAddress((void**)&wpth, g_wpth); cudaGetSymbolAddress((void**)&wptl, g_wptl);

    const long WEE = (long)E_DIM * E_DIM;
    const long QKV = (long)NS * E_DIM;
    const long ATT = (long)S_LEN * E_DIM;
    const long SCS = (long)S_LEN * S_LEN;
    dim3 tb(32, 8);

    // Launch order puts the Q-projection GEMM at index 5 for ncu (-s 5 -c 1).
    // 0) LN1 -> x (fp32 + fp16)
    ln_kernel<<<NS, 256>>>(inputs, nullptr, g1, b1, x, xh);
    // 1-4) weight transposes needed before QKV
    transpose_conv<<<dim3(E_DIM / 32, E_DIM / 32, H_HEADS), tb>>>(Wq, wqth, wqtl, E_DIM, E_DIM, WEE, WEE);
    transpose_conv<<<dim3(E_DIM / 32, E_DIM / 32, H_HEADS), tb>>>(Wk, wkth, wktl, E_DIM, E_DIM, WEE, WEE);
    transpose_conv<<<dim3(E_DIM / 32, E_DIM / 32, H_HEADS), tb>>>(Wv, wvth, wvtl, E_DIM, E_DIM, WEE, WEE);
    transpose_conv<<<dim3(E_DIM / 32, HE / 32, 1), tb>>>(Wc, wcth, wctl, HE, E_DIM, 0, 0);

    dim3 gQKV(E_DIM / 128, NS / 128, H_HEADS);
    // 5) Q projection  <-- ncu capture lands here
    gemm_mma<<<gQKV, 256, GEMM_SMEM>>>(xh, wqth, wqtl, bq, nullptr,
                                       nullptr, qh, nullptr, E_DIM, E_DIM,
                                       0, WEE, E_DIM, QKV, 0, 0, 0);
    // 6) K projection (fp16 hi/lo out: B-side of scores)
    gemm_mma<<<gQKV, 256, GEMM_SMEM>>>(xh, wkth, wktl, bk, nullptr,
                                       nullptr, kh, kl, E_DIM, E_DIM,
                                       0, WEE, E_DIM, QKV, 0, 0, 0);
    // 7) V projection (fp32 out, transposed+split below)
    gemm_mma<<<gQKV, 256, GEMM_SMEM>>>(xh, wvth, wvtl, bv, nullptr,
                                       v, nullptr, nullptr, E_DIM, E_DIM,
                                       0, WEE, E_DIM, QKV, 0, 0, 0);

    // remaining weight transposes
    transpose_conv<<<dim3(FF / 32, E_DIM / 32, 1), tb>>>(Wfc, wfcth, wfctl, E_DIM, FF, 0, 0);
    transpose_conv<<<dim3(E_DIM / 32, FF / 32, 1), tb>>>(Wp, wpth, wptl, FF, E_DIM, 0, 0);
    // v -> v^T hi/lo per (h,n)
    transpose_conv<<<dim3(E_DIM / 32, S_LEN / 32, H_HEADS * N_B), tb>>>(v, vth, vtl, S_LEN, E_DIM, ATT, ATT);

    // scores = Q @ K^T (causal block skip), fp32 out
    dim3 gSC(S_LEN / 128, S_LEN / 128, H_HEADS * N_B);
    gemm_mma<<<gSC, 256, GEMM_SMEM>>>(qh, kh, kl, nullptr, nullptr,
                                      sc, nullptr, nullptr, S_LEN, E_DIM,
                                      ATT, ATT, 0, SCS, 0, 1, 0);

    // softmax -> attn fp16
    softmax_causal<<<dim3(S_LEN, H_HEADS * N_B), 256>>>(sc, ah);

    // heads = attn @ V^T, epilogue writes straight into cat layout (fp16)
    dim3 gAV(E_DIM / 128, S_LEN / 128, H_HEADS * N_B);
    gemm_mma<<<gAV, 256, GEMM_SMEM>>>(ah, vth, vtl, nullptr, nullptr,
                                      nullptr, cath, nullptr, E_DIM, S_LEN,
                                      SCS, ATT, 0, 0, 0, 2, 1);

    // c_proj
    dim3 gCP(E_DIM / 128, NS / 128, 1);
    gemm_mma<<<gCP, 256, GEMM_SMEM>>>(cath, wcth, wctl, bc, nullptr,
                                      mha, nullptr, nullptr, E_DIM, HE,
                                      0, 0, 0, 0, 0, 0, 0);

    // y2 = LN2(mha + x)
    ln_kernel<<<NS, 256>>>(mha, x, g2, b2, y2, y2h);

    // fc + GELU -> hb fp16
    dim3 gFC(FF / 128, NS / 128, 1);
    gemm_mma<<<gFC, 256, GEMM_SMEM>>>(y2h, wfcth, wfctl, bfc, nullptr,
                                      nullptr, hbh, nullptr, FF, E_DIM,
                                      0, 0, 0, 0, 1, 0, 0);

    // proj + bias + residual(y2) -> out
    dim3 gPJ(E_DIM / 128, NS / 128, 1);
    gemm_mma<<<gPJ, 256, GEMM_SMEM>>>(hbh, wpth, wptl, bp, y2,
                                      out, nullptr, nullptr, E_DIM, FF,
                                      0, 0, 0, 0, 2, 0, 0);
}

// round 12
// speedup vs baseline: 5.9110x; 1.5852x over previous
#include <cuda_runtime.h>
#include <cuda_fp16.h>
#include <math.h>
#include <stdint.h>
#include <string.h>

// Problem constants
#define N_B    4
#define S_LEN  1024
#define E_DIM  768
#define H_HEADS 12
constexpr int NS  = N_B * S_LEN;       // 4096
constexpr int HE  = H_HEADS * E_DIM;   // 9216
constexpr int FF  = 4 * E_DIM;         // 3072

// ---------------- scratch (__device__ globals; allocation-free) ----------------
__device__ float  g_x   [(size_t)NS * E_DIM];
__device__ __half g_xh  [(size_t)NS * E_DIM];

__device__ __half g_wqth[(size_t)H_HEADS * E_DIM * E_DIM];
__device__ __half g_wkth[(size_t)H_HEADS * E_DIM * E_DIM];
__device__ __half g_wvth[(size_t)H_HEADS * E_DIM * E_DIM];

__device__ __half g_qh  [(size_t)H_HEADS * NS * E_DIM];
__device__ __half g_kh  [(size_t)H_HEADS * NS * E_DIM];
__device__ float  g_v   [(size_t)H_HEADS * NS * E_DIM];
__device__ __half g_vth [(size_t)H_HEADS * NS * E_DIM];

__device__ float  g_sc  [(size_t)H_HEADS * N_B * S_LEN * S_LEN];
__device__ __half g_ah  [(size_t)H_HEADS * N_B * S_LEN * S_LEN];

__device__ __half g_cath[(size_t)NS * HE];
__device__ __half g_wcth[(size_t)HE * E_DIM];
__device__ float  g_mha [(size_t)NS * E_DIM];

__device__ float  g_y2  [(size_t)NS * E_DIM];
__device__ __half g_y2h [(size_t)NS * E_DIM];
__device__ __half g_wfcth[(size_t)E_DIM * FF];
__device__ __half g_hbh [(size_t)NS * FF];
__device__ __half g_wpth[(size_t)FF * E_DIM];

// ---------------- helpers ----------------
__device__ __forceinline__ uint32_t smem_u32(const void* p) {
    uint32_t a;
    asm("{ .reg .u64 t; cvta.to.shared.u64 t, %1; cvt.u32.u64 %0, t; }" : "=r"(a) : "l"(p));
    return a;
}

__device__ __forceinline__ void cp_async16(uint32_t dst, const void* src) {
    asm volatile("cp.async.cg.shared.global [%0], [%1], 16;" :: "r"(dst), "l"(src) : "memory");
}
__device__ __forceinline__ void cp_commit() {
    asm volatile("cp.async.commit_group;" ::: "memory");
}
__device__ __forceinline__ void cp_wait2() { asm volatile("cp.async.wait_group 2;" ::: "memory"); }
__device__ __forceinline__ void cp_wait1() { asm volatile("cp.async.wait_group 1;" ::: "memory"); }
__device__ __forceinline__ void cp_wait0() { asm volatile("cp.async.wait_group 0;" ::: "memory"); }

__device__ __forceinline__ void ldmatrix_x4(uint32_t& r0, uint32_t& r1, uint32_t& r2, uint32_t& r3,
                                            uint32_t addr) {
    asm volatile("ldmatrix.sync.aligned.m8n8.x4.shared.b16 {%0,%1,%2,%3}, [%4];"
                 : "=r"(r0), "=r"(r1), "=r"(r2), "=r"(r3) : "r"(addr));
}

#define MMA16816F16(acc, af, b0, b1) \
    asm volatile( \
        "mma.sync.aligned.m16n8k16.row.col.f32.f16.f16.f32 " \
        "{%0,%1,%2,%3}, {%4,%5,%6,%7}, {%8,%9}, {%0,%1,%2,%3};" \
        : "+f"((acc)[0]), "+f"((acc)[1]), "+f"((acc)[2]), "+f"((acc)[3]) \
        : "r"((af)[0]), "r"((af)[1]), "r"((af)[2]), "r"((af)[3]), \
          "r"(b0), "r"(b1))

// ---------------- reductions ----------------
__device__ __forceinline__ float warpReduceSum(float v) {
    #pragma unroll
    for (int o = 16; o > 0; o >>= 1) v += __shfl_xor_sync(0xffffffffu, v, o);
    return v;
}
__device__ __forceinline__ float warpReduceMax(float v) {
    #pragma unroll
    for (int o = 16; o > 0; o >>= 1) v = fmaxf(v, __shfl_xor_sync(0xffffffffu, v, o));
    return v;
}

// ---------------- LayerNorm: fp32 out + fp16 out ----------------
__global__ void ln_kernel(const float* __restrict__ in, const float* __restrict__ resid,
                          const float* __restrict__ gamma, const float* __restrict__ beta,
                          float* __restrict__ out, __half* __restrict__ oh) {
    long base = (long)blockIdx.x * E_DIM;
    int tid = threadIdx.x;
    float vals[3];
    float s = 0.f, s2 = 0.f;
    #pragma unroll
    for (int i = 0; i < 3; i++) {
        int c = tid + i * 256;
        float v = in[base + c];
        if (resid) v += resid[base + c];
        vals[i] = v; s += v; s2 += v * v;
    }
    __shared__ float shs[8], shs2[8];
    s = warpReduceSum(s); s2 = warpReduceSum(s2);
    int lane = tid & 31, w = tid >> 5;
    if (lane == 0) { shs[w] = s; shs2[w] = s2; }
    __syncthreads();
    if (tid < 32) {
        float a = (lane < 8) ? shs[lane]  : 0.f;
        float b = (lane < 8) ? shs2[lane] : 0.f;
        a = warpReduceSum(a); b = warpReduceSum(b);
        if (lane == 0) { shs[0] = a; shs2[0] = b; }
    }
    __syncthreads();
    float mean = shs[0] * (1.f / E_DIM);
    float var  = shs2[0] * (1.f / E_DIM) - mean * mean;
    float rstd = rsqrtf(var + 1e-5f);
    #pragma unroll
    for (int i = 0; i < 3; i++) {
        int c = tid + i * 256;
        float v = (vals[i] - mean) * rstd * gamma[c] + beta[c];
        out[base + c] = v;
        oh[base + c] = __float2half_rn(v);
    }
}

// ---------------- causal softmax: fp32 scores in, fp16 probs out ----------------
__global__ void softmax_causal(const float* __restrict__ scores, __half* __restrict__ ah) {
    int srow = blockIdx.x;
    long off = ((long)blockIdx.y * S_LEN + srow) * S_LEN;
    const float* row = scores + off;
    int tid = threadIdx.x;
    const float scale = 0.03608439182435161f;  // 1/sqrt(768)
    float v[4];
    float mx = -1e30f;
    #pragma unroll
    for (int i = 0; i < 4; i++) {
        int t = tid + i * 256;
        float val = (t <= srow) ? row[t] * scale : -1e30f;
        v[i] = val; mx = fmaxf(mx, val);
    }
    __shared__ float sh[8];
    int lane = tid & 31, w = tid >> 5;
    mx = warpReduceMax(mx);
    if (lane == 0) sh[w] = mx;
    __syncthreads();
    if (tid < 32) {
        float m2 = (lane < 8) ? sh[lane] : -1e30f;
        m2 = warpReduceMax(m2);
        if (lane == 0) sh[0] = m2;
    }
    __syncthreads();
    mx = sh[0];
    __syncthreads();
    float sum = 0.f;
    #pragma unroll
    for (int i = 0; i < 4; i++) {
        int t = tid + i * 256;
        float e = (t <= srow) ? __expf(v[i] - mx) : 0.f;
        v[i] = e; sum += e;
    }
    sum = warpReduceSum(sum);
    if (lane == 0) sh[w] = sum;
    __syncthreads();
    if (tid < 32) {
        float s2 = (lane < 8) ? sh[lane] : 0.f;
        s2 = warpReduceSum(s2);
        if (lane == 0) sh[0] = s2;
    }
    __syncthreads();
    float inv = 1.f / sh[0];
    #pragma unroll
    for (int i = 0; i < 4; i++) {
        int t = tid + i * 256;
        ah[off + t] = __float2half_rn(v[i] * inv);
    }
}

// ---------------- tiled transpose + fp16 convert: src[R,C] f32 -> dst[C,R] ----------------
__global__ void transpose_conv(const float* __restrict__ src,
                               __half* __restrict__ dh,
                               int R, int C, long sS, long sD) {
    __shared__ float t[32][33];
    src += (long)blockIdx.z * sS;
    dh  += (long)blockIdx.z * sD;
    int c0 = blockIdx.x * 32, r0 = blockIdx.y * 32;
    #pragma unroll
    for (int i = 0; i < 32; i += 8)
        t[threadIdx.y + i][threadIdx.x] = src[(long)(r0 + threadIdx.y + i) * C + c0 + threadIdx.x];
    __syncthreads();
    #pragma unroll
    for (int i = 0; i < 32; i += 8) {
        float v = t[threadIdx.x][threadIdx.y + i];
        long o = (long)(c0 + threadIdx.y + i) * R + r0 + threadIdx.x;
        dh[o] = __float2half_rn(v);
    }
}

// ---------------- mma.sync fp16 single-pass GEMM ----------------
// C[M,N] = A[M,K](fp16) @ B[N,K]^T(fp16), fp32 accum in regs.
// Tile 128x128, BK=64 (128B SW128 rows). 8 warps (4m x 2n), warp tile 32x64.
// 3-stage cp.async pipeline; pass-major issue (RAW distance 16 MMAs).
// epi: 0 bias, 1 bias+GELU(exact), 2 bias+residual.
// causal: 0 none, 1 skip upper blocks, 2 K limited to row0+128.
// catmode: write Ch at [(z&3)*S + row][(z>>2)*E + col], ld=HE.
constexpr int STAGE_BYTES = 32768;   // 2 tiles x 16KB (A, B)
constexpr int GEMM_SMEM = 3 * STAGE_BYTES + 128;

__global__ void __launch_bounds__(256, 1)
gemm_mma(const __half* __restrict__ A, const __half* __restrict__ B,
         const float* __restrict__ bias, const float* __restrict__ res,
         float* __restrict__ Cf, __half* __restrict__ Ch,
         int Ntot, int K,
         long sA, long sB, long sBias, long sC,
         int epi, int causal, int catmode) {
    extern __shared__ char smem_raw[];
    const int row0 = blockIdx.y * 128;
    const int col0 = blockIdx.x * 128;
    if (causal == 1 && col0 > row0 + 127) return;

    const int z = blockIdx.z;
    A += (long)z * sA;
    B += (long)z * sB;
    if (bias) bias += (long)z * sBias;
    if (!catmode) {
        if (Cf) Cf += (long)z * sC;
        if (Ch) Ch += (long)z * sC;
    }

    const int tid = threadIdx.x;
    const int wid = tid >> 5, lane = tid & 31;
    const int warp_m = wid & 3, warp_n = wid >> 2;

    uint32_t sbase = (smem_u32(smem_raw) + 127) & ~127u;

    int Keff = K;
    if (causal == 2) { int kl = row0 + 128; Keff = kl < K ? kl : K; }
    const int nch = Keff >> 6;

    float acc[2][8][4];
    #pragma unroll
    for (int a = 0; a < 2; a++)
        #pragma unroll
        for (int b = 0; b < 8; b++)
            #pragma unroll
            for (int d = 0; d < 4; d++) acc[a][b][d] = 0.f;

    const __half* srcs[2] = {A, B};
    const int rbs[2] = {row0, col0};

    auto issue = [&](int c) {
        uint32_t dstb = sbase + (uint32_t)(c % 3) * STAGE_BYTES;
        int k0 = c << 6;
        #pragma unroll
        for (int t = 0; t < 2; t++) {
            #pragma unroll
            for (int i = 0; i < 4; i++) {
                int idx = i * 256 + tid;
                int r = idx >> 3, kb = idx & 7;
                uint32_t so = (uint32_t)(r * 128 + ((kb * 16) ^ ((r & 7) << 4)));
                const void* src = (const char*)(srcs[t] + (long)(rbs[t] + r) * K + k0) + kb * 16;
                cp_async16(dstb + t * 16384 + so, src);
            }
        }
        cp_commit();
    };

    // ldmatrix lane addressing pieces
    const int li  = lane & 7;
    const int s8  = (lane >> 3) & 1;
    const int s16 = lane >> 4;

    int ar[2], arsw[2];
    #pragma unroll
    for (int mt = 0; mt < 2; mt++) {
        int r = warp_m * 32 + mt * 16 + s8 * 8 + li;
        ar[mt] = r * 128; arsw[mt] = (r & 7) << 4;
    }
    int br[4], brsw[4];
    #pragma unroll
    for (int nt2 = 0; nt2 < 4; nt2++) {
        int r = warp_n * 64 + nt2 * 16 + s8 * 8 + li;
        br[nt2] = r * 128; brsw[nt2] = (r & 7) << 4;
    }

    issue(0);
    if (nch > 1) issue(1);
    for (int c = 0; c < nch; c++) {
        if (c + 2 < nch) { issue(c + 2); cp_wait2(); }
        else if (c + 1 < nch) cp_wait1();
        else cp_wait0();
        __syncthreads();
        uint32_t bufb = sbase + (uint32_t)(c % 3) * STAGE_BYTES;

        #pragma unroll
        for (int ks = 0; ks < 4; ks++) {
            const int kb = ks * 32 + s16 * 16;
            uint32_t af[2][4];
            #pragma unroll
            for (int mt = 0; mt < 2; mt++) {
                uint32_t off = (uint32_t)(ar[mt] + (kb ^ arsw[mt]));
                ldmatrix_x4(af[mt][0], af[mt][1], af[mt][2], af[mt][3], bufb + off);
            }
            uint32_t bf[8][2];
            #pragma unroll
            for (int nt2 = 0; nt2 < 4; nt2++) {
                uint32_t off = (uint32_t)(br[nt2] + (kb ^ brsw[nt2]));
                uint32_t r0, r1, r2, r3;
                ldmatrix_x4(r0, r1, r2, r3, bufb + 16384 + off);
                bf[nt2 * 2][0] = r0; bf[nt2 * 2][1] = r2;
                bf[nt2 * 2 + 1][0] = r1; bf[nt2 * 2 + 1][1] = r3;
            }
            #pragma unroll
            for (int mt = 0; mt < 2; mt++)
                #pragma unroll
                for (int nt = 0; nt < 8; nt++)
                    MMA16816F16(acc[mt][nt], af[mt], bf[nt][0], bf[nt][1]);
        }
        __syncthreads();
    }

    // ---------------- epilogue straight from register fragments ----------------
    const int g = lane >> 2, t = lane & 3;
    const int hh = z >> 2, nb = z & 3;
    #pragma unroll
    for (int mt = 0; mt < 2; mt++)
        #pragma unroll
        for (int nt = 0; nt < 8; nt++)
            #pragma unroll
            for (int hr = 0; hr < 2; hr++) {
                int gr = row0 + warp_m * 32 + mt * 16 + g + hr * 8;
                int gc = col0 + warp_n * 64 + nt * 8 + t * 2;
                float v0 = acc[mt][nt][hr * 2];
                float v1 = acc[mt][nt][hr * 2 + 1];
                if (bias) { v0 += bias[gc]; v1 += bias[gc + 1]; }
                if (epi == 1) { v0 = v0 * normcdff(v0); v1 = v1 * normcdff(v1); }
                else if (epi == 2) {
                    long o = (long)gr * Ntot + gc;
                    v0 += res[o]; v1 += res[o + 1];
                }
                if (Cf) {
                    long o = (long)gr * Ntot + gc;
                    Cf[o] = v0; Cf[o + 1] = v1;
                }
                if (Ch) {
                    long o = catmode ? ((long)(nb * S_LEN + gr) * HE + (long)hh * E_DIM + gc)
                                     : ((long)gr * Ntot + gc);
                    __half2 hp;
                    hp.x = __float2half_rn(v0);
                    hp.y = __float2half_rn(v1);
                    *(__half2*)(Ch + o) = hp;
                }
            }
}

// ---------------- launch ----------------
extern "C" void kernel_launch(void* const* d_in, const int* in_sizes, int n_in,
                              void* d_out, int out_size) {
    const float* inputs = (const float*)d_in[0];
    const float* g1  = (const float*)d_in[1];
    const float* b1  = (const float*)d_in[2];
    const float* Wq  = (const float*)d_in[3];
    const float* bq  = (const float*)d_in[4];
    const float* Wk  = (const float*)d_in[5];
    const float* bk  = (const float*)d_in[6];
    const float* Wv  = (const float*)d_in[7];
    const float* bv  = (const float*)d_in[8];
    const float* Wc  = (const float*)d_in[9];
    const float* bc  = (const float*)d_in[10];
    const float* g2  = (const float*)d_in[11];
    const float* b2  = (const float*)d_in[12];
    const float* Wfc = (const float*)d_in[13];
    const float* bfc = (const float*)d_in[14];
    const float* Wp  = (const float*)d_in[15];
    const float* bp  = (const float*)d_in[16];
    float* out = (float*)d_out;

    cudaFuncSetAttribute(gemm_mma, cudaFuncAttributeMaxDynamicSharedMemorySize, GEMM_SMEM);

    float *x, *v, *sc, *mha, *y2;
    __half *xh, *wqth, *wkth, *wvth;
    __half *qh, *kh, *vth, *ah;
    __half *cath, *wcth, *y2h, *wfcth, *hbh, *wpth;
    cudaGetSymbolAddress((void**)&x, g_x);     cudaGetSymbolAddress((void**)&xh, g_xh);
    cudaGetSymbolAddress((void**)&wqth, g_wqth);
    cudaGetSymbolAddress((void**)&wkth, g_wkth);
    cudaGetSymbolAddress((void**)&wvth, g_wvth);
    cudaGetSymbolAddress((void**)&qh, g_qh);
    cudaGetSymbolAddress((void**)&kh, g_kh);
    cudaGetSymbolAddress((void**)&v, g_v);
    cudaGetSymbolAddress((void**)&vth, g_vth);
    cudaGetSymbolAddress((void**)&sc, g_sc);
    cudaGetSymbolAddress((void**)&ah, g_ah);
    cudaGetSymbolAddress((void**)&cath, g_cath);
    cudaGetSymbolAddress((void**)&wcth, g_wcth);
    cudaGetSymbolAddress((void**)&mha, g_mha);
    cudaGetSymbolAddress((void**)&y2, g_y2);
    cudaGetSymbolAddress((void**)&y2h, g_y2h);
    cudaGetSymbolAddress((void**)&wfcth, g_wfcth);
    cudaGetSymbolAddress((void**)&hbh, g_hbh);
    cudaGetSymbolAddress((void**)&wpth, g_wpth);

    const long WEE = (long)E_DIM * E_DIM;
    const long QKV = (long)NS * E_DIM;
    const long ATT = (long)S_LEN * E_DIM;
    const long SCS = (long)S_LEN * S_LEN;
    dim3 tb(32, 8);

    // 0) LN1 -> x (fp32 + fp16)
    ln_kernel<<<NS, 256>>>(inputs, nullptr, g1, b1, x, xh);
    // 1-4) weight transposes needed before QKV
    transpose_conv<<<dim3(E_DIM / 32, E_DIM / 32, H_HEADS), tb>>>(Wq, wqth, E_DIM, E_DIM, WEE, WEE);
    transpose_conv<<<dim3(E_DIM / 32, E_DIM / 32, H_HEADS), tb>>>(Wk, wkth, E_DIM, E_DIM, WEE, WEE);
    transpose_conv<<<dim3(E_DIM / 32, E_DIM / 32, H_HEADS), tb>>>(Wv, wvth, E_DIM, E_DIM, WEE, WEE);
    transpose_conv<<<dim3(E_DIM / 32, HE / 32, 1), tb>>>(Wc, wcth, HE, E_DIM, 0, 0);

    dim3 gQKV(E_DIM / 128, NS / 128, H_HEADS);
    // 5) Q projection  <-- ncu capture lands here
    gemm_mma<<<gQKV, 256, GEMM_SMEM>>>(xh, wqth, bq, nullptr,
                                       nullptr, qh, E_DIM, E_DIM,
                                       0, WEE, E_DIM, QKV, 0, 0, 0);
    // 6) K projection
    gemm_mma<<<gQKV, 256, GEMM_SMEM>>>(xh, wkth, bk, nullptr,
                                       nullptr, kh, E_DIM, E_DIM,
                                       0, WEE, E_DIM, QKV, 0, 0, 0);
    // 7) V projection (fp32 out, transposed below)
    gemm_mma<<<gQKV, 256, GEMM_SMEM>>>(xh, wvth, bv, nullptr,
                                       v, nullptr, E_DIM, E_DIM,
                                       0, WEE, E_DIM, QKV, 0, 0, 0);

    // remaining weight transposes
    transpose_conv<<<dim3(FF / 32, E_DIM / 32, 1), tb>>>(Wfc, wfcth, E_DIM, FF, 0, 0);
    transpose_conv<<<dim3(E_DIM / 32, FF / 32, 1), tb>>>(Wp, wpth, FF, E_DIM, 0, 0);
    // v -> v^T per (h,n)
    transpose_conv<<<dim3(E_DIM / 32, S_LEN / 32, H_HEADS * N_B), tb>>>(v, vth, S_LEN, E_DIM, ATT, ATT);

    // scores = Q @ K^T (causal block skip), fp32 out
    dim3 gSC(S_LEN / 128, S_LEN / 128, H_HEADS * N_B);
    gemm_mma<<<gSC, 256, GEMM_SMEM>>>(qh, kh, nullptr, nullptr,
                                      sc, nullptr, S_LEN, E_DIM,
                                      ATT, ATT, 0, SCS, 0, 1, 0);

    // softmax -> attn fp16
    softmax_causal<<<dim3(S_LEN, H_HEADS * N_B), 256>>>(sc, ah);

    // heads = attn @ V^T, epilogue writes straight into cat layout (fp16)
    dim3 gAV(E_DIM / 128, S_LEN / 128, H_HEADS * N_B);
    gemm_mma<<<gAV, 256, GEMM_SMEM>>>(ah, vth, nullptr, nullptr,
                                      nullptr, cath, E_DIM, S_LEN,
                                      SCS, ATT, 0, 0, 0, 2, 1);

    // c_proj
    dim3 gCP(E_DIM / 128, NS / 128, 1);
    gemm_mma<<<gCP, 256, GEMM_SMEM>>>(cath, wcth, bc, nullptr,
                                      mha, nullptr, E_DIM, HE,
                                      0, 0, 0, 0, 0, 0, 0);

    // y2 = LN2(mha + x)
    ln_kernel<<<NS, 256>>>(mha, x, g2, b2, y2, y2h);

    // fc + GELU -> hb fp16
    dim3 gFC(FF / 128, NS / 128, 1);
    gemm_mma<<<gFC, 256, GEMM_SMEM>>>(y2h, wfcth, bfc, nullptr,
                                      nullptr, hbh, FF, E_DIM,
                                      0, 0, 0, 0, 1, 0, 0);

    // proj + bias + residual(y2) -> out
    dim3 gPJ(E_DIM / 128, NS / 128, 1);
    gemm_mma<<<gPJ, 256, GEMM_SMEM>>>(hbh, wpth, bp, y2,
                                      out, nullptr, E_DIM, FF,
                                      0, 0, 0, 0, 2, 0, 0);
}

// round 13
// speedup vs baseline: 5.9898x; 1.0133x over previous
#include <cuda_runtime.h>
#include <cuda_fp16.h>
#include <math.h>
#include <stdint.h>
#include <string.h>

// Problem constants
#define N_B    4
#define S_LEN  1024
#define E_DIM  768
#define H_HEADS 12
constexpr int NS  = N_B * S_LEN;       // 4096
constexpr int HE  = H_HEADS * E_DIM;   // 9216
constexpr int FF  = 4 * E_DIM;         // 3072

// ---------------- scratch (__device__ globals; allocation-free) ----------------
__device__ float  g_x   [(size_t)NS * E_DIM];
__device__ __half g_xh  [(size_t)NS * E_DIM];

__device__ __half g_wqth[(size_t)H_HEADS * E_DIM * E_DIM];
__device__ __half g_wkth[(size_t)H_HEADS * E_DIM * E_DIM];
__device__ __half g_wvth[(size_t)H_HEADS * E_DIM * E_DIM];

__device__ __half g_qh  [(size_t)H_HEADS * NS * E_DIM];
__device__ __half g_kh  [(size_t)H_HEADS * NS * E_DIM];
__device__ __half g_vth [(size_t)H_HEADS * NS * E_DIM];   // [h*4+n][e][t] panes

__device__ float  g_sc  [(size_t)H_HEADS * N_B * S_LEN * S_LEN];
__device__ __half g_ah  [(size_t)H_HEADS * N_B * S_LEN * S_LEN];

__device__ __half g_cath[(size_t)NS * HE];
__device__ __half g_wcth[(size_t)HE * E_DIM];
__device__ float  g_mha [(size_t)NS * E_DIM];

__device__ float  g_y2  [(size_t)NS * E_DIM];
__device__ __half g_y2h [(size_t)NS * E_DIM];
__device__ __half g_wfcth[(size_t)E_DIM * FF];
__device__ __half g_hbh [(size_t)NS * FF];
__device__ __half g_wpth[(size_t)FF * E_DIM];

// ---------------- helpers ----------------
__device__ __forceinline__ uint32_t smem_u32(const void* p) {
    uint32_t a;
    asm("{ .reg .u64 t; cvta.to.shared.u64 t, %1; cvt.u32.u64 %0, t; }" : "=r"(a) : "l"(p));
    return a;
}

__device__ __forceinline__ void cp_async16(uint32_t dst, const void* src) {
    asm volatile("cp.async.cg.shared.global [%0], [%1], 16;" :: "r"(dst), "l"(src) : "memory");
}
__device__ __forceinline__ void cp_commit() {
    asm volatile("cp.async.commit_group;" ::: "memory");
}
__device__ __forceinline__ void cp_wait2() { asm volatile("cp.async.wait_group 2;" ::: "memory"); }
__device__ __forceinline__ void cp_wait1() { asm volatile("cp.async.wait_group 1;" ::: "memory"); }
__device__ __forceinline__ void cp_wait0() { asm volatile("cp.async.wait_group 0;" ::: "memory"); }

__device__ __forceinline__ void ldmatrix_x4(uint32_t& r0, uint32_t& r1, uint32_t& r2, uint32_t& r3,
                                            uint32_t addr) {
    asm volatile("ldmatrix.sync.aligned.m8n8.x4.shared.b16 {%0,%1,%2,%3}, [%4];"
                 : "=r"(r0), "=r"(r1), "=r"(r2), "=r"(r3) : "r"(addr));
}

#define MMA16816F16(acc, af, b0, b1) \
    asm volatile( \
        "mma.sync.aligned.m16n8k16.row.col.f32.f16.f16.f32 " \
        "{%0,%1,%2,%3}, {%4,%5,%6,%7}, {%8,%9}, {%0,%1,%2,%3};" \
        : "+f"((acc)[0]), "+f"((acc)[1]), "+f"((acc)[2]), "+f"((acc)[3]) \
        : "r"((af)[0]), "r"((af)[1]), "r"((af)[2]), "r"((af)[3]), \
          "r"(b0), "r"(b1))

// ---------------- reductions ----------------
__device__ __forceinline__ float warpReduceSum(float v) {
    #pragma unroll
    for (int o = 16; o > 0; o >>= 1) v += __shfl_xor_sync(0xffffffffu, v, o);
    return v;
}
__device__ __forceinline__ float warpReduceMax(float v) {
    #pragma unroll
    for (int o = 16; o > 0; o >>= 1) v = fmaxf(v, __shfl_xor_sync(0xffffffffu, v, o));
    return v;
}

// ---------------- LayerNorm: fp32 out + fp16 out ----------------
__global__ void ln_kernel(const float* __restrict__ in, const float* __restrict__ resid,
                          const float* __restrict__ gamma, const float* __restrict__ beta,
                          float* __restrict__ out, __half* __restrict__ oh) {
    long base = (long)blockIdx.x * E_DIM;
    int tid = threadIdx.x;
    float vals[3];
    float s = 0.f, s2 = 0.f;
    #pragma unroll
    for (int i = 0; i < 3; i++) {
        int c = tid + i * 256;
        float v = in[base + c];
        if (resid) v += resid[base + c];
        vals[i] = v; s += v; s2 += v * v;
    }
    __shared__ float shs[8], shs2[8];
    s = warpReduceSum(s); s2 = warpReduceSum(s2);
    int lane = tid & 31, w = tid >> 5;
    if (lane == 0) { shs[w] = s; shs2[w] = s2; }
    __syncthreads();
    if (tid < 32) {
        float a = (lane < 8) ? shs[lane]  : 0.f;
        float b = (lane < 8) ? shs2[lane] : 0.f;
        a = warpReduceSum(a); b = warpReduceSum(b);
        if (lane == 0) { shs[0] = a; shs2[0] = b; }
    }
    __syncthreads();
    float mean = shs[0] * (1.f / E_DIM);
    float var  = shs2[0] * (1.f / E_DIM) - mean * mean;
    float rstd = rsqrtf(var + 1e-5f);
    #pragma unroll
    for (int i = 0; i < 3; i++) {
        int c = tid + i * 256;
        float v = (vals[i] - mean) * rstd * gamma[c] + beta[c];
        out[base + c] = v;
        oh[base + c] = __float2half_rn(v);
    }
}

// ---------------- causal softmax (truncated to the live causal extent) ----------------
__global__ void softmax_causal(const float* __restrict__ scores, __half* __restrict__ ah) {
    int srow = blockIdx.x;
    long off = ((long)blockIdx.y * S_LEN + srow) * S_LEN;
    const float* row = scores + off;
    int tid = threadIdx.x;
    const float scale = 0.03608439182435161f;  // 1/sqrt(768)
    const int L = ((srow >> 7) + 1) << 7;      // AV never reads cols >= L
    float v[4];
    float mx = -1e30f;
    #pragma unroll
    for (int i = 0; i < 4; i++) {
        int t = tid + i * 256;
        float val = (t <= srow) ? row[t] * scale : -1e30f;
        v[i] = val; mx = fmaxf(mx, val);
    }
    __shared__ float sh[8];
    int lane = tid & 31, w = tid >> 5;
    mx = warpReduceMax(mx);
    if (lane == 0) sh[w] = mx;
    __syncthreads();
    if (tid < 32) {
        float m2 = (lane < 8) ? sh[lane] : -1e30f;
        m2 = warpReduceMax(m2);
        if (lane == 0) sh[0] = m2;
    }
    __syncthreads();
    mx = sh[0];
    __syncthreads();
    float sum = 0.f;
    #pragma unroll
    for (int i = 0; i < 4; i++) {
        int t = tid + i * 256;
        float e = (t <= srow) ? __expf(v[i] - mx) : 0.f;
        v[i] = e; sum += e;
    }
    sum = warpReduceSum(sum);
    if (lane == 0) sh[w] = sum;
    __syncthreads();
    if (tid < 32) {
        float s2 = (lane < 8) ? sh[lane] : 0.f;
        s2 = warpReduceSum(s2);
        if (lane == 0) sh[0] = s2;
    }
    __syncthreads();
    float inv = 1.f / sh[0];
    #pragma unroll
    for (int i = 0; i < 4; i++) {
        int t = tid + i * 256;
        if (t < L) ah[off + t] = __float2half_rn(v[i] * inv);
    }
}

// ---------------- tiled transpose + fp16 convert: src[R?,C] f32 -> dst[C,R] ----------------
__global__ void transpose_conv(const float* __restrict__ src,
                               __half* __restrict__ dh,
                               int R, int C, long sS, long sD) {
    __shared__ float t[32][33];
    src += (long)blockIdx.z * sS;
    dh  += (long)blockIdx.z * sD;
    int c0 = blockIdx.x * 32, r0 = blockIdx.y * 32;
    #pragma unroll
    for (int i = 0; i < 32; i += 8)
        t[threadIdx.y + i][threadIdx.x] = src[(long)(r0 + threadIdx.y + i) * C + c0 + threadIdx.x];
    __syncthreads();
    #pragma unroll
    for (int i = 0; i < 32; i += 8) {
        float v = t[threadIdx.x][threadIdx.y + i];
        long o = (long)(c0 + threadIdx.y + i) * R + r0 + threadIdx.x;
        dh[o] = __float2half_rn(v);
    }
}

// ---------------- mma.sync fp16 single-pass GEMM, BK=128 ----------------
// C[M,N] = A[M,K](fp16) @ B[N,K]^T(fp16), fp32 accum in regs.
// Tile 128x128, BK=128 (two 64-K sub-tiles, each 128B SW128 rows).
// 8 warps (4m x 2n), warp tile 32x64. 3-stage cp.async pipeline; pass-major issue.
// epi: 0 bias, 1 bias+GELU(exact), 2 bias+residual.
// causal: 0 none, 1 skip upper blocks, 2 K limited to row0+128.
// catmode: 0 normal; 1 cat-heads scatter; 2 V^T pane scatter (row-bias).
constexpr int STAGE_BYTES = 65536;   // 2 tiles x 32KB
constexpr int GEMM_SMEM = 3 * STAGE_BYTES + 128;

__global__ void __launch_bounds__(256, 1)
gemm_mma(const __half* __restrict__ A, const __half* __restrict__ B,
         const float* __restrict__ bias, const float* __restrict__ res,
         float* __restrict__ Cf, __half* __restrict__ Ch,
         int Ntot, int K,
         long sA, long sB, long sBias, long sC,
         int epi, int causal, int catmode) {
    extern __shared__ char smem_raw[];
    const int row0 = blockIdx.y * 128;
    const int col0 = blockIdx.x * 128;
    if (causal == 1 && col0 > row0 + 127) return;

    const int z = blockIdx.z;
    A += (long)z * sA;
    B += (long)z * sB;
    if (bias) bias += (long)z * sBias;
    if (!catmode) {
        if (Cf) Cf += (long)z * sC;
        if (Ch) Ch += (long)z * sC;
    }

    const int tid = threadIdx.x;
    const int wid = tid >> 5, lane = tid & 31;
    const int warp_m = wid & 3, warp_n = wid >> 2;

    uint32_t sbase = (smem_u32(smem_raw) + 127) & ~127u;

    int Keff = K;
    if (causal == 2) { int kl = row0 + 128; Keff = kl < K ? kl : K; }
    const int nch = Keff >> 7;

    float acc[2][8][4];
    #pragma unroll
    for (int a = 0; a < 2; a++)
        #pragma unroll
        for (int b = 0; b < 8; b++)
            #pragma unroll
            for (int d = 0; d < 4; d++) acc[a][b][d] = 0.f;

    const __half* srcs[2] = {A, B};
    const int rbs[2] = {row0, col0};

    auto issue = [&](int c) {
        uint32_t dstb = sbase + (uint32_t)(c % 3) * STAGE_BYTES;
        int k0 = c << 7;
        #pragma unroll
        for (int t = 0; t < 2; t++) {
            #pragma unroll
            for (int i = 0; i < 8; i++) {
                int idx = i * 256 + tid;         // 0..2047
                int r = idx >> 4;                // 0..127
                int kb = idx & 15;               // 16B segment within 256B row
                uint32_t so = (uint32_t)((kb >> 3) * 16384 + r * 128 +
                                         (((kb & 7) * 16) ^ ((r & 7) << 4)));
                const void* src = (const char*)(srcs[t] + (long)(rbs[t] + r) * K + k0) + kb * 16;
                cp_async16(dstb + t * 32768 + so, src);
            }
        }
        cp_commit();
    };

    // ldmatrix lane addressing pieces
    const int li  = lane & 7;
    const int s8  = (lane >> 3) & 1;
    const int s16 = lane >> 4;

    int ar[2], arsw[2];
    #pragma unroll
    for (int mt = 0; mt < 2; mt++) {
        int r = warp_m * 32 + mt * 16 + s8 * 8 + li;
        ar[mt] = r * 128; arsw[mt] = (r & 7) << 4;
    }
    int br[4], brsw[4];
    #pragma unroll
    for (int nt2 = 0; nt2 < 4; nt2++) {
        int r = warp_n * 64 + nt2 * 16 + s8 * 8 + li;
        br[nt2] = r * 128; brsw[nt2] = (r & 7) << 4;
    }

    issue(0);
    if (nch > 1) issue(1);
    for (int c = 0; c < nch; c++) {
        if (c + 2 < nch) { issue(c + 2); cp_wait2(); }
        else if (c + 1 < nch) cp_wait1();
        else cp_wait0();
        __syncthreads();
        uint32_t bufb = sbase + (uint32_t)(c % 3) * STAGE_BYTES;

        #pragma unroll
        for (int ks = 0; ks < 8; ks++) {
            const int kbyte = ks * 32 + s16 * 16;          // 0..255
            const int sub   = (kbyte >> 7) * 16384;
            const int inner = kbyte & 127;
            uint32_t af[2][4];
            #pragma unroll
            for (int mt = 0; mt < 2; mt++) {
                uint32_t off = (uint32_t)(sub + ar[mt] + (inner ^ arsw[mt]));
                ldmatrix_x4(af[mt][0], af[mt][1], af[mt][2], af[mt][3], bufb + off);
            }
            uint32_t bf[8][2];
            #pragma unroll
            for (int nt2 = 0; nt2 < 4; nt2++) {
                uint32_t off = (uint32_t)(sub + br[nt2] + (inner ^ brsw[nt2]));
                uint32_t r0, r1, r2, r3;
                ldmatrix_x4(r0, r1, r2, r3, bufb + 32768 + off);
                bf[nt2 * 2][0] = r0; bf[nt2 * 2][1] = r2;
                bf[nt2 * 2 + 1][0] = r1; bf[nt2 * 2 + 1][1] = r3;
            }
            #pragma unroll
            for (int mt = 0; mt < 2; mt++)
                #pragma unroll
                for (int nt = 0; nt < 8; nt++)
                    MMA16816F16(acc[mt][nt], af[mt], bf[nt][0], bf[nt][1]);
        }
        __syncthreads();
    }

    // ---------------- epilogue straight from register fragments ----------------
    const int g = lane >> 2, t = lane & 3;
    const int hh = z >> 2, nb = z & 3;
    #pragma unroll
    for (int mt = 0; mt < 2; mt++)
        #pragma unroll
        for (int nt = 0; nt < 8; nt++)
            #pragma unroll
            for (int hr = 0; hr < 2; hr++) {
                int gr = row0 + warp_m * 32 + mt * 16 + g + hr * 8;
                int gc = col0 + warp_n * 64 + nt * 8 + t * 2;
                float v0 = acc[mt][nt][hr * 2];
                float v1 = acc[mt][nt][hr * 2 + 1];
                if (bias) {
                    if (catmode == 2) { float b = bias[gr]; v0 += b; v1 += b; }
                    else { v0 += bias[gc]; v1 += bias[gc + 1]; }
                }
                if (epi == 1) { v0 = v0 * normcdff(v0); v1 = v1 * normcdff(v1); }
                else if (epi == 2) {
                    long o = (long)gr * Ntot + gc;
                    v0 += res[o]; v1 += res[o + 1];
                }
                if (Cf) {
                    long o = (long)gr * Ntot + gc;
                    Cf[o] = v0; Cf[o + 1] = v1;
                }
                if (Ch) {
                    long o;
                    if (catmode == 1)
                        o = (long)(nb * S_LEN + gr) * HE + (long)hh * E_DIM + gc;
                    else if (catmode == 2)
                        o = (long)z * N_B * ((long)S_LEN * E_DIM)
                          + (long)(gc >> 10) * ((long)S_LEN * E_DIM)
                          + (long)gr * S_LEN + (gc & 1023);
                    else
                        o = (long)gr * Ntot + gc;
                    __half2 hp;
                    hp.x = __float2half_rn(v0);
                    hp.y = __float2half_rn(v1);
                    *(__half2*)(Ch + o) = hp;
                }
            }
}

// ---------------- launch ----------------
extern "C" void kernel_launch(void* const* d_in, const int* in_sizes, int n_in,
                              void* d_out, int out_size) {
    const float* inputs = (const float*)d_in[0];
    const float* g1  = (const float*)d_in[1];
    const float* b1  = (const float*)d_in[2];
    const float* Wq  = (const float*)d_in[3];
    const float* bq  = (const float*)d_in[4];
    const float* Wk  = (const float*)d_in[5];
    const float* bk  = (const float*)d_in[6];
    const float* Wv  = (const float*)d_in[7];
    const float* bv  = (const float*)d_in[8];
    const float* Wc  = (const float*)d_in[9];
    const float* bc  = (const float*)d_in[10];
    const float* g2  = (const float*)d_in[11];
    const float* b2  = (const float*)d_in[12];
    const float* Wfc = (const float*)d_in[13];
    const float* bfc = (const float*)d_in[14];
    const float* Wp  = (const float*)d_in[15];
    const float* bp  = (const float*)d_in[16];
    float* out = (float*)d_out;

    cudaFuncSetAttribute(gemm_mma, cudaFuncAttributeMaxDynamicSharedMemorySize, GEMM_SMEM);

    float *x, *sc, *mha, *y2;
    __half *xh, *wqth, *wkth, *wvth;
    __half *qh, *kh, *vth, *ah;
    __half *cath, *wcth, *y2h, *wfcth, *hbh, *wpth;
    cudaGetSymbolAddress((void**)&x, g_x);     cudaGetSymbolAddress((void**)&xh, g_xh);
    cudaGetSymbolAddress((void**)&wqth, g_wqth);
    cudaGetSymbolAddress((void**)&wkth, g_wkth);
    cudaGetSymbolAddress((void**)&wvth, g_wvth);
    cudaGetSymbolAddress((void**)&qh, g_qh);
    cudaGetSymbolAddress((void**)&kh, g_kh);
    cudaGetSymbolAddress((void**)&vth, g_vth);
    cudaGetSymbolAddress((void**)&sc, g_sc);
    cudaGetSymbolAddress((void**)&ah, g_ah);
    cudaGetSymbolAddress((void**)&cath, g_cath);
    cudaGetSymbolAddress((void**)&wcth, g_wcth);
    cudaGetSymbolAddress((void**)&mha, g_mha);
    cudaGetSymbolAddress((void**)&y2, g_y2);
    cudaGetSymbolAddress((void**)&y2h, g_y2h);
    cudaGetSymbolAddress((void**)&wfcth, g_wfcth);
    cudaGetSymbolAddress((void**)&hbh, g_hbh);
    cudaGetSymbolAddress((void**)&wpth, g_wpth);

    const long WEE = (long)E_DIM * E_DIM;
    const long QKV = (long)NS * E_DIM;
    const long ATT = (long)S_LEN * E_DIM;
    const long SCS = (long)S_LEN * S_LEN;
    dim3 tb(32, 8);

    // 0) LN1 -> x (fp32 + fp16)
    ln_kernel<<<NS, 256>>>(inputs, nullptr, g1, b1, x, xh);
    // 1-4) weight transposes needed before QKV
    transpose_conv<<<dim3(E_DIM / 32, E_DIM / 32, H_HEADS), tb>>>(Wq, wqth, E_DIM, E_DIM, WEE, WEE);
    transpose_conv<<<dim3(E_DIM / 32, E_DIM / 32, H_HEADS), tb>>>(Wk, wkth, E_DIM, E_DIM, WEE, WEE);
    transpose_conv<<<dim3(E_DIM / 32, E_DIM / 32, H_HEADS), tb>>>(Wv, wvth, E_DIM, E_DIM, WEE, WEE);
    transpose_conv<<<dim3(E_DIM / 32, HE / 32, 1), tb>>>(Wc, wcth, HE, E_DIM, 0, 0);

    dim3 gQKV(E_DIM / 128, NS / 128, H_HEADS);
    // 5) Q projection
    gemm_mma<<<gQKV, 256, GEMM_SMEM>>>(xh, wqth, bq, nullptr,
                                       nullptr, qh, E_DIM, E_DIM,
                                       0, WEE, E_DIM, QKV, 0, 0, 0);
    // 6) K projection
    gemm_mma<<<gQKV, 256, GEMM_SMEM>>>(xh, wkth, bk, nullptr,
                                       nullptr, kh, E_DIM, E_DIM,
                                       0, WEE, E_DIM, QKV, 0, 0, 0);
    // 7) V^T = Wv^T @ x^T, scattered into [h*4+n][e][t] panes with row-bias
    dim3 gVT(NS / 128, E_DIM / 128, H_HEADS);
    gemm_mma<<<gVT, 256, GEMM_SMEM>>>(wvth, xh, bv, nullptr,
                                      nullptr, vth, NS, E_DIM,
                                      WEE, 0, E_DIM, 0, 0, 0, 2);

    // remaining weight transposes
    transpose_conv<<<dim3(FF / 32, E_DIM / 32, 1), tb>>>(Wfc, wfcth, E_DIM, FF, 0, 0);
    transpose_conv<<<dim3(E_DIM / 32, FF / 32, 1), tb>>>(Wp, wpth, FF, E_DIM, 0, 0);

    // scores = Q @ K^T (causal block skip), fp32 out
    dim3 gSC(S_LEN / 128, S_LEN / 128, H_HEADS * N_B);
    gemm_mma<<<gSC, 256, GEMM_SMEM>>>(qh, kh, nullptr, nullptr,
                                      sc, nullptr, S_LEN, E_DIM,
                                      ATT, ATT, 0, SCS, 0, 1, 0);

    // softmax -> attn fp16 (truncated)
    softmax_causal<<<dim3(S_LEN, H_HEADS * N_B), 256>>>(sc, ah);

    // heads = attn @ V^T panes, epilogue writes straight into cat layout (fp16)
    dim3 gAV(E_DIM / 128, S_LEN / 128, H_HEADS * N_B);
    gemm_mma<<<gAV, 256, GEMM_SMEM>>>(ah, vth, nullptr, nullptr,
                                      nullptr, cath, E_DIM, S_LEN,
                                      SCS, ATT, 0, 0, 0, 2, 1);

    // c_proj
    dim3 gCP(E_DIM / 128, NS / 128, 1);
    gemm_mma<<<gCP, 256, GEMM_SMEM>>>(cath, wcth, bc, nullptr,
                                      mha, nullptr, E_DIM, HE,
                                      0, 0, 0, 0, 0, 0, 0);

    // y2 = LN2(mha + x)
    ln_kernel<<<NS, 256>>>(mha, x, g2, b2, y2, y2h);

    // fc + GELU -> hb fp16
    dim3 gFC(FF / 128, NS / 128, 1);
    gemm_mma<<<gFC, 256, GEMM_SMEM>>>(y2h, wfcth, bfc, nullptr,
                                      nullptr, hbh, FF, E_DIM,
                                      0, 0, 0, 0, 1, 0, 0);

    // proj + bias + residual(y2) -> out
    dim3 gPJ(E_DIM / 128, NS / 128, 1);
    gemm_mma<<<gPJ, 256, GEMM_SMEM>>>(hbh, wpth, bp, y2,
                                      out, nullptr, E_DIM, FF,
                                      0, 0, 0, 0, 2, 0, 0);
}

// round 14
// speedup vs baseline: 6.0511x; 1.0102x over previous
#include <cuda_runtime.h>
#include <cuda_fp16.h>
#include <math.h>
#include <stdint.h>
#include <string.h>

// Problem constants
#define N_B    4
#define S_LEN  1024
#define E_DIM  768
#define H_HEADS 12
constexpr int NS  = N_B * S_LEN;       // 4096
constexpr int HE  = H_HEADS * E_DIM;   // 9216
constexpr int FF  = 4 * E_DIM;         // 3072

// ---------------- scratch (__device__ globals; allocation-free) ----------------
__device__ float  g_x   [(size_t)NS * E_DIM];
__device__ __half g_xh  [(size_t)NS * E_DIM];

__device__ __half g_wqth[(size_t)H_HEADS * E_DIM * E_DIM];
__device__ __half g_wkth[(size_t)H_HEADS * E_DIM * E_DIM];
__device__ __half g_wvth[(size_t)H_HEADS * E_DIM * E_DIM];

__device__ __half g_qh  [(size_t)H_HEADS * NS * E_DIM];
__device__ __half g_kh  [(size_t)H_HEADS * NS * E_DIM];
__device__ __half g_vth [(size_t)H_HEADS * NS * E_DIM];   // [h*4+n][e][t] panes

__device__ __half g_sch [(size_t)H_HEADS * N_B * S_LEN * S_LEN];  // fp16 scores
__device__ __half g_ah  [(size_t)H_HEADS * N_B * S_LEN * S_LEN];

__device__ __half g_cath[(size_t)NS * HE];
__device__ __half g_wcth[(size_t)HE * E_DIM];
__device__ float  g_mha [(size_t)NS * E_DIM];

__device__ float  g_y2  [(size_t)NS * E_DIM];
__device__ __half g_y2h [(size_t)NS * E_DIM];
__device__ __half g_wfcth[(size_t)E_DIM * FF];
__device__ __half g_hbh [(size_t)NS * FF];
__device__ __half g_wpth[(size_t)FF * E_DIM];

// ---------------- helpers ----------------
__device__ __forceinline__ uint32_t smem_u32(const void* p) {
    uint32_t a;
    asm("{ .reg .u64 t; cvta.to.shared.u64 t, %1; cvt.u32.u64 %0, t; }" : "=r"(a) : "l"(p));
    return a;
}

__device__ __forceinline__ void cp_async16(uint32_t dst, const void* src) {
    asm volatile("cp.async.cg.shared.global [%0], [%1], 16;" :: "r"(dst), "l"(src) : "memory");
}
__device__ __forceinline__ void cp_commit() {
    asm volatile("cp.async.commit_group;" ::: "memory");
}
__device__ __forceinline__ void cp_wait2() { asm volatile("cp.async.wait_group 2;" ::: "memory"); }
__device__ __forceinline__ void cp_wait1() { asm volatile("cp.async.wait_group 1;" ::: "memory"); }
__device__ __forceinline__ void cp_wait0() { asm volatile("cp.async.wait_group 0;" ::: "memory"); }

__device__ __forceinline__ void ldmatrix_x4(uint32_t& r0, uint32_t& r1, uint32_t& r2, uint32_t& r3,
                                            uint32_t addr) {
    asm volatile("ldmatrix.sync.aligned.m8n8.x4.shared.b16 {%0,%1,%2,%3}, [%4];"
                 : "=r"(r0), "=r"(r1), "=r"(r2), "=r"(r3) : "r"(addr));
}

#define MMA16816F16(acc, af, b0, b1) \
    asm volatile( \
        "mma.sync.aligned.m16n8k16.row.col.f32.f16.f16.f32 " \
        "{%0,%1,%2,%3}, {%4,%5,%6,%7}, {%8,%9}, {%0,%1,%2,%3};" \
        : "+f"((acc)[0]), "+f"((acc)[1]), "+f"((acc)[2]), "+f"((acc)[3]) \
        : "r"((af)[0]), "r"((af)[1]), "r"((af)[2]), "r"((af)[3]), \
          "r"(b0), "r"(b1))

// ---------------- reductions ----------------
__device__ __forceinline__ float warpReduceSum(float v) {
    #pragma unroll
    for (int o = 16; o > 0; o >>= 1) v += __shfl_xor_sync(0xffffffffu, v, o);
    return v;
}
__device__ __forceinline__ float warpReduceMax(float v) {
    #pragma unroll
    for (int o = 16; o > 0; o >>= 1) v = fmaxf(v, __shfl_xor_sync(0xffffffffu, v, o));
    return v;
}

// ---------------- LayerNorm: fp32 out + fp16 out ----------------
__global__ void ln_kernel(const float* __restrict__ in, const float* __restrict__ resid,
                          const float* __restrict__ gamma, const float* __restrict__ beta,
                          float* __restrict__ out, __half* __restrict__ oh) {
    long base = (long)blockIdx.x * E_DIM;
    int tid = threadIdx.x;
    float vals[3];
    float s = 0.f, s2 = 0.f;
    #pragma unroll
    for (int i = 0; i < 3; i++) {
        int c = tid + i * 256;
        float v = in[base + c];
        if (resid) v += resid[base + c];
        vals[i] = v; s += v; s2 += v * v;
    }
    __shared__ float shs[8], shs2[8];
    s = warpReduceSum(s); s2 = warpReduceSum(s2);
    int lane = tid & 31, w = tid >> 5;
    if (lane == 0) { shs[w] = s; shs2[w] = s2; }
    __syncthreads();
    if (tid < 32) {
        float a = (lane < 8) ? shs[lane]  : 0.f;
        float b = (lane < 8) ? shs2[lane] : 0.f;
        a = warpReduceSum(a); b = warpReduceSum(b);
        if (lane == 0) { shs[0] = a; shs2[0] = b; }
    }
    __syncthreads();
    float mean = shs[0] * (1.f / E_DIM);
    float var  = shs2[0] * (1.f / E_DIM) - mean * mean;
    float rstd = rsqrtf(var + 1e-5f);
    #pragma unroll
    for (int i = 0; i < 3; i++) {
        int c = tid + i * 256;
        float v = (vals[i] - mean) * rstd * gamma[c] + beta[c];
        out[base + c] = v;
        oh[base + c] = __float2half_rn(v);
    }
}

// ---------------- causal softmax (fp16 scores in, fp16 probs out, truncated) ----------------
__global__ void softmax_causal(const __half* __restrict__ scores, __half* __restrict__ ah) {
    int srow = blockIdx.x;
    long off = ((long)blockIdx.y * S_LEN + srow) * S_LEN;
    const __half* row = scores + off;
    int tid = threadIdx.x;
    const float scale = 0.03608439182435161f;  // 1/sqrt(768)
    const int L = ((srow >> 7) + 1) << 7;      // AV never reads cols >= L
    float v[4];
    float mx = -1e30f;
    #pragma unroll
    for (int i = 0; i < 4; i++) {
        int t = tid + i * 256;
        float val = (t <= srow) ? __half2float(row[t]) * scale : -1e30f;
        v[i] = val; mx = fmaxf(mx, val);
    }
    __shared__ float sh[8];
    int lane = tid & 31, w = tid >> 5;
    mx = warpReduceMax(mx);
    if (lane == 0) sh[w] = mx;
    __syncthreads();
    if (tid < 32) {
        float m2 = (lane < 8) ? sh[lane] : -1e30f;
        m2 = warpReduceMax(m2);
        if (lane == 0) sh[0] = m2;
    }
    __syncthreads();
    mx = sh[0];
    __syncthreads();
    float sum = 0.f;
    #pragma unroll
    for (int i = 0; i < 4; i++) {
        int t = tid + i * 256;
        float e = (t <= srow) ? __expf(v[i] - mx) : 0.f;
        v[i] = e; sum += e;
    }
    sum = warpReduceSum(sum);
    if (lane == 0) sh[w] = sum;
    __syncthreads();
    if (tid < 32) {
        float s2 = (lane < 8) ? sh[lane] : 0.f;
        s2 = warpReduceSum(s2);
        if (lane == 0) sh[0] = s2;
    }
    __syncthreads();
    float inv = 1.f / sh[0];
    #pragma unroll
    for (int i = 0; i < 4; i++) {
        int t = tid + i * 256;
        if (t < L) ah[off + t] = __float2half_rn(v[i] * inv);
    }
}

// ---------------- tiled transpose + fp16 convert: src[R,C] f32 -> dst[C,R] ----------------
__global__ void transpose_conv(const float* __restrict__ src,
                               __half* __restrict__ dh,
                               int R, int C, long sS, long sD) {
    __shared__ float t[32][33];
    src += (long)blockIdx.z * sS;
    dh  += (long)blockIdx.z * sD;
    int c0 = blockIdx.x * 32, r0 = blockIdx.y * 32;
    #pragma unroll
    for (int i = 0; i < 32; i += 8)
        t[threadIdx.y + i][threadIdx.x] = src[(long)(r0 + threadIdx.y + i) * C + c0 + threadIdx.x];
    __syncthreads();
    #pragma unroll
    for (int i = 0; i < 32; i += 8) {
        float v = t[threadIdx.x][threadIdx.y + i];
        long o = (long)(c0 + threadIdx.y + i) * R + r0 + threadIdx.x;
        dh[o] = __float2half_rn(v);
    }
}

// ---------------- mma.sync fp16 single-pass GEMM, BK=128, frag double-buffer ----------------
// C[M,N] = A[M,K](fp16) @ B[N,K]^T(fp16), fp32 accum in regs.
// Tile 128x128, BK=128 (two 64-K sub-tiles, each 128B SW128 rows).
// 8 warps (4m x 2n), warp tile 32x64. 3-stage cp.async pipeline.
// Register-double-buffered fragments: k-step i+1's ldmatrix issue before
// k-step i's MMAs, hiding shared-load latency behind tensor work.
// epi: 0 bias, 1 bias+GELU(exact), 2 bias+residual.
// causal: 0 none, 1 skip upper blocks, 2 K limited to row0+128.
// catmode: 0 normal; 1 cat-heads scatter; 2 V^T pane scatter (row-bias).
constexpr int STAGE_BYTES = 65536;   // 2 tiles x 32KB
constexpr int GEMM_SMEM = 3 * STAGE_BYTES + 128;

__global__ void __launch_bounds__(256, 1)
gemm_mma(const __half* __restrict__ A, const __half* __restrict__ B,
         const float* __restrict__ bias, const float* __restrict__ res,
         float* __restrict__ Cf, __half* __restrict__ Ch,
         int Ntot, int K,
         long sA, long sB, long sBias, long sC,
         int epi, int causal, int catmode) {
    extern __shared__ char smem_raw[];
    const int row0 = blockIdx.y * 128;
    const int col0 = blockIdx.x * 128;
    if (causal == 1 && col0 > row0 + 127) return;

    const int z = blockIdx.z;
    A += (long)z * sA;
    B += (long)z * sB;
    if (bias) bias += (long)z * sBias;
    if (!catmode) {
        if (Cf) Cf += (long)z * sC;
        if (Ch) Ch += (long)z * sC;
    }

    const int tid = threadIdx.x;
    const int wid = tid >> 5, lane = tid & 31;
    const int warp_m = wid & 3, warp_n = wid >> 2;

    uint32_t sbase = (smem_u32(smem_raw) + 127) & ~127u;

    int Keff = K;
    if (causal == 2) { int kl = row0 + 128; Keff = kl < K ? kl : K; }
    const int nch = Keff >> 7;

    float acc[2][8][4];
    #pragma unroll
    for (int a = 0; a < 2; a++)
        #pragma unroll
        for (int b = 0; b < 8; b++)
            #pragma unroll
            for (int d = 0; d < 4; d++) acc[a][b][d] = 0.f;

    const __half* srcs[2] = {A, B};
    const int rbs[2] = {row0, col0};

    auto issue = [&](int c) {
        uint32_t dstb = sbase + (uint32_t)(c % 3) * STAGE_BYTES;
        int k0 = c << 7;
        #pragma unroll
        for (int t = 0; t < 2; t++) {
            #pragma unroll
            for (int i = 0; i < 8; i++) {
                int idx = i * 256 + tid;         // 0..2047
                int r = idx >> 4;                // 0..127
                int kb = idx & 15;               // 16B segment within 256B row
                uint32_t so = (uint32_t)((kb >> 3) * 16384 + r * 128 +
                                         (((kb & 7) * 16) ^ ((r & 7) << 4)));
                const void* src = (const char*)(srcs[t] + (long)(rbs[t] + r) * K + k0) + kb * 16;
                cp_async16(dstb + t * 32768 + so, src);
            }
        }
        cp_commit();
    };

    // ldmatrix lane addressing pieces
    const int li  = lane & 7;
    const int s8  = (lane >> 3) & 1;
    const int s16 = lane >> 4;

    int ar[2], arsw[2];
    #pragma unroll
    for (int mt = 0; mt < 2; mt++) {
        int r = warp_m * 32 + mt * 16 + s8 * 8 + li;
        ar[mt] = r * 128; arsw[mt] = (r & 7) << 4;
    }
    int br[4], brsw[4];
    #pragma unroll
    for (int nt2 = 0; nt2 < 4; nt2++) {
        int r = warp_n * 64 + nt2 * 16 + s8 * 8 + li;
        br[nt2] = r * 128; brsw[nt2] = (r & 7) << 4;
    }

    // fragment double buffers
    uint32_t af[2][2][4];
    uint32_t bf[2][8][2];

    issue(0);
    if (nch > 1) issue(1);
    for (int c = 0; c < nch; c++) {
        if (c + 2 < nch) { issue(c + 2); cp_wait2(); }
        else if (c + 1 < nch) cp_wait1();
        else cp_wait0();
        __syncthreads();
        uint32_t bufb = sbase + (uint32_t)(c % 3) * STAGE_BYTES;

        // load k-step 0 fragments into buffer 0
        {
            const int kbyte = s16 * 16;
            const int sub   = 0;
            const int inner = kbyte & 127;
            #pragma unroll
            for (int mt = 0; mt < 2; mt++) {
                uint32_t off = (uint32_t)(sub + ar[mt] + (inner ^ arsw[mt]));
                ldmatrix_x4(af[0][mt][0], af[0][mt][1], af[0][mt][2], af[0][mt][3], bufb + off);
            }
            #pragma unroll
            for (int nt2 = 0; nt2 < 4; nt2++) {
                uint32_t off = (uint32_t)(sub + br[nt2] + (inner ^ brsw[nt2]));
                uint32_t r0, r1, r2, r3;
                ldmatrix_x4(r0, r1, r2, r3, bufb + 32768 + off);
                bf[0][nt2 * 2][0] = r0; bf[0][nt2 * 2][1] = r2;
                bf[0][nt2 * 2 + 1][0] = r1; bf[0][nt2 * 2 + 1][1] = r3;
            }
        }

        #pragma unroll
        for (int ks = 0; ks < 8; ks++) {
            const int cur = ks & 1, nxt = cur ^ 1;
            if (ks < 7) {
                const int kbyte = (ks + 1) * 32 + s16 * 16;
                const int sub   = (kbyte >> 7) * 16384;
                const int inner = kbyte & 127;
                #pragma unroll
                for (int mt = 0; mt < 2; mt++) {
                    uint32_t off = (uint32_t)(sub + ar[mt] + (inner ^ arsw[mt]));
                    ldmatrix_x4(af[nxt][mt][0], af[nxt][mt][1], af[nxt][mt][2], af[nxt][mt][3],
                                bufb + off);
                }
                #pragma unroll
                for (int nt2 = 0; nt2 < 4; nt2++) {
                    uint32_t off = (uint32_t)(sub + br[nt2] + (inner ^ brsw[nt2]));
                    uint32_t r0, r1, r2, r3;
                    ldmatrix_x4(r0, r1, r2, r3, bufb + 32768 + off);
                    bf[nxt][nt2 * 2][0] = r0; bf[nxt][nt2 * 2][1] = r2;
                    bf[nxt][nt2 * 2 + 1][0] = r1; bf[nxt][nt2 * 2 + 1][1] = r3;
                }
            }
            #pragma unroll
            for (int mt = 0; mt < 2; mt++)
                #pragma unroll
                for (int nt = 0; nt < 8; nt++)
                    MMA16816F16(acc[mt][nt], af[cur][mt], bf[cur][nt][0], bf[cur][nt][1]);
        }
        __syncthreads();
    }

    // ---------------- epilogue straight from register fragments ----------------
    const int g = lane >> 2, t = lane & 3;
    const int hh = z >> 2, nb = z & 3;
    #pragma unroll
    for (int mt = 0; mt < 2; mt++)
        #pragma unroll
        for (int nt = 0; nt < 8; nt++)
            #pragma unroll
            for (int hr = 0; hr < 2; hr++) {
                int gr = row0 + warp_m * 32 + mt * 16 + g + hr * 8;
                int gc = col0 + warp_n * 64 + nt * 8 + t * 2;
                float v0 = acc[mt][nt][hr * 2];
                float v1 = acc[mt][nt][hr * 2 + 1];
                if (bias) {
                    if (catmode == 2) { float b = bias[gr]; v0 += b; v1 += b; }
                    else { v0 += bias[gc]; v1 += bias[gc + 1]; }
                }
                if (epi == 1) { v0 = v0 * normcdff(v0); v1 = v1 * normcdff(v1); }
                else if (epi == 2) {
                    long o = (long)gr * Ntot + gc;
                    v0 += res[o]; v1 += res[o + 1];
                }
                if (Cf) {
                    long o = (long)gr * Ntot + gc;
                    Cf[o] = v0; Cf[o + 1] = v1;
                }
                if (Ch) {
                    long o;
                    if (catmode == 1)
                        o = (long)(nb * S_LEN + gr) * HE + (long)hh * E_DIM + gc;
                    else if (catmode == 2)
                        o = (long)z * N_B * ((long)S_LEN * E_DIM)
                          + (long)(gc >> 10) * ((long)S_LEN * E_DIM)
                          + (long)gr * S_LEN + (gc & 1023);
                    else
                        o = (long)gr * Ntot + gc;
                    __half2 hp;
                    hp.x = __float2half_rn(v0);
                    hp.y = __float2half_rn(v1);
                    *(__half2*)(Ch + o) = hp;
                }
            }
}

// ---------------- launch ----------------
extern "C" void kernel_launch(void* const* d_in, const int* in_sizes, int n_in,
                              void* d_out, int out_size) {
    const float* inputs = (const float*)d_in[0];
    const float* g1  = (const float*)d_in[1];
    const float* b1  = (const float*)d_in[2];
    const float* Wq  = (const float*)d_in[3];
    const float* bq  = (const float*)d_in[4];
    const float* Wk  = (const float*)d_in[5];
    const float* bk  = (const float*)d_in[6];
    const float* Wv  = (const float*)d_in[7];
    const float* bv  = (const float*)d_in[8];
    const float* Wc  = (const float*)d_in[9];
    const float* bc  = (const float*)d_in[10];
    const float* g2  = (const float*)d_in[11];
    const float* b2  = (const float*)d_in[12];
    const float* Wfc = (const float*)d_in[13];
    const float* bfc = (const float*)d_in[14];
    const float* Wp  = (const float*)d_in[15];
    const float* bp  = (const float*)d_in[16];
    float* out = (float*)d_out;

    cudaFuncSetAttribute(gemm_mma, cudaFuncAttributeMaxDynamicSharedMemorySize, GEMM_SMEM);

    float *x, *mha, *y2;
    __half *xh, *wqth, *wkth, *wvth;
    __half *qh, *kh, *vth, *sch, *ah;
    __half *cath, *wcth, *y2h, *wfcth, *hbh, *wpth;
    cudaGetSymbolAddress((void**)&x, g_x);     cudaGetSymbolAddress((void**)&xh, g_xh);
    cudaGetSymbolAddress((void**)&wqth, g_wqth);
    cudaGetSymbolAddress((void**)&wkth, g_wkth);
    cudaGetSymbolAddress((void**)&wvth, g_wvth);
    cudaGetSymbolAddress((void**)&qh, g_qh);
    cudaGetSymbolAddress((void**)&kh, g_kh);
    cudaGetSymbolAddress((void**)&vth, g_vth);
    cudaGetSymbolAddress((void**)&sch, g_sch);
    cudaGetSymbolAddress((void**)&ah, g_ah);
    cudaGetSymbolAddress((void**)&cath, g_cath);
    cudaGetSymbolAddress((void**)&wcth, g_wcth);
    cudaGetSymbolAddress((void**)&mha, g_mha);
    cudaGetSymbolAddress((void**)&y2, g_y2);
    cudaGetSymbolAddress((void**)&y2h, g_y2h);
    cudaGetSymbolAddress((void**)&wfcth, g_wfcth);
    cudaGetSymbolAddress((void**)&hbh, g_hbh);
    cudaGetSymbolAddress((void**)&wpth, g_wpth);

    const long WEE = (long)E_DIM * E_DIM;
    const long QKV = (long)NS * E_DIM;
    const long ATT = (long)S_LEN * E_DIM;
    const long SCS = (long)S_LEN * S_LEN;
    dim3 tb(32, 8);

    // 0) LN1 -> x (fp32 + fp16)
    ln_kernel<<<NS, 256>>>(inputs, nullptr, g1, b1, x, xh);
    // 1-4) weight transposes needed before QKV
    transpose_conv<<<dim3(E_DIM / 32, E_DIM / 32, H_HEADS), tb>>>(Wq, wqth, E_DIM, E_DIM, WEE, WEE);
    transpose_conv<<<dim3(E_DIM / 32, E_DIM / 32, H_HEADS), tb>>>(Wk, wkth, E_DIM, E_DIM, WEE, WEE);
    transpose_conv<<<dim3(E_DIM / 32, E_DIM / 32, H_HEADS), tb>>>(Wv, wvth, E_DIM, E_DIM, WEE, WEE);
    transpose_conv<<<dim3(E_DIM / 32, HE / 32, 1), tb>>>(Wc, wcth, HE, E_DIM, 0, 0);

    dim3 gQKV(E_DIM / 128, NS / 128, H_HEADS);
    // 5) Q projection
    gemm_mma<<<gQKV, 256, GEMM_SMEM>>>(xh, wqth, bq, nullptr,
                                       nullptr, qh, E_DIM, E_DIM,
                                       0, WEE, E_DIM, QKV, 0, 0, 0);
    // 6) K projection
    gemm_mma<<<gQKV, 256, GEMM_SMEM>>>(xh, wkth, bk, nullptr,
                                       nullptr, kh, E_DIM, E_DIM,
                                       0, WEE, E_DIM, QKV, 0, 0, 0);
    // 7) V^T = Wv^T @ x^T, scattered into [h*4+n][e][t] panes with row-bias
    dim3 gVT(NS / 128, E_DIM / 128, H_HEADS);
    gemm_mma<<<gVT, 256, GEMM_SMEM>>>(wvth, xh, bv, nullptr,
                                      nullptr, vth, NS, E_DIM,
                                      WEE, 0, E_DIM, 0, 0, 0, 2);

    // remaining weight transposes
    transpose_conv<<<dim3(FF / 32, E_DIM / 32, 1), tb>>>(Wfc, wfcth, E_DIM, FF, 0, 0);
    transpose_conv<<<dim3(E_DIM / 32, FF / 32, 1), tb>>>(Wp, wpth, FF, E_DIM, 0, 0);

    // scores = Q @ K^T (causal block skip), fp16 out
    dim3 gSC(S_LEN / 128, S_LEN / 128, H_HEADS * N_B);
    gemm_mma<<<gSC, 256, GEMM_SMEM>>>(qh, kh, nullptr, nullptr,
                                      nullptr, sch, S_LEN, E_DIM,
                                      ATT, ATT, 0, SCS, 0, 1, 0);

    // softmax -> attn fp16 (truncated)
    softmax_causal<<<dim3(S_LEN, H_HEADS * N_B), 256>>>(sch, ah);

    // heads = attn @ V^T panes, epilogue writes straight into cat layout (fp16)
    dim3 gAV(E_DIM / 128, S_LEN / 128, H_HEADS * N_B);
    gemm_mma<<<gAV, 256, GEMM_SMEM>>>(ah, vth, nullptr, nullptr,
                                      nullptr, cath, E_DIM, S_LEN,
                                      SCS, ATT, 0, 0, 0, 2, 1);

    // c_proj
    dim3 gCP(E_DIM / 128, NS / 128, 1);
    gemm_mma<<<gCP, 256, GEMM_SMEM>>>(cath, wcth, bc, nullptr,
                                      mha, nullptr, E_DIM, HE,
                                      0, 0, 0, 0, 0, 0, 0);

    // y2 = LN2(mha + x)
    ln_kernel<<<NS, 256>>>(mha, x, g2, b2, y2, y2h);

    // fc + GELU -> hb fp16
    dim3 gFC(FF / 128, NS / 128, 1);
    gemm_mma<<<gFC, 256, GEMM_SMEM>>>(y2h, wfcth, bfc, nullptr,
                                      nullptr, hbh, FF, E_DIM,
                                      0, 0, 0, 0, 1, 0, 0);

    // proj + bias + residual(y2) -> out
    dim3 gPJ(E_DIM / 128, NS / 128, 1);
    gemm_mma<<<gPJ, 256, GEMM_SMEM>>>(hbh, wpth, bp, y2,
                                      out, nullptr, E_DIM, FF,
                                      0, 0, 0, 0, 2, 0, 0);
}

// round 15
// speedup vs baseline: 6.1382x; 1.0144x over previous
#include <cuda_runtime.h>
#include <cuda_fp16.h>
#include <math.h>
#include <stdint.h>
#include <string.h>

// Problem constants
#define N_B    4
#define S_LEN  1024
#define E_DIM  768
#define H_HEADS 12
constexpr int NS  = N_B * S_LEN;       // 4096
constexpr int HE  = H_HEADS * E_DIM;   // 9216
constexpr int FF  = 4 * E_DIM;         // 3072

// ---------------- scratch (__device__ globals; allocation-free) ----------------
__device__ float  g_x   [(size_t)NS * E_DIM];
__device__ __half g_xh  [(size_t)NS * E_DIM];

__device__ __half g_wqth[(size_t)H_HEADS * E_DIM * E_DIM];
__device__ __half g_wkth[(size_t)H_HEADS * E_DIM * E_DIM];
__device__ __half g_wvth[(size_t)H_HEADS * E_DIM * E_DIM];

__device__ __half g_qh  [(size_t)H_HEADS * NS * E_DIM];
__device__ __half g_kh  [(size_t)H_HEADS * NS * E_DIM];
__device__ __half g_vth [(size_t)H_HEADS * NS * E_DIM];   // [h*4+n][e][t] panes

__device__ __half g_sch [(size_t)H_HEADS * N_B * S_LEN * S_LEN];  // fp16 scores
__device__ __half g_ah  [(size_t)H_HEADS * N_B * S_LEN * S_LEN];

__device__ __half g_cath[(size_t)NS * HE];
__device__ __half g_wcth[(size_t)HE * E_DIM];
__device__ float  g_mha [(size_t)NS * E_DIM];

__device__ float  g_y2  [(size_t)NS * E_DIM];
__device__ __half g_y2h [(size_t)NS * E_DIM];
__device__ __half g_wfcth[(size_t)E_DIM * FF];
__device__ __half g_hbh [(size_t)NS * FF];
__device__ __half g_wpth[(size_t)FF * E_DIM];

// ---------------- helpers ----------------
__device__ __forceinline__ uint32_t smem_u32(const void* p) {
    uint32_t a;
    asm("{ .reg .u64 t; cvta.to.shared.u64 t, %1; cvt.u32.u64 %0, t; }" : "=r"(a) : "l"(p));
    return a;
}

__device__ __forceinline__ void cp_async16(uint32_t dst, const void* src) {
    asm volatile("cp.async.cg.shared.global [%0], [%1], 16;" :: "r"(dst), "l"(src) : "memory");
}
__device__ __forceinline__ void cp_commit() {
    asm volatile("cp.async.commit_group;" ::: "memory");
}
__device__ __forceinline__ void cp_wait2() { asm volatile("cp.async.wait_group 2;" ::: "memory"); }
__device__ __forceinline__ void cp_wait1() { asm volatile("cp.async.wait_group 1;" ::: "memory"); }
__device__ __forceinline__ void cp_wait0() { asm volatile("cp.async.wait_group 0;" ::: "memory"); }

__device__ __forceinline__ void ldmatrix_x4(uint32_t& r0, uint32_t& r1, uint32_t& r2, uint32_t& r3,
                                            uint32_t addr) {
    asm volatile("ldmatrix.sync.aligned.m8n8.x4.shared.b16 {%0,%1,%2,%3}, [%4];"
                 : "=r"(r0), "=r"(r1), "=r"(r2), "=r"(r3) : "r"(addr));
}

#define MMA16816F16(acc, af, b0, b1) \
    asm volatile( \
        "mma.sync.aligned.m16n8k16.row.col.f32.f16.f16.f32 " \
        "{%0,%1,%2,%3}, {%4,%5,%6,%7}, {%8,%9}, {%0,%1,%2,%3};" \
        : "+f"((acc)[0]), "+f"((acc)[1]), "+f"((acc)[2]), "+f"((acc)[3]) \
        : "r"((af)[0]), "r"((af)[1]), "r"((af)[2]), "r"((af)[3]), \
          "r"(b0), "r"(b1))

// ---------------- reductions ----------------
__device__ __forceinline__ float warpReduceSum(float v) {
    #pragma unroll
    for (int o = 16; o > 0; o >>= 1) v += __shfl_xor_sync(0xffffffffu, v, o);
    return v;
}
__device__ __forceinline__ float warpReduceMax(float v) {
    #pragma unroll
    for (int o = 16; o > 0; o >>= 1) v = fmaxf(v, __shfl_xor_sync(0xffffffffu, v, o));
    return v;
}

// ---------------- LayerNorm: fp32 out + fp16 out ----------------
__global__ void ln_kernel(const float* __restrict__ in, const float* __restrict__ resid,
                          const float* __restrict__ gamma, const float* __restrict__ beta,
                          float* __restrict__ out, __half* __restrict__ oh) {
    long base = (long)blockIdx.x * E_DIM;
    int tid = threadIdx.x;
    float vals[3];
    float s = 0.f, s2 = 0.f;
    #pragma unroll
    for (int i = 0; i < 3; i++) {
        int c = tid + i * 256;
        float v = in[base + c];
        if (resid) v += resid[base + c];
        vals[i] = v; s += v; s2 += v * v;
    }
    __shared__ float shs[8], shs2[8];
    s = warpReduceSum(s); s2 = warpReduceSum(s2);
    int lane = tid & 31, w = tid >> 5;
    if (lane == 0) { shs[w] = s; shs2[w] = s2; }
    __syncthreads();
    if (tid < 32) {
        float a = (lane < 8) ? shs[lane]  : 0.f;
        float b = (lane < 8) ? shs2[lane] : 0.f;
        a = warpReduceSum(a); b = warpReduceSum(b);
        if (lane == 0) { shs[0] = a; shs2[0] = b; }
    }
    __syncthreads();
    float mean = shs[0] * (1.f / E_DIM);
    float var  = shs2[0] * (1.f / E_DIM) - mean * mean;
    float rstd = rsqrtf(var + 1e-5f);
    #pragma unroll
    for (int i = 0; i < 3; i++) {
        int c = tid + i * 256;
        float v = (vals[i] - mean) * rstd * gamma[c] + beta[c];
        out[base + c] = v;
        oh[base + c] = __float2half_rn(v);
    }
}

// ---------------- causal softmax (fp16 scores in, fp16 probs out, truncated) ----------------
__global__ void softmax_causal(const __half* __restrict__ scores, __half* __restrict__ ah) {
    int srow = blockIdx.x;
    long off = ((long)blockIdx.y * S_LEN + srow) * S_LEN;
    const __half* row = scores + off;
    int tid = threadIdx.x;
    const float scale = 0.03608439182435161f;  // 1/sqrt(768)
    const int L = ((srow >> 7) + 1) << 7;      // AV never reads cols >= L
    float v[4];
    float mx = -1e30f;
    #pragma unroll
    for (int i = 0; i < 4; i++) {
        int t = tid + i * 256;
        float val = (t <= srow) ? __half2float(row[t]) * scale : -1e30f;
        v[i] = val; mx = fmaxf(mx, val);
    }
    __shared__ float sh[8];
    int lane = tid & 31, w = tid >> 5;
    mx = warpReduceMax(mx);
    if (lane == 0) sh[w] = mx;
    __syncthreads();
    if (tid < 32) {
        float m2 = (lane < 8) ? sh[lane] : -1e30f;
        m2 = warpReduceMax(m2);
        if (lane == 0) sh[0] = m2;
    }
    __syncthreads();
    mx = sh[0];
    __syncthreads();
    float sum = 0.f;
    #pragma unroll
    for (int i = 0; i < 4; i++) {
        int t = tid + i * 256;
        float e = (t <= srow) ? __expf(v[i] - mx) : 0.f;
        v[i] = e; sum += e;
    }
    sum = warpReduceSum(sum);
    if (lane == 0) sh[w] = sum;
    __syncthreads();
    if (tid < 32) {
        float s2 = (lane < 8) ? sh[lane] : 0.f;
        s2 = warpReduceSum(s2);
        if (lane == 0) sh[0] = s2;
    }
    __syncthreads();
    float inv = 1.f / sh[0];
    #pragma unroll
    for (int i = 0; i < 4; i++) {
        int t = tid + i * 256;
        if (t < L) ah[off + t] = __float2half_rn(v[i] * inv);
    }
}

// ---------------- tiled transpose + fp16 convert: src[R,C] f32 -> dst[C,R] ----------------
__global__ void transpose_conv(const float* __restrict__ src,
                               __half* __restrict__ dh,
                               int R, int C, long sS, long sD) {
    __shared__ float t[32][33];
    src += (long)blockIdx.z * sS;
    dh  += (long)blockIdx.z * sD;
    int c0 = blockIdx.x * 32, r0 = blockIdx.y * 32;
    #pragma unroll
    for (int i = 0; i < 32; i += 8)
        t[threadIdx.y + i][threadIdx.x] = src[(long)(r0 + threadIdx.y + i) * C + c0 + threadIdx.x];
    __syncthreads();
    #pragma unroll
    for (int i = 0; i < 32; i += 8) {
        float v = t[threadIdx.x][threadIdx.y + i];
        long o = (long)(c0 + threadIdx.y + i) * R + r0 + threadIdx.x;
        dh[o] = __float2half_rn(v);
    }
}

// ---------------- mma.sync fp16 GEMM, BK=128, templated BN (128 or 64) ----------------
// C[M,N] = A[M,K](fp16) @ B[N,K]^T(fp16), fp32 accum in regs.
// Tile 128xBN. 8 warps (4m x 2n), warp tile 32x(BN/2). 3-stage cp.async pipeline,
// register-double-buffered fragments.
// epi: 0 bias, 1 bias+GELU(exact), 2 bias+residual.
// causal: 0 none, 1 skip upper blocks, 2 K limited to row0+128.
// catmode: 0 normal; 1 cat-heads scatter; 2 V^T pane scatter (row-bias).
template<int BN>
__global__ void __launch_bounds__(256, 1)
gemm_mma(const __half* __restrict__ A, const __half* __restrict__ B,
         const float* __restrict__ bias, const float* __restrict__ res,
         float* __restrict__ Cf, __half* __restrict__ Ch,
         int Ntot, int K,
         long sA, long sB, long sBias, long sC,
         int epi, int causal, int catmode) {
    constexpr int NT = BN / 16;                 // n8-tiles per warp (warp_n covers BN/2)
    constexpr int BSTAGE = 32768 + BN * 256;    // A tile (32KB) + B tile
    constexpr int BSUB = BN * 128;              // per-64k-subtile B bytes

    extern __shared__ char smem_raw[];
    const int row0 = blockIdx.y * 128;
    const int col0 = blockIdx.x * BN;
    if (causal == 1 && col0 > row0 + 127) return;

    const int z = blockIdx.z;
    A += (long)z * sA;
    B += (long)z * sB;
    if (bias) bias += (long)z * sBias;
    if (!catmode) {
        if (Cf) Cf += (long)z * sC;
        if (Ch) Ch += (long)z * sC;
    }

    const int tid = threadIdx.x;
    const int wid = tid >> 5, lane = tid & 31;
    const int warp_m = wid & 3, warp_n = wid >> 2;

    uint32_t sbase = (smem_u32(smem_raw) + 127) & ~127u;

    int Keff = K;
    if (causal == 2) { int kl = row0 + 128; Keff = kl < K ? kl : K; }
    const int nch = Keff >> 7;

    float acc[2][NT][4];
    #pragma unroll
    for (int a = 0; a < 2; a++)
        #pragma unroll
        for (int b = 0; b < NT; b++)
            #pragma unroll
            for (int d = 0; d < 4; d++) acc[a][b][d] = 0.f;

    auto issue = [&](int c) {
        uint32_t dstb = sbase + (uint32_t)(c % 3) * BSTAGE;
        int k0 = c << 7;
        // A tile: 128 rows x 16 segs
        #pragma unroll
        for (int i = 0; i < 8; i++) {
            int idx = i * 256 + tid;
            int r = idx >> 4, kb = idx & 15;
            uint32_t so = (uint32_t)((kb >> 3) * 16384 + r * 128 +
                                     (((kb & 7) * 16) ^ ((r & 7) << 4)));
            const void* src = (const char*)(A + (long)(row0 + r) * K + k0) + kb * 16;
            cp_async16(dstb + so, src);
        }
        // B tile: BN rows x 16 segs
        #pragma unroll
        for (int i = 0; i < BN / 16; i++) {
            int idx = i * 256 + tid;
            int r = idx >> 4, kb = idx & 15;
            uint32_t so = (uint32_t)((kb >> 3) * BSUB + r * 128 +
                                     (((kb & 7) * 16) ^ ((r & 7) << 4)));
            const void* src = (const char*)(B + (long)(col0 + r) * K + k0) + kb * 16;
            cp_async16(dstb + 32768 + so, src);
        }
        cp_commit();
    };

    // ldmatrix lane addressing pieces
    const int li  = lane & 7;
    const int s8  = (lane >> 3) & 1;
    const int s16 = lane >> 4;

    int ar[2], arsw[2];
    #pragma unroll
    for (int mt = 0; mt < 2; mt++) {
        int r = warp_m * 32 + mt * 16 + s8 * 8 + li;
        ar[mt] = r * 128; arsw[mt] = (r & 7) << 4;
    }
    int br[NT / 2], brsw[NT / 2];
    #pragma unroll
    for (int nt2 = 0; nt2 < NT / 2; nt2++) {
        int r = warp_n * (BN / 2) + nt2 * 16 + s8 * 8 + li;
        br[nt2] = r * 128; brsw[nt2] = (r & 7) << 4;
    }

    // fragment double buffers
    uint32_t af[2][2][4];
    uint32_t bf[2][NT][2];

    issue(0);
    if (nch > 1) issue(1);
    for (int c = 0; c < nch; c++) {
        if (c + 2 < nch) { issue(c + 2); cp_wait2(); }
        else if (c + 1 < nch) cp_wait1();
        else cp_wait0();
        __syncthreads();
        uint32_t bufb = sbase + (uint32_t)(c % 3) * BSTAGE;

        // load k-step 0 fragments into buffer 0
        {
            const int kbyte = s16 * 16;
            const int inner = kbyte & 127;
            #pragma unroll
            for (int mt = 0; mt < 2; mt++) {
                uint32_t off = (uint32_t)(ar[mt] + (inner ^ arsw[mt]));
                ldmatrix_x4(af[0][mt][0], af[0][mt][1], af[0][mt][2], af[0][mt][3], bufb + off);
            }
            #pragma unroll
            for (int nt2 = 0; nt2 < NT / 2; nt2++) {
                uint32_t off = (uint32_t)(br[nt2] + (inner ^ brsw[nt2]));
                uint32_t r0, r1, r2, r3;
                ldmatrix_x4(r0, r1, r2, r3, bufb + 32768 + off);
                bf[0][nt2 * 2][0] = r0; bf[0][nt2 * 2][1] = r2;
                bf[0][nt2 * 2 + 1][0] = r1; bf[0][nt2 * 2 + 1][1] = r3;
            }
        }

        #pragma unroll
        for (int ks = 0; ks < 8; ks++) {
            const int cur = ks & 1, nxt = cur ^ 1;
            if (ks < 7) {
                const int kbyte = (ks + 1) * 32 + s16 * 16;
                const int subA  = (kbyte >> 7) * 16384;
                const int subB  = (kbyte >> 7) * BSUB;
                const int inner = kbyte & 127;
                #pragma unroll
                for (int mt = 0; mt < 2; mt++) {
                    uint32_t off = (uint32_t)(subA + ar[mt] + (inner ^ arsw[mt]));
                    ldmatrix_x4(af[nxt][mt][0], af[nxt][mt][1], af[nxt][mt][2], af[nxt][mt][3],
                                bufb + off);
                }
                #pragma unroll
                for (int nt2 = 0; nt2 < NT / 2; nt2++) {
                    uint32_t off = (uint32_t)(subB + br[nt2] + (inner ^ brsw[nt2]));
                    uint32_t r0, r1, r2, r3;
                    ldmatrix_x4(r0, r1, r2, r3, bufb + 32768 + off);
                    bf[nxt][nt2 * 2][0] = r0; bf[nxt][nt2 * 2][1] = r2;
                    bf[nxt][nt2 * 2 + 1][0] = r1; bf[nxt][nt2 * 2 + 1][1] = r3;
                }
            }
            #pragma unroll
            for (int mt = 0; mt < 2; mt++)
                #pragma unroll
                for (int nt = 0; nt < NT; nt++)
                    MMA16816F16(acc[mt][nt], af[cur][mt], bf[cur][nt][0], bf[cur][nt][1]);
        }
        __syncthreads();
    }

    // ---------------- epilogue straight from register fragments ----------------
    const int g = lane >> 2, t = lane & 3;
    const int hh = z >> 2, nb = z & 3;
    #pragma unroll
    for (int mt = 0; mt < 2; mt++)
        #pragma unroll
        for (int nt = 0; nt < NT; nt++)
            #pragma unroll
            for (int hr = 0; hr < 2; hr++) {
                int gr = row0 + warp_m * 32 + mt * 16 + g + hr * 8;
                int gc = col0 + warp_n * (BN / 2) + nt * 8 + t * 2;
                float v0 = acc[mt][nt][hr * 2];
                float v1 = acc[mt][nt][hr * 2 + 1];
                if (bias) {
                    if (catmode == 2) { float b = bias[gr]; v0 += b; v1 += b; }
                    else { v0 += bias[gc]; v1 += bias[gc + 1]; }
                }
                if (epi == 1) { v0 = v0 * normcdff(v0); v1 = v1 * normcdff(v1); }
                else if (epi == 2) {
                    long o = (long)gr * Ntot + gc;
                    v0 += res[o]; v1 += res[o + 1];
                }
                if (Cf) {
                    long o = (long)gr * Ntot + gc;
                    Cf[o] = v0; Cf[o + 1] = v1;
                }
                if (Ch) {
                    long o;
                    if (catmode == 1)
                        o = (long)(nb * S_LEN + gr) * HE + (long)hh * E_DIM + gc;
                    else if (catmode == 2)
                        o = (long)z * N_B * ((long)S_LEN * E_DIM)
                          + (long)(gc >> 10) * ((long)S_LEN * E_DIM)
                          + (long)gr * S_LEN + (gc & 1023);
                    else
                        o = (long)gr * Ntot + gc;
                    __half2 hp;
                    hp.x = __float2half_rn(v0);
                    hp.y = __float2half_rn(v1);
                    *(__half2*)(Ch + o) = hp;
                }
            }
}

constexpr int GEMM_SMEM128 = 3 * (32768 + 128 * 256) + 128;   // 196736
constexpr int GEMM_SMEM64  = 3 * (32768 + 64 * 256) + 128;    // 147584

// ---------------- launch ----------------
extern "C" void kernel_launch(void* const* d_in, const int* in_sizes, int n_in,
                              void* d_out, int out_size) {
    const float* inputs = (const float*)d_in[0];
    const float* g1  = (const float*)d_in[1];
    const float* b1  = (const float*)d_in[2];
    const float* Wq  = (const float*)d_in[3];
    const float* bq  = (const float*)d_in[4];
    const float* Wk  = (const float*)d_in[5];
    const float* bk  = (const float*)d_in[6];
    const float* Wv  = (const float*)d_in[7];
    const float* bv  = (const float*)d_in[8];
    const float* Wc  = (const float*)d_in[9];
    const float* bc  = (const float*)d_in[10];
    const float* g2  = (const float*)d_in[11];
    const float* b2  = (const float*)d_in[12];
    const float* Wfc = (const float*)d_in[13];
    const float* bfc = (const float*)d_in[14];
    const float* Wp  = (const float*)d_in[15];
    const float* bp  = (const float*)d_in[16];
    float* out = (float*)d_out;

    cudaFuncSetAttribute(gemm_mma<128>, cudaFuncAttributeMaxDynamicSharedMemorySize, GEMM_SMEM128);
    cudaFuncSetAttribute(gemm_mma<64>,  cudaFuncAttributeMaxDynamicSharedMemorySize, GEMM_SMEM64);

    float *x, *mha, *y2;
    __half *xh, *wqth, *wkth, *wvth;
    __half *qh, *kh, *vth, *sch, *ah;
    __half *cath, *wcth, *y2h, *wfcth, *hbh, *wpth;
    cudaGetSymbolAddress((void**)&x, g_x);     cudaGetSymbolAddress((void**)&xh, g_xh);
    cudaGetSymbolAddress((void**)&wqth, g_wqth);
    cudaGetSymbolAddress((void**)&wkth, g_wkth);
    cudaGetSymbolAddress((void**)&wvth, g_wvth);
    cudaGetSymbolAddress((void**)&qh, g_qh);
    cudaGetSymbolAddress((void**)&kh, g_kh);
    cudaGetSymbolAddress((void**)&vth, g_vth);
    cudaGetSymbolAddress((void**)&sch, g_sch);
    cudaGetSymbolAddress((void**)&ah, g_ah);
    cudaGetSymbolAddress((void**)&cath, g_cath);
    cudaGetSymbolAddress((void**)&wcth, g_wcth);
    cudaGetSymbolAddress((void**)&mha, g_mha);
    cudaGetSymbolAddress((void**)&y2, g_y2);
    cudaGetSymbolAddress((void**)&y2h, g_y2h);
    cudaGetSymbolAddress((void**)&wfcth, g_wfcth);
    cudaGetSymbolAddress((void**)&hbh, g_hbh);
    cudaGetSymbolAddress((void**)&wpth, g_wpth);

    const long WEE = (long)E_DIM * E_DIM;
    const long QKV = (long)NS * E_DIM;
    const long ATT = (long)S_LEN * E_DIM;
    const long SCS = (long)S_LEN * S_LEN;
    dim3 tb(32, 8);

    // 0) LN1 -> x (fp32 + fp16)
    ln_kernel<<<NS, 256>>>(inputs, nullptr, g1, b1, x, xh);
    // weight transposes needed before QKV
    transpose_conv<<<dim3(E_DIM / 32, E_DIM / 32, H_HEADS), tb>>>(Wq, wqth, E_DIM, E_DIM, WEE, WEE);
    transpose_conv<<<dim3(E_DIM / 32, E_DIM / 32, H_HEADS), tb>>>(Wk, wkth, E_DIM, E_DIM, WEE, WEE);
    transpose_conv<<<dim3(E_DIM / 32, E_DIM / 32, H_HEADS), tb>>>(Wv, wvth, E_DIM, E_DIM, WEE, WEE);
    transpose_conv<<<dim3(E_DIM / 32, HE / 32, 1), tb>>>(Wc, wcth, HE, E_DIM, 0, 0);

    dim3 gQKV(E_DIM / 128, NS / 128, H_HEADS);
    // Q projection
    gemm_mma<128><<<gQKV, 256, GEMM_SMEM128>>>(xh, wqth, bq, nullptr,
                                               nullptr, qh, E_DIM, E_DIM,
                                               0, WEE, E_DIM, QKV, 0, 0, 0);
    // K projection
    gemm_mma<128><<<gQKV, 256, GEMM_SMEM128>>>(xh, wkth, bk, nullptr,
                                               nullptr, kh, E_DIM, E_DIM,
                                               0, WEE, E_DIM, QKV, 0, 0, 0);
    // V^T = Wv^T @ x^T, scattered into [h*4+n][e][t] panes with row-bias
    dim3 gVT(NS / 128, E_DIM / 128, H_HEADS);
    gemm_mma<128><<<gVT, 256, GEMM_SMEM128>>>(wvth, xh, bv, nullptr,
                                              nullptr, vth, NS, E_DIM,
                                              WEE, 0, E_DIM, 0, 0, 0, 2);

    // remaining weight transposes
    transpose_conv<<<dim3(FF / 32, E_DIM / 32, 1), tb>>>(Wfc, wfcth, E_DIM, FF, 0, 0);
    transpose_conv<<<dim3(E_DIM / 32, FF / 32, 1), tb>>>(Wp, wpth, FF, E_DIM, 0, 0);

    // scores = Q @ K^T (causal block skip), fp16 out
    dim3 gSC(S_LEN / 128, S_LEN / 128, H_HEADS * N_B);
    gemm_mma<128><<<gSC, 256, GEMM_SMEM128>>>(qh, kh, nullptr, nullptr,
                                              nullptr, sch, S_LEN, E_DIM,
                                              ATT, ATT, 0, SCS, 0, 1, 0);

    // softmax -> attn fp16 (truncated)
    softmax_causal<<<dim3(S_LEN, H_HEADS * N_B), 256>>>(sch, ah);

    // heads = attn @ V^T panes, cat layout out.  BN=64: 4608 blocks, smooth waves.
    dim3 gAV(E_DIM / 64, S_LEN / 128, H_HEADS * N_B);
    gemm_mma<64><<<gAV, 256, GEMM_SMEM64>>>(ah, vth, nullptr, nullptr,
                                            nullptr, cath, E_DIM, S_LEN,
                                            SCS, ATT, 0, 0, 0, 2, 1);

    // c_proj.  BN=64: 384 blocks (vs 192) -> kills 2-wave quantization.
    dim3 gCP(E_DIM / 64, NS / 128, 1);
    gemm_mma<64><<<gCP, 256, GEMM_SMEM64>>>(cath, wcth, bc, nullptr,
                                            mha, nullptr, E_DIM, HE,
                                            0, 0, 0, 0, 0, 0, 0);

    // y2 = LN2(mha + x)
    ln_kernel<<<NS, 256>>>(mha, x, g2, b2, y2, y2h);

    // fc + GELU.  BN=64: 1536 blocks.
    dim3 gFC(FF / 64, NS / 128, 1);
    gemm_mma<64><<<gFC, 256, GEMM_SMEM64>>>(y2h, wfcth, bfc, nullptr,
                                            nullptr, hbh, FF, E_DIM,
                                            0, 0, 0, 0, 1, 0, 0);

    // proj + bias + residual(y2) -> out.  BN=64: 384 blocks.
    dim3 gPJ(E_DIM / 64, NS / 128, 1);
    gemm_mma<64><<<gPJ, 256, GEMM_SMEM64>>>(hbh, wpth, bp, y2,
                                            out, nullptr, E_DIM, FF,
                                            0, 0, 0, 0, 2, 0, 0);
}

// round 16
// speedup vs baseline: 7.0650x; 1.1510x over previous
#include <cuda_runtime.h>
#include <cuda_fp16.h>
#include <math.h>
#include <stdint.h>
#include <string.h>

// Problem constants
#define N_B    4
#define S_LEN  1024
#define E_DIM  768
#define H_HEADS 12
constexpr int NS  = N_B * S_LEN;       // 4096
constexpr int HE  = H_HEADS * E_DIM;   // 9216
constexpr int FF  = 4 * E_DIM;         // 3072

// ---------------- scratch (__device__ globals; allocation-free) ----------------
__device__ float  g_x   [(size_t)NS * E_DIM];
__device__ __half g_xh  [(size_t)NS * E_DIM];

__device__ __half g_wqth[(size_t)H_HEADS * E_DIM * E_DIM];
__device__ __half g_wkth[(size_t)H_HEADS * E_DIM * E_DIM];
__device__ __half g_wvth[(size_t)H_HEADS * E_DIM * E_DIM];

__device__ __half g_qh  [(size_t)H_HEADS * NS * E_DIM];
__device__ __half g_kh  [(size_t)H_HEADS * NS * E_DIM];
__device__ __half g_vth [(size_t)H_HEADS * NS * E_DIM];   // [h*4+n][e][t] panes

__device__ __half g_sch [(size_t)H_HEADS * N_B * S_LEN * S_LEN];  // fp16 scores
__device__ __half g_ah  [(size_t)H_HEADS * N_B * S_LEN * S_LEN];

__device__ __half g_cath[(size_t)NS * HE];
__device__ __half g_wcth[(size_t)HE * E_DIM];
__device__ float  g_mha [(size_t)NS * E_DIM];

__device__ float  g_y2  [(size_t)NS * E_DIM];
__device__ __half g_y2h [(size_t)NS * E_DIM];
__device__ __half g_wfcth[(size_t)E_DIM * FF];
__device__ __half g_hbh [(size_t)NS * FF];
__device__ __half g_wpth[(size_t)FF * E_DIM];

// ---------------- helpers ----------------
__device__ __forceinline__ uint32_t smem_u32(const void* p) {
    uint32_t a;
    asm("{ .reg .u64 t; cvta.to.shared.u64 t, %1; cvt.u32.u64 %0, t; }" : "=r"(a) : "l"(p));
    return a;
}

__device__ __forceinline__ void cp_async16(uint32_t dst, const void* src) {
    asm volatile("cp.async.cg.shared.global [%0], [%1], 16;" :: "r"(dst), "l"(src) : "memory");
}
__device__ __forceinline__ void cp_commit() {
    asm volatile("cp.async.commit_group;" ::: "memory");
}
__device__ __forceinline__ void cp_wait1() { asm volatile("cp.async.wait_group 1;" ::: "memory"); }
__device__ __forceinline__ void cp_wait0() { asm volatile("cp.async.wait_group 0;" ::: "memory"); }

__device__ __forceinline__ void ldmatrix_x4(uint32_t& r0, uint32_t& r1, uint32_t& r2, uint32_t& r3,
                                            uint32_t addr) {
    asm volatile("ldmatrix.sync.aligned.m8n8.x4.shared.b16 {%0,%1,%2,%3}, [%4];"
                 : "=r"(r0), "=r"(r1), "=r"(r2), "=r"(r3) : "r"(addr));
}

#define MMA16816F16(acc, af, b0, b1) \
    asm volatile( \
        "mma.sync.aligned.m16n8k16.row.col.f32.f16.f16.f32 " \
        "{%0,%1,%2,%3}, {%4,%5,%6,%7}, {%8,%9}, {%0,%1,%2,%3};" \
        : "+f"((acc)[0]), "+f"((acc)[1]), "+f"((acc)[2]), "+f"((acc)[3]) \
        : "r"((af)[0]), "r"((af)[1]), "r"((af)[2]), "r"((af)[3]), \
          "r"(b0), "r"(b1))

// ---------------- reductions ----------------
__device__ __forceinline__ float warpReduceSum(float v) {
    #pragma unroll
    for (int o = 16; o > 0; o >>= 1) v += __shfl_xor_sync(0xffffffffu, v, o);
    return v;
}
__device__ __forceinline__ float warpReduceMax(float v) {
    #pragma unroll
    for (int o = 16; o > 0; o >>= 1) v = fmaxf(v, __shfl_xor_sync(0xffffffffu, v, o));
    return v;
}

// ---------------- LayerNorm: fp32 out + fp16 out ----------------
__global__ void ln_kernel(const float* __restrict__ in, const float* __restrict__ resid,
                          const float* __restrict__ gamma, const float* __restrict__ beta,
                          float* __restrict__ out, __half* __restrict__ oh) {
    long base = (long)blockIdx.x * E_DIM;
    int tid = threadIdx.x;
    float vals[3];
    float s = 0.f, s2 = 0.f;
    #pragma unroll
    for (int i = 0; i < 3; i++) {
        int c = tid + i * 256;
        float v = in[base + c];
        if (resid) v += resid[base + c];
        vals[i] = v; s += v; s2 += v * v;
    }
    __shared__ float shs[8], shs2[8];
    s = warpReduceSum(s); s2 = warpReduceSum(s2);
    int lane = tid & 31, w = tid >> 5;
    if (lane == 0) { shs[w] = s; shs2[w] = s2; }
    __syncthreads();
    if (tid < 32) {
        float a = (lane < 8) ? shs[lane]  : 0.f;
        float b = (lane < 8) ? shs2[lane] : 0.f;
        a = warpReduceSum(a); b = warpReduceSum(b);
        if (lane == 0) { shs[0] = a; shs2[0] = b; }
    }
    __syncthreads();
    float mean = shs[0] * (1.f / E_DIM);
    float var  = shs2[0] * (1.f / E_DIM) - mean * mean;
    float rstd = rsqrtf(var + 1e-5f);
    #pragma unroll
    for (int i = 0; i < 3; i++) {
        int c = tid + i * 256;
        float v = (vals[i] - mean) * rstd * gamma[c] + beta[c];
        out[base + c] = v;
        oh[base + c] = __float2half_rn(v);
    }
}

// ---------------- causal softmax (fp16 scores in, fp16 probs out, truncated) ----------------
__global__ void softmax_causal(const __half* __restrict__ scores, __half* __restrict__ ah) {
    int srow = blockIdx.x;
    long off = ((long)blockIdx.y * S_LEN + srow) * S_LEN;
    const __half* row = scores + off;
    int tid = threadIdx.x;
    const float scale = 0.03608439182435161f;  // 1/sqrt(768)
    const int L = ((srow >> 6) + 1) << 6;      // AV (BN=64 K-limit rounds to 128) safe: keep 128-mult
    const int L128 = ((srow >> 7) + 1) << 7;
    (void)L;
    float v[4];
    float mx = -1e30f;
    #pragma unroll
    for (int i = 0; i < 4; i++) {
        int t = tid + i * 256;
        float val = (t <= srow) ? __half2float(row[t]) * scale : -1e30f;
        v[i] = val; mx = fmaxf(mx, val);
    }
    __shared__ float sh[8];
    int lane = tid & 31, w = tid >> 5;
    mx = warpReduceMax(mx);
    if (lane == 0) sh[w] = mx;
    __syncthreads();
    if (tid < 32) {
        float m2 = (lane < 8) ? sh[lane] : -1e30f;
        m2 = warpReduceMax(m2);
        if (lane == 0) sh[0] = m2;
    }
    __syncthreads();
    mx = sh[0];
    __syncthreads();
    float sum = 0.f;
    #pragma unroll
    for (int i = 0; i < 4; i++) {
        int t = tid + i * 256;
        float e = (t <= srow) ? __expf(v[i] - mx) : 0.f;
        v[i] = e; sum += e;
    }
    sum = warpReduceSum(sum);
    if (lane == 0) sh[w] = sum;
    __syncthreads();
    if (tid < 32) {
        float s2 = (lane < 8) ? sh[lane] : 0.f;
        s2 = warpReduceSum(s2);
        if (lane == 0) sh[0] = s2;
    }
    __syncthreads();
    float inv = 1.f / sh[0];
    #pragma unroll
    for (int i = 0; i < 4; i++) {
        int t = tid + i * 256;
        if (t < L128) ah[off + t] = __float2half_rn(v[i] * inv);
    }
}

// ---------------- tiled transpose + fp16 convert: src[R,C] f32 -> dst[C,R] ----------------
__global__ void transpose_conv(const float* __restrict__ src,
                               __half* __restrict__ dh,
                               int R, int C, long sS, long sD) {
    __shared__ float t[32][33];
    src += (long)blockIdx.z * sS;
    dh  += (long)blockIdx.z * sD;
    int c0 = blockIdx.x * 32, r0 = blockIdx.y * 32;
    #pragma unroll
    for (int i = 0; i < 32; i += 8)
        t[threadIdx.y + i][threadIdx.x] = src[(long)(r0 + threadIdx.y + i) * C + c0 + threadIdx.x];
    __syncthreads();
    #pragma unroll
    for (int i = 0; i < 32; i += 8) {
        float v = t[threadIdx.x][threadIdx.y + i];
        long o = (long)(c0 + threadIdx.y + i) * R + r0 + threadIdx.x;
        dh[o] = __float2half_rn(v);
    }
}

// ---------------- mma.sync fp16 GEMM, BK=128, BN=64, 2-stage, 2 CTAs/SM ----------------
// C[M,N] = A[M,K](fp16) @ B[N,K]^T(fp16), fp32 accum in regs.
// Tile 128x64. 8 warps (4m x 2n), warp tile 32x32. 2-stage cp.async pipeline,
// register-double-buffered fragments. __launch_bounds__(256,2): two CTAs per SM so
// one block's pipeline fill/drain overlaps the other's mainloop.
// epi: 0 bias, 1 bias+GELU(exact), 2 bias+residual.
// causal: 0 none, 1 skip upper blocks, 2 K limited to row0+128.
// catmode: 0 normal; 1 cat-heads scatter; 2 V^T pane scatter (row-bias).
constexpr int BN = 64;
constexpr int NT = BN / 16;                 // 4 n8-tiles per warp
constexpr int BSTAGE = 32768 + BN * 256;    // 48KB: A tile (32KB) + B tile (16KB)
constexpr int BSUB = BN * 128;              // per-64k-subtile B bytes
constexpr int GEMM_SMEM = 2 * BSTAGE + 128; // 98432 -> 2 CTAs/SM

__global__ void __launch_bounds__(256, 2)
gemm_mma(const __half* __restrict__ A, const __half* __restrict__ B,
         const float* __restrict__ bias, const float* __restrict__ res,
         float* __restrict__ Cf, __half* __restrict__ Ch,
         int Ntot, int K,
         long sA, long sB, long sBias, long sC,
         int epi, int causal, int catmode) {
    extern __shared__ char smem_raw[];
    const int row0 = blockIdx.y * 128;
    const int col0 = blockIdx.x * BN;
    if (causal == 1 && col0 > row0 + 127) return;

    const int z = blockIdx.z;
    A += (long)z * sA;
    B += (long)z * sB;
    if (bias) bias += (long)z * sBias;
    if (!catmode) {
        if (Cf) Cf += (long)z * sC;
        if (Ch) Ch += (long)z * sC;
    }

    const int tid = threadIdx.x;
    const int wid = tid >> 5, lane = tid & 31;
    const int warp_m = wid & 3, warp_n = wid >> 2;

    uint32_t sbase = (smem_u32(smem_raw) + 127) & ~127u;

    int Keff = K;
    if (causal == 2) { int kl = row0 + 128; Keff = kl < K ? kl : K; }
    const int nch = Keff >> 7;

    float acc[2][NT][4];
    #pragma unroll
    for (int a = 0; a < 2; a++)
        #pragma unroll
        for (int b = 0; b < NT; b++)
            #pragma unroll
            for (int d = 0; d < 4; d++) acc[a][b][d] = 0.f;

    auto issue = [&](int c) {
        uint32_t dstb = sbase + (uint32_t)(c & 1) * BSTAGE;
        int k0 = c << 7;
        // A tile: 128 rows x 16 segs
        #pragma unroll
        for (int i = 0; i < 8; i++) {
            int idx = i * 256 + tid;
            int r = idx >> 4, kb = idx & 15;
            uint32_t so = (uint32_t)((kb >> 3) * 16384 + r * 128 +
                                     (((kb & 7) * 16) ^ ((r & 7) << 4)));
            const void* src = (const char*)(A + (long)(row0 + r) * K + k0) + kb * 16;
            cp_async16(dstb + so, src);
        }
        // B tile: 64 rows x 16 segs
        #pragma unroll
        for (int i = 0; i < 4; i++) {
            int idx = i * 256 + tid;
            int r = idx >> 4, kb = idx & 15;
            uint32_t so = (uint32_t)((kb >> 3) * BSUB + r * 128 +
                                     (((kb & 7) * 16) ^ ((r & 7) << 4)));
            const void* src = (const char*)(B + (long)(col0 + r) * K + k0) + kb * 16;
            cp_async16(dstb + 32768 + so, src);
        }
        cp_commit();
    };

    // ldmatrix lane addressing pieces
    const int li  = lane & 7;
    const int s8  = (lane >> 3) & 1;
    const int s16 = lane >> 4;

    int ar[2], arsw[2];
    #pragma unroll
    for (int mt = 0; mt < 2; mt++) {
        int r = warp_m * 32 + mt * 16 + s8 * 8 + li;
        ar[mt] = r * 128; arsw[mt] = (r & 7) << 4;
    }
    int br[NT / 2], brsw[NT / 2];
    #pragma unroll
    for (int nt2 = 0; nt2 < NT / 2; nt2++) {
        int r = warp_n * (BN / 2) + nt2 * 16 + s8 * 8 + li;
        br[nt2] = r * 128; brsw[nt2] = (r & 7) << 4;
    }

    // fragment double buffers
    uint32_t af[2][2][4];
    uint32_t bf[2][NT][2];

    issue(0);
    for (int c = 0; c < nch; c++) {
        if (c + 1 < nch) { issue(c + 1); cp_wait1(); }
        else cp_wait0();
        __syncthreads();
        uint32_t bufb = sbase + (uint32_t)(c & 1) * BSTAGE;

        // load k-step 0 fragments into buffer 0
        {
            const int kbyte = s16 * 16;
            const int inner = kbyte & 127;
            #pragma unroll
            for (int mt = 0; mt < 2; mt++) {
                uint32_t off = (uint32_t)(ar[mt] + (inner ^ arsw[mt]));
                ldmatrix_x4(af[0][mt][0], af[0][mt][1], af[0][mt][2], af[0][mt][3], bufb + off);
            }
            #pragma unroll
            for (int nt2 = 0; nt2 < NT / 2; nt2++) {
                uint32_t off = (uint32_t)(br[nt2] + (inner ^ brsw[nt2]));
                uint32_t r0, r1, r2, r3;
                ldmatrix_x4(r0, r1, r2, r3, bufb + 32768 + off);
                bf[0][nt2 * 2][0] = r0; bf[0][nt2 * 2][1] = r2;
                bf[0][nt2 * 2 + 1][0] = r1; bf[0][nt2 * 2 + 1][1] = r3;
            }
        }

        #pragma unroll
        for (int ks = 0; ks < 8; ks++) {
            const int cur = ks & 1, nxt = cur ^ 1;
            if (ks < 7) {
                const int kbyte = (ks + 1) * 32 + s16 * 16;
                const int subA  = (kbyte >> 7) * 16384;
                const int subB  = (kbyte >> 7) * BSUB;
                const int inner = kbyte & 127;
                #pragma unroll
                for (int mt = 0; mt < 2; mt++) {
                    uint32_t off = (uint32_t)(subA + ar[mt] + (inner ^ arsw[mt]));
                    ldmatrix_x4(af[nxt][mt][0], af[nxt][mt][1], af[nxt][mt][2], af[nxt][mt][3],
                                bufb + off);
                }
                #pragma unroll
                for (int nt2 = 0; nt2 < NT / 2; nt2++) {
                    uint32_t off = (uint32_t)(subB + br[nt2] + (inner ^ brsw[nt2]));
                    uint32_t r0, r1, r2, r3;
                    ldmatrix_x4(r0, r1, r2, r3, bufb + 32768 + off);
                    bf[nxt][nt2 * 2][0] = r0; bf[nxt][nt2 * 2][1] = r2;
                    bf[nxt][nt2 * 2 + 1][0] = r1; bf[nxt][nt2 * 2 + 1][1] = r3;
                }
            }
            #pragma unroll
            for (int mt = 0; mt < 2; mt++)
                #pragma unroll
                for (int nt = 0; nt < NT; nt++)
                    MMA16816F16(acc[mt][nt], af[cur][mt], bf[cur][nt][0], bf[cur][nt][1]);
        }
        __syncthreads();
    }

    // ---------------- epilogue straight from register fragments ----------------
    const int g = lane >> 2, t = lane & 3;
    const int hh = z >> 2, nb = z & 3;
    #pragma unroll
    for (int mt = 0; mt < 2; mt++)
        #pragma unroll
        for (int nt = 0; nt < NT; nt++)
            #pragma unroll
            for (int hr = 0; hr < 2; hr++) {
                int gr = row0 + warp_m * 32 + mt * 16 + g + hr * 8;
                int gc = col0 + warp_n * (BN / 2) + nt * 8 + t * 2;
                float v0 = acc[mt][nt][hr * 2];
                float v1 = acc[mt][nt][hr * 2 + 1];
                if (bias) {
                    if (catmode == 2) { float b = bias[gr]; v0 += b; v1 += b; }
                    else { v0 += bias[gc]; v1 += bias[gc + 1]; }
                }
                if (epi == 1) { v0 = v0 * normcdff(v0); v1 = v1 * normcdff(v1); }
                else if (epi == 2) {
                    long o = (long)gr * Ntot + gc;
                    v0 += res[o]; v1 += res[o + 1];
                }
                if (Cf) {
                    long o = (long)gr * Ntot + gc;
                    Cf[o] = v0; Cf[o + 1] = v1;
                }
                if (Ch) {
                    long o;
                    if (catmode == 1)
                        o = (long)(nb * S_LEN + gr) * HE + (long)hh * E_DIM + gc;
                    else if (catmode == 2)
                        o = (long)z * N_B * ((long)S_LEN * E_DIM)
                          + (long)(gc >> 10) * ((long)S_LEN * E_DIM)
                          + (long)gr * S_LEN + (gc & 1023);
                    else
                        o = (long)gr * Ntot + gc;
                    __half2 hp;
                    hp.x = __float2half_rn(v0);
                    hp.y = __float2half_rn(v1);
                    *(__half2*)(Ch + o) = hp;
                }
            }
}

// ---------------- launch ----------------
extern "C" void kernel_launch(void* const* d_in, const int* in_sizes, int n_in,
                              void* d_out, int out_size) {
    const float* inputs = (const float*)d_in[0];
    const float* g1  = (const float*)d_in[1];
    const float* b1  = (const float*)d_in[2];
    const float* Wq  = (const float*)d_in[3];
    const float* bq  = (const float*)d_in[4];
    const float* Wk  = (const float*)d_in[5];
    const float* bk  = (const float*)d_in[6];
    const float* Wv  = (const float*)d_in[7];
    const float* bv  = (const float*)d_in[8];
    const float* Wc  = (const float*)d_in[9];
    const float* bc  = (const float*)d_in[10];
    const float* g2  = (const float*)d_in[11];
    const float* b2  = (const float*)d_in[12];
    const float* Wfc = (const float*)d_in[13];
    const float* bfc = (const float*)d_in[14];
    const float* Wp  = (const float*)d_in[15];
    const float* bp  = (const float*)d_in[16];
    float* out = (float*)d_out;

    cudaFuncSetAttribute(gemm_mma, cudaFuncAttributeMaxDynamicSharedMemorySize, GEMM_SMEM);

    float *x, *mha, *y2;
    __half *xh, *wqth, *wkth, *wvth;
    __half *qh, *kh, *vth, *sch, *ah;
    __half *cath, *wcth, *y2h, *wfcth, *hbh, *wpth;
    cudaGetSymbolAddress((void**)&x, g_x);     cudaGetSymbolAddress((void**)&xh, g_xh);
    cudaGetSymbolAddress((void**)&wqth, g_wqth);
    cudaGetSymbolAddress((void**)&wkth, g_wkth);
    cudaGetSymbolAddress((void**)&wvth, g_wvth);
    cudaGetSymbolAddress((void**)&qh, g_qh);
    cudaGetSymbolAddress((void**)&kh, g_kh);
    cudaGetSymbolAddress((void**)&vth, g_vth);
    cudaGetSymbolAddress((void**)&sch, g_sch);
    cudaGetSymbolAddress((void**)&ah, g_ah);
    cudaGetSymbolAddress((void**)&cath, g_cath);
    cudaGetSymbolAddress((void**)&wcth, g_wcth);
    cudaGetSymbolAddress((void**)&mha, g_mha);
    cudaGetSymbolAddress((void**)&y2, g_y2);
    cudaGetSymbolAddress((void**)&y2h, g_y2h);
    cudaGetSymbolAddress((void**)&wfcth, g_wfcth);
    cudaGetSymbolAddress((void**)&hbh, g_hbh);
    cudaGetSymbolAddress((void**)&wpth, g_wpth);

    const long WEE = (long)E_DIM * E_DIM;
    const long QKV = (long)NS * E_DIM;
    const long ATT = (long)S_LEN * E_DIM;
    const long SCS = (long)S_LEN * S_LEN;
    dim3 tb(32, 8);

    // 0) LN1 -> x (fp32 + fp16)
    ln_kernel<<<NS, 256>>>(inputs, nullptr, g1, b1, x, xh);
    // weight transposes needed before QKV
    transpose_conv<<<dim3(E_DIM / 32, E_DIM / 32, H_HEADS), tb>>>(Wq, wqth, E_DIM, E_DIM, WEE, WEE);
    transpose_conv<<<dim3(E_DIM / 32, E_DIM / 32, H_HEADS), tb>>>(Wk, wkth, E_DIM, E_DIM, WEE, WEE);
    transpose_conv<<<dim3(E_DIM / 32, E_DIM / 32, H_HEADS), tb>>>(Wv, wvth, E_DIM, E_DIM, WEE, WEE);
    transpose_conv<<<dim3(E_DIM / 32, HE / 32, 1), tb>>>(Wc, wcth, HE, E_DIM, 0, 0);

    dim3 gQKV(E_DIM / BN, NS / 128, H_HEADS);
    // Q projection
    gemm_mma<<<gQKV, 256, GEMM_SMEM>>>(xh, wqth, bq, nullptr,
                                       nullptr, qh, E_DIM, E_DIM,
                                       0, WEE, E_DIM, QKV, 0, 0, 0);
    // K projection
    gemm_mma<<<gQKV, 256, GEMM_SMEM>>>(xh, wkth, bk, nullptr,
                                       nullptr, kh, E_DIM, E_DIM,
                                       0, WEE, E_DIM, QKV, 0, 0, 0);
    // V^T = Wv^T @ x^T, scattered into [h*4+n][e][t] panes with row-bias
    dim3 gVT(NS / BN, E_DIM / 128, H_HEADS);
    gemm_mma<<<gVT, 256, GEMM_SMEM>>>(wvth, xh, bv, nullptr,
                                      nullptr, vth, NS, E_DIM,
                                      WEE, 0, E_DIM, 0, 0, 0, 2);

    // remaining weight transposes
    transpose_conv<<<dim3(FF / 32, E_DIM / 32, 1), tb>>>(Wfc, wfcth, E_DIM, FF, 0, 0);
    transpose_conv<<<dim3(E_DIM / 32, FF / 32, 1), tb>>>(Wp, wpth, FF, E_DIM, 0, 0);

    // scores = Q @ K^T (causal block skip), fp16 out
    dim3 gSC(S_LEN / BN, S_LEN / 128, H_HEADS * N_B);
    gemm_mma<<<gSC, 256, GEMM_SMEM>>>(qh, kh, nullptr, nullptr,
                                      nullptr, sch, S_LEN, E_DIM,
                                      ATT, ATT, 0, SCS, 0, 1, 0);

    // softmax -> attn fp16 (truncated)
    softmax_causal<<<dim3(S_LEN, H_HEADS * N_B), 256>>>(sch, ah);

    // heads = attn @ V^T panes, cat layout out
    dim3 gAV(E_DIM / BN, S_LEN / 128, H_HEADS * N_B);
    gemm_mma<<<gAV, 256, GEMM_SMEM>>>(ah, vth, nullptr, nullptr,
                                      nullptr, cath, E_DIM, S_LEN,
                                      SCS, ATT, 0, 0, 0, 2, 1);

    // c_proj
    dim3 gCP(E_DIM / BN, NS / 128, 1);
    gemm_mma<<<gCP, 256, GEMM_SMEM>>>(cath, wcth, bc, nullptr,
                                      mha, nullptr, E_DIM, HE,
                                      0, 0, 0, 0, 0, 0, 0);

    // y2 = LN2(mha + x)
    ln_kernel<<<NS, 256>>>(mha, x, g2, b2, y2, y2h);

    // fc + GELU
    dim3 gFC(FF / BN, NS / 128, 1);
    gemm_mma<<<gFC, 256, GEMM_SMEM>>>(y2h, wfcth, bfc, nullptr,
                                      nullptr, hbh, FF, E_DIM,
                                      0, 0, 0, 0, 1, 0, 0);

    // proj + bias + residual(y2) -> out
    dim3 gPJ(E_DIM / BN, NS / 128, 1);
    gemm_mma<<<gPJ, 256, GEMM_SMEM>>>(hbh, wpth, bp, y2,
                                      out, nullptr, E_DIM, FF,
                                      0, 0, 0, 0, 2, 0, 0);
}

// round 17
// speedup vs baseline: 7.3147x; 1.0353x over previous
#include <cuda_runtime.h>
#include <cuda_fp16.h>
#include <math.h>
#include <stdint.h>
#include <string.h>

// Problem constants
#define N_B    4
#define S_LEN  1024
#define E_DIM  768
#define H_HEADS 12
constexpr int NS  = N_B * S_LEN;       // 4096
constexpr int HE  = H_HEADS * E_DIM;   // 9216
constexpr int FF  = 4 * E_DIM;         // 3072

// ---------------- scratch (__device__ globals; allocation-free) ----------------
__device__ float  g_x   [(size_t)NS * E_DIM];
__device__ __half g_xh  [(size_t)NS * E_DIM];

__device__ __half g_wqth[(size_t)H_HEADS * E_DIM * E_DIM];
__device__ __half g_wkth[(size_t)H_HEADS * E_DIM * E_DIM];
__device__ __half g_wvth[(size_t)H_HEADS * E_DIM * E_DIM];

__device__ __half g_qh  [(size_t)H_HEADS * NS * E_DIM];
__device__ __half g_kh  [(size_t)H_HEADS * NS * E_DIM];
__device__ __half g_vth [(size_t)H_HEADS * NS * E_DIM];   // [h*4+n][e][t] panes

__device__ __half g_sch [(size_t)H_HEADS * N_B * S_LEN * S_LEN];  // fp16 scores (pre-scaled)
__device__ __half g_ah  [(size_t)H_HEADS * N_B * S_LEN * S_LEN];

__device__ __half g_cath[(size_t)NS * HE];
__device__ __half g_wcth[(size_t)HE * E_DIM];
__device__ float  g_mha [(size_t)NS * E_DIM];

__device__ float  g_y2  [(size_t)NS * E_DIM];
__device__ __half g_y2h [(size_t)NS * E_DIM];
__device__ __half g_wfcth[(size_t)E_DIM * FF];
__device__ __half g_hbh [(size_t)NS * FF];
__device__ __half g_wpth[(size_t)FF * E_DIM];

// ---------------- helpers ----------------
__device__ __forceinline__ uint32_t smem_u32(const void* p) {
    uint32_t a;
    asm("{ .reg .u64 t; cvta.to.shared.u64 t, %1; cvt.u32.u64 %0, t; }" : "=r"(a) : "l"(p));
    return a;
}

__device__ __forceinline__ void cp_async16(uint32_t dst, const void* src) {
    asm volatile("cp.async.cg.shared.global [%0], [%1], 16;" :: "r"(dst), "l"(src) : "memory");
}
__device__ __forceinline__ void cp_commit() {
    asm volatile("cp.async.commit_group;" ::: "memory");
}
__device__ __forceinline__ void cp_wait1() { asm volatile("cp.async.wait_group 1;" ::: "memory"); }
__device__ __forceinline__ void cp_wait0() { asm volatile("cp.async.wait_group 0;" ::: "memory"); }

__device__ __forceinline__ void ldmatrix_x4(uint32_t& r0, uint32_t& r1, uint32_t& r2, uint32_t& r3,
                                            uint32_t addr) {
    asm volatile("ldmatrix.sync.aligned.m8n8.x4.shared.b16 {%0,%1,%2,%3}, [%4];"
                 : "=r"(r0), "=r"(r1), "=r"(r2), "=r"(r3) : "r"(addr));
}

#define MMA16816F16(acc, af, b0, b1) \
    asm volatile( \
        "mma.sync.aligned.m16n8k16.row.col.f32.f16.f16.f32 " \
        "{%0,%1,%2,%3}, {%4,%5,%6,%7}, {%8,%9}, {%0,%1,%2,%3};" \
        : "+f"((acc)[0]), "+f"((acc)[1]), "+f"((acc)[2]), "+f"((acc)[3]) \
        : "r"((af)[0]), "r"((af)[1]), "r"((af)[2]), "r"((af)[3]), \
          "r"(b0), "r"(b1))

// ---------------- reductions ----------------
__device__ __forceinline__ float warpReduceSum(float v) {
    #pragma unroll
    for (int o = 16; o > 0; o >>= 1) v += __shfl_xor_sync(0xffffffffu, v, o);
    return v;
}
__device__ __forceinline__ float warpReduceMax(float v) {
    #pragma unroll
    for (int o = 16; o > 0; o >>= 1) v = fmaxf(v, __shfl_xor_sync(0xffffffffu, v, o));
    return v;
}

// ---------------- LayerNorm: fp32 out + fp16 out ----------------
__global__ void ln_kernel(const float* __restrict__ in, const float* __restrict__ resid,
                          const float* __restrict__ gamma, const float* __restrict__ beta,
                          float* __restrict__ out, __half* __restrict__ oh) {
    long base = (long)blockIdx.x * E_DIM;
    int tid = threadIdx.x;
    float vals[3];
    float s = 0.f, s2 = 0.f;
    #pragma unroll
    for (int i = 0; i < 3; i++) {
        int c = tid + i * 256;
        float v = in[base + c];
        if (resid) v += resid[base + c];
        vals[i] = v; s += v; s2 += v * v;
    }
    __shared__ float shs[8], shs2[8];
    s = warpReduceSum(s); s2 = warpReduceSum(s2);
    int lane = tid & 31, w = tid >> 5;
    if (lane == 0) { shs[w] = s; shs2[w] = s2; }
    __syncthreads();
    if (tid < 32) {
        float a = (lane < 8) ? shs[lane]  : 0.f;
        float b = (lane < 8) ? shs2[lane] : 0.f;
        a = warpReduceSum(a); b = warpReduceSum(b);
        if (lane == 0) { shs[0] = a; shs2[0] = b; }
    }
    __syncthreads();
    float mean = shs[0] * (1.f / E_DIM);
    float var  = shs2[0] * (1.f / E_DIM) - mean * mean;
    float rstd = rsqrtf(var + 1e-5f);
    #pragma unroll
    for (int i = 0; i < 3; i++) {
        int c = tid + i * 256;
        float v = (vals[i] - mean) * rstd * gamma[c] + beta[c];
        out[base + c] = v;
        oh[base + c] = __float2half_rn(v);
    }
}

// ---------------- warp-per-row causal softmax (scores pre-scaled via Q) ----------------
// grid: (S_LEN/8, 48), block 256 = 8 warps; warp w owns row blockIdx.x*8+w.
// Row (1024 fp16) held in 16 x float2 registers; no block barriers.
__global__ void softmax_causal(const __half* __restrict__ scores, __half* __restrict__ ah) {
    int w = threadIdx.x >> 5, lane = threadIdx.x & 31;
    int srow = blockIdx.x * 8 + w;
    long off = ((long)blockIdx.y * S_LEN + srow) * S_LEN;
    const __half2* row2 = (const __half2*)(scores + off);
    float2 f[16];
    float mx = -1e30f;
    #pragma unroll
    for (int i = 0; i < 16; i++) {
        int t0 = i * 64 + lane * 2;
        float2 v = __half22float2(row2[i * 32 + lane]);
        v.x = (t0     <= srow) ? v.x : -1e30f;
        v.y = (t0 + 1 <= srow) ? v.y : -1e30f;
        f[i] = v;
        mx = fmaxf(mx, fmaxf(v.x, v.y));
    }
    mx = warpReduceMax(mx);
    float sum = 0.f;
    #pragma unroll
    for (int i = 0; i < 16; i++) {
        f[i].x = __expf(f[i].x - mx);
        f[i].y = __expf(f[i].y - mx);
        sum += f[i].x + f[i].y;
    }
    sum = warpReduceSum(sum);
    float inv = 1.f / sum;
    // AV GEMM reads cols < L128 only (K limited to row0+128)
    const int iw = ((srow >> 7) + 1) * 2;   // write groups of 64 elems
    __half2* out2 = (__half2*)(ah + off);
    #pragma unroll
    for (int i = 0; i < 16; i++)
        if (i < iw)
            out2[i * 32 + lane] = __floats2half2_rn(f[i].x * inv, f[i].y * inv);
}

// ---------------- fused weight prep: all six W transposes+fp16 in ONE launch ----------------
// Each 32x32 tile job decoded from blockIdx.x. src[R,C] fp32 -> dst[C,R] fp16.
__global__ void prep_weights(const float* __restrict__ Wq, const float* __restrict__ Wk,
                             const float* __restrict__ Wv, const float* __restrict__ Wc,
                             const float* __restrict__ Wfc, const float* __restrict__ Wp,
                             __half* __restrict__ wqth, __half* __restrict__ wkth,
                             __half* __restrict__ wvth, __half* __restrict__ wcth,
                             __half* __restrict__ wfcth, __half* __restrict__ wpth) {
    const long WEE = (long)E_DIM * E_DIM;
    int b = blockIdx.x;
    const float* src; __half* dst; int R, C;
    // job table: [Wq 6912][Wk 6912][Wv 6912][Wc 6912][Wfc 2304][Wp 2304]
    if (b < 20736) {
        int which = b / 6912;          // 0,1,2
        int rem   = b % 6912;
        int z     = rem / 576;         // head
        int tile  = rem % 576;         // 24x24 tiles
        R = E_DIM; C = E_DIM;
        const float* s0 = which == 0 ? Wq : which == 1 ? Wk : Wv;
        __half* d0      = which == 0 ? wqth : which == 1 ? wkth : wvth;
        src = s0 + (long)z * WEE;
        dst = d0 + (long)z * WEE;
        b = tile;
    } else if (b < 27648) {
        int tile = b - 20736;          // 24 x 288 tiles (nx=24)
        R = HE; C = E_DIM;
        src = Wc; dst = wcth;
        b = tile;
    } else if (b < 29952) {
        int tile = b - 27648;          // nx = 96, ny = 24
        R = E_DIM; C = FF;
        src = Wfc; dst = wfcth;
        b = tile;
    } else {
        int tile = b - 29952;          // nx = 24, ny = 96
        R = FF; C = E_DIM;
        src = Wp; dst = wpth;
        b = tile;
    }
    int nx = C / 32;
    int tx_t = b % nx, ty_t = b / nx;
    int c0 = tx_t * 32, r0 = ty_t * 32;

    __shared__ float t[32][33];
    #pragma unroll
    for (int i = 0; i < 32; i += 8)
        t[threadIdx.y + i][threadIdx.x] = src[(long)(r0 + threadIdx.y + i) * C + c0 + threadIdx.x];
    __syncthreads();
    #pragma unroll
    for (int i = 0; i < 32; i += 8) {
        float v = t[threadIdx.x][threadIdx.y + i];
        long o = (long)(c0 + threadIdx.y + i) * R + r0 + threadIdx.x;
        dst[o] = __float2half_rn(v);
    }
}

// ---------------- mma.sync fp16 GEMM, BK=128, BN=64, 2-stage, 2 CTAs/SM ----------------
// epi: 0 bias, 1 bias+GELU(exact), 2 bias+residual, 3 (bias)*1/sqrt(E) [Q-scale fold].
// causal: 0 none, 1 skip upper blocks, 2 K limited to row0+128.
// catmode: 0 normal; 1 cat-heads scatter; 2 V^T pane scatter (row-bias).
constexpr int BN = 64;
constexpr int NT = BN / 16;                 // 4 n8-tiles per warp
constexpr int BSTAGE = 32768 + BN * 256;    // 48KB: A tile (32KB) + B tile (16KB)
constexpr int BSUB = BN * 128;              // per-64k-subtile B bytes
constexpr int GEMM_SMEM = 2 * BSTAGE + 128; // 98432 -> 2 CTAs/SM

__global__ void __launch_bounds__(256, 2)
gemm_mma(const __half* __restrict__ A, const __half* __restrict__ B,
         const float* __restrict__ bias, const float* __restrict__ res,
         float* __restrict__ Cf, __half* __restrict__ Ch,
         int Ntot, int K,
         long sA, long sB, long sBias, long sC,
         int epi, int causal, int catmode) {
    extern __shared__ char smem_raw[];
    const int row0 = blockIdx.y * 128;
    const int col0 = blockIdx.x * BN;
    if (causal == 1 && col0 > row0 + 127) return;

    const int z = blockIdx.z;
    A += (long)z * sA;
    B += (long)z * sB;
    if (bias) bias += (long)z * sBias;
    if (!catmode) {
        if (Cf) Cf += (long)z * sC;
        if (Ch) Ch += (long)z * sC;
    }

    const int tid = threadIdx.x;
    const int wid = tid >> 5, lane = tid & 31;
    const int warp_m = wid & 3, warp_n = wid >> 2;

    uint32_t sbase = (smem_u32(smem_raw) + 127) & ~127u;

    int Keff = K;
    if (causal == 2) { int kl = row0 + 128; Keff = kl < K ? kl : K; }
    const int nch = Keff >> 7;

    float acc[2][NT][4];
    #pragma unroll
    for (int a = 0; a < 2; a++)
        #pragma unroll
        for (int b = 0; b < NT; b++)
            #pragma unroll
            for (int d = 0; d < 4; d++) acc[a][b][d] = 0.f;

    auto issue = [&](int c) {
        uint32_t dstb = sbase + (uint32_t)(c & 1) * BSTAGE;
        int k0 = c << 7;
        #pragma unroll
        for (int i = 0; i < 8; i++) {
            int idx = i * 256 + tid;
            int r = idx >> 4, kb = idx & 15;
            uint32_t so = (uint32_t)((kb >> 3) * 16384 + r * 128 +
                                     (((kb & 7) * 16) ^ ((r & 7) << 4)));
            const void* src = (const char*)(A + (long)(row0 + r) * K + k0) + kb * 16;
            cp_async16(dstb + so, src);
        }
        #pragma unroll
        for (int i = 0; i < 4; i++) {
            int idx = i * 256 + tid;
            int r = idx >> 4, kb = idx & 15;
            uint32_t so = (uint32_t)((kb >> 3) * BSUB + r * 128 +
                                     (((kb & 7) * 16) ^ ((r & 7) << 4)));
            const void* src = (const char*)(B + (long)(col0 + r) * K + k0) + kb * 16;
            cp_async16(dstb + 32768 + so, src);
        }
        cp_commit();
    };

    const int li  = lane & 7;
    const int s8  = (lane >> 3) & 1;
    const int s16 = lane >> 4;

    int ar[2], arsw[2];
    #pragma unroll
    for (int mt = 0; mt < 2; mt++) {
        int r = warp_m * 32 + mt * 16 + s8 * 8 + li;
        ar[mt] = r * 128; arsw[mt] = (r & 7) << 4;
    }
    int br[NT / 2], brsw[NT / 2];
    #pragma unroll
    for (int nt2 = 0; nt2 < NT / 2; nt2++) {
        int r = warp_n * (BN / 2) + nt2 * 16 + s8 * 8 + li;
        br[nt2] = r * 128; brsw[nt2] = (r & 7) << 4;
    }

    uint32_t af[2][2][4];
    uint32_t bf[2][NT][2];

    issue(0);
    for (int c = 0; c < nch; c++) {
        if (c + 1 < nch) { issue(c + 1); cp_wait1(); }
        else cp_wait0();
        __syncthreads();
        uint32_t bufb = sbase + (uint32_t)(c & 1) * BSTAGE;

        {
            const int kbyte = s16 * 16;
            const int inner = kbyte & 127;
            #pragma unroll
            for (int mt = 0; mt < 2; mt++) {
                uint32_t off = (uint32_t)(ar[mt] + (inner ^ arsw[mt]));
                ldmatrix_x4(af[0][mt][0], af[0][mt][1], af[0][mt][2], af[0][mt][3], bufb + off);
            }
            #pragma unroll
            for (int nt2 = 0; nt2 < NT / 2; nt2++) {
                uint32_t off = (uint32_t)(br[nt2] + (inner ^ brsw[nt2]));
                uint32_t r0, r1, r2, r3;
                ldmatrix_x4(r0, r1, r2, r3, bufb + 32768 + off);
                bf[0][nt2 * 2][0] = r0; bf[0][nt2 * 2][1] = r2;
                bf[0][nt2 * 2 + 1][0] = r1; bf[0][nt2 * 2 + 1][1] = r3;
            }
        }

        #pragma unroll
        for (int ks = 0; ks < 8; ks++) {
            const int cur = ks & 1, nxt = cur ^ 1;
            if (ks < 7) {
                const int kbyte = (ks + 1) * 32 + s16 * 16;
                const int subA  = (kbyte >> 7) * 16384;
                const int subB  = (kbyte >> 7) * BSUB;
                const int inner = kbyte & 127;
                #pragma unroll
                for (int mt = 0; mt < 2; mt++) {
                    uint32_t off = (uint32_t)(subA + ar[mt] + (inner ^ arsw[mt]));
                    ldmatrix_x4(af[nxt][mt][0], af[nxt][mt][1], af[nxt][mt][2], af[nxt][mt][3],
                                bufb + off);
                }
                #pragma unroll
                for (int nt2 = 0; nt2 < NT / 2; nt2++) {
                    uint32_t off = (uint32_t)(subB + br[nt2] + (inner ^ brsw[nt2]));
                    uint32_t r0, r1, r2, r3;
                    ldmatrix_x4(r0, r1, r2, r3, bufb + 32768 + off);
                    bf[nxt][nt2 * 2][0] = r0; bf[nxt][nt2 * 2][1] = r2;
                    bf[nxt][nt2 * 2 + 1][0] = r1; bf[nxt][nt2 * 2 + 1][1] = r3;
                }
            }
            #pragma unroll
            for (int mt = 0; mt < 2; mt++)
                #pragma unroll
                for (int nt = 0; nt < NT; nt++)
                    MMA16816F16(acc[mt][nt], af[cur][mt], bf[cur][nt][0], bf[cur][nt][1]);
        }
        __syncthreads();
    }

    // ---------------- epilogue ----------------
    const int g = lane >> 2, t = lane & 3;
    const int hh = z >> 2, nb = z & 3;
    const float QSCALE = 0.03608439182435161f;  // 1/sqrt(768)
    #pragma unroll
    for (int mt = 0; mt < 2; mt++)
        #pragma unroll
        for (int nt = 0; nt < NT; nt++)
            #pragma unroll
            for (int hr = 0; hr < 2; hr++) {
                int gr = row0 + warp_m * 32 + mt * 16 + g + hr * 8;
                int gc = col0 + warp_n * (BN / 2) + nt * 8 + t * 2;
                float v0 = acc[mt][nt][hr * 2];
                float v1 = acc[mt][nt][hr * 2 + 1];
                if (bias) {
                    if (catmode == 2) { float b = bias[gr]; v0 += b; v1 += b; }
                    else { v0 += bias[gc]; v1 += bias[gc + 1]; }
                }
                if (epi == 1) { v0 = v0 * normcdff(v0); v1 = v1 * normcdff(v1); }
                else if (epi == 2) {
                    long o = (long)gr * Ntot + gc;
                    v0 += res[o]; v1 += res[o + 1];
                } else if (epi == 3) { v0 *= QSCALE; v1 *= QSCALE; }
                if (Cf) {
                    long o = (long)gr * Ntot + gc;
                    Cf[o] = v0; Cf[o + 1] = v1;
                }
                if (Ch) {
                    long o;
                    if (catmode == 1)
                        o = (long)(nb * S_LEN + gr) * HE + (long)hh * E_DIM + gc;
                    else if (catmode == 2)
                        o = (long)z * N_B * ((long)S_LEN * E_DIM)
                          + (long)(gc >> 10) * ((long)S_LEN * E_DIM)
                          + (long)gr * S_LEN + (gc & 1023);
                    else
                        o = (long)gr * Ntot + gc;
                    __half2 hp;
                    hp.x = __float2half_rn(v0);
                    hp.y = __float2half_rn(v1);
                    *(__half2*)(Ch + o) = hp;
                }
            }
}

// ---------------- launch ----------------
extern "C" void kernel_launch(void* const* d_in, const int* in_sizes, int n_in,
                              void* d_out, int out_size) {
    const float* inputs = (const float*)d_in[0];
    const float* g1  = (const float*)d_in[1];
    const float* b1  = (const float*)d_in[2];
    const float* Wq  = (const float*)d_in[3];
    const float* bq  = (const float*)d_in[4];
    const float* Wk  = (const float*)d_in[5];
    const float* bk  = (const float*)d_in[6];
    const float* Wv  = (const float*)d_in[7];
    const float* bv  = (const float*)d_in[8];
    const float* Wc  = (const float*)d_in[9];
    const float* bc  = (const float*)d_in[10];
    const float* g2  = (const float*)d_in[11];
    const float* b2  = (const float*)d_in[12];
    const float* Wfc = (const float*)d_in[13];
    const float* bfc = (const float*)d_in[14];
    const float* Wp  = (const float*)d_in[15];
    const float* bp  = (const float*)d_in[16];
    float* out = (float*)d_out;

    cudaFuncSetAttribute(gemm_mma, cudaFuncAttributeMaxDynamicSharedMemorySize, GEMM_SMEM);

    float *x, *mha, *y2;
    __half *xh, *wqth, *wkth, *wvth;
    __half *qh, *kh, *vth, *sch, *ah;
    __half *cath, *wcth, *y2h, *wfcth, *hbh, *wpth;
    cudaGetSymbolAddress((void**)&x, g_x);     cudaGetSymbolAddress((void**)&xh, g_xh);
    cudaGetSymbolAddress((void**)&wqth, g_wqth);
    cudaGetSymbolAddress((void**)&wkth, g_wkth);
    cudaGetSymbolAddress((void**)&wvth, g_wvth);
    cudaGetSymbolAddress((void**)&qh, g_qh);
    cudaGetSymbolAddress((void**)&kh, g_kh);
    cudaGetSymbolAddress((void**)&vth, g_vth);
    cudaGetSymbolAddress((void**)&sch, g_sch);
    cudaGetSymbolAddress((void**)&ah, g_ah);
    cudaGetSymbolAddress((void**)&cath, g_cath);
    cudaGetSymbolAddress((void**)&wcth, g_wcth);
    cudaGetSymbolAddress((void**)&mha, g_mha);
    cudaGetSymbolAddress((void**)&y2, g_y2);
    cudaGetSymbolAddress((void**)&y2h, g_y2h);
    cudaGetSymbolAddress((void**)&wfcth, g_wfcth);
    cudaGetSymbolAddress((void**)&hbh, g_hbh);
    cudaGetSymbolAddress((void**)&wpth, g_wpth);

    const long WEE = (long)E_DIM * E_DIM;
    const long QKV = (long)NS * E_DIM;
    const long ATT = (long)S_LEN * E_DIM;
    const long SCS = (long)S_LEN * S_LEN;

    // 0) LN1 -> x (fp32 + fp16)
    ln_kernel<<<NS, 256>>>(inputs, nullptr, g1, b1, x, xh);
    // 1) ALL weight transposes in one launch
    prep_weights<<<32256, dim3(32, 8)>>>(Wq, Wk, Wv, Wc, Wfc, Wp,
                                         wqth, wkth, wvth, wcth, wfcth, wpth);

    dim3 gQKV(E_DIM / BN, NS / 128, H_HEADS);
    // Q projection, scaled by 1/sqrt(E) (epi=3)
    gemm_mma<<<gQKV, 256, GEMM_SMEM>>>(xh, wqth, bq, nullptr,
                                       nullptr, qh, E_DIM, E_DIM,
                                       0, WEE, E_DIM, QKV, 3, 0, 0);
    // K projection
    gemm_mma<<<gQKV, 256, GEMM_SMEM>>>(xh, wkth, bk, nullptr,
                                       nullptr, kh, E_DIM, E_DIM,
                                       0, WEE, E_DIM, QKV, 0, 0, 0);
    // V^T = Wv^T @ x^T, scattered into [h*4+n][e][t] panes with row-bias
    dim3 gVT(NS / BN, E_DIM / 128, H_HEADS);
    gemm_mma<<<gVT, 256, GEMM_SMEM>>>(wvth, xh, bv, nullptr,
                                      nullptr, vth, NS, E_DIM,
                                      WEE, 0, E_DIM, 0, 0, 0, 2);

    // scores = Q @ K^T (causal block skip), fp16 out (already scaled via Q)
    dim3 gSC(S_LEN / BN, S_LEN / 128, H_HEADS * N_B);
    gemm_mma<<<gSC, 256, GEMM_SMEM>>>(qh, kh, nullptr, nullptr,
                                      nullptr, sch, S_LEN, E_DIM,
                                      ATT, ATT, 0, SCS, 0, 1, 0);

    // softmax -> attn fp16 (warp-per-row, truncated writes)
    softmax_causal<<<dim3(S_LEN / 8, H_HEADS * N_B), 256>>>(sch, ah);

    // heads = attn @ V^T panes, cat layout out
    dim3 gAV(E_DIM / BN, S_LEN / 128, H_HEADS * N_B);
    gemm_mma<<<gAV, 256, GEMM_SMEM>>>(ah, vth, nullptr, nullptr,
                                      nullptr, cath, E_DIM, S_LEN,
                                      SCS, ATT, 0, 0, 0, 2, 1);

    // c_proj
    dim3 gCP(E_DIM / BN, NS / 128, 1);
    gemm_mma<<<gCP, 256, GEMM_SMEM>>>(cath, wcth, bc, nullptr,
                                      mha, nullptr, E_DIM, HE,
                                      0, 0, 0, 0, 0, 0, 0);

    // y2 = LN2(mha + x)
    ln_kernel<<<NS, 256>>>(mha, x, g2, b2, y2, y2h);

    // fc + GELU
    dim3 gFC(FF / BN, NS / 128, 1);
    gemm_mma<<<gFC, 256, GEMM_SMEM>>>(y2h, wfcth, bfc, nullptr,
                                      nullptr, hbh, FF, E_DIM,
                                      0, 0, 0, 0, 1, 0, 0);

    // proj + bias + residual(y2) -> out
    dim3 gPJ(E_DIM / BN, NS / 128, 1);
    gemm_mma<<<gPJ, 256, GEMM_SMEM>>>(hbh, wpth, bp, y2,
                                      out, nullptr, E_DIM, FF,
                                      0, 0, 0, 0, 2, 0, 0);
}